// round 1
// baseline (speedup 1.0000x reference)
#include <cuda_runtime.h>
#include <math.h>
#include <stdint.h>

#define B_  2
#define S_  2048
#define D_  1024
#define V_  32000
#define NL_ 6
#define M_  (B_*S_)   // 4096 rows (tokens)

// ---------------------------------------------------------------------------
// Scratch (static __device__ arrays; no runtime allocation)
// ---------------------------------------------------------------------------
__device__ float  g_x0[M_*D_];
__device__ float  g_x1[M_*D_];
__device__ float  g_hT[M_*D_];     // (B, D, S) channel-major LN output
__device__ float  g_yT[M_*D_];     // (B, D, S) conv+silu output
__device__ float  g_ref[M_*D_];    // refined (M, D)
__device__ float  g_xf[M_*D_];     // final LN output
__device__ float2 g_stats[M_];     // per-row (mu, rstd)

// ---------------------------------------------------------------------------
// Embedding + sinusoidal PE
// ---------------------------------------------------------------------------
__global__ void embed_kernel(const int* __restrict__ ids,
                             const float* __restrict__ emb,
                             float* __restrict__ x) {
    int row = blockIdx.x;          // 0..M_-1
    int s   = row & (S_ - 1);
    int tok = ids[row];
    int d0  = threadIdx.x * 4;     // 256 threads * 4 = 1024
    float4 e = *(const float4*)(emb + (size_t)tok * D_ + d0);
    const float cln = -logf(10000.0f) / (float)D_;
    float pe[4];
#pragma unroll
    for (int j = 0; j < 4; j += 2) {
        float freq = expf(cln * (float)(d0 + j));   // exponent index 2p = d0+j (even)
        float a = (float)s * freq;
        pe[j]   = sinf(a);
        pe[j+1] = cosf(a);
    }
    float4 o;
    o.x = e.x + pe[0]; o.y = e.y + pe[1]; o.z = e.z + pe[2]; o.w = e.w + pe[3];
    *(float4*)(x + (size_t)row * D_ + d0) = o;
}

// ---------------------------------------------------------------------------
// LayerNorm statistics: per-row mean and rstd
// ---------------------------------------------------------------------------
__global__ void ln_stats_kernel(const float* __restrict__ x, float2* __restrict__ stats) {
    int row = blockIdx.x;
    float4 v = ((const float4*)(x + (size_t)row * D_))[threadIdx.x];
    float s = v.x + v.y + v.z + v.w;
    float q = v.x*v.x + v.y*v.y + v.z*v.z + v.w*v.w;
#pragma unroll
    for (int o = 16; o; o >>= 1) {
        s += __shfl_xor_sync(0xffffffffu, s, o);
        q += __shfl_xor_sync(0xffffffffu, q, o);
    }
    __shared__ float ss[8], sq[8];
    int w = threadIdx.x >> 5;
    if ((threadIdx.x & 31) == 0) { ss[w] = s; sq[w] = q; }
    __syncthreads();
    if (threadIdx.x == 0) {
        float S = 0.f, Q = 0.f;
#pragma unroll
        for (int i = 0; i < 8; i++) { S += ss[i]; Q += sq[i]; }
        float mu  = S / (float)D_;
        float var = Q / (float)D_ - mu * mu;
        stats[row] = make_float2(mu, rsqrtf(var + 1e-5f));
    }
}

// ---------------------------------------------------------------------------
// Apply LN while transposing (B,S,D)->(B,D,S)
// blockDim (32,8); grid (S/32, D/32, B)
// ---------------------------------------------------------------------------
__global__ void ln_transpose_kernel(const float* __restrict__ x,
                                    const float2* __restrict__ stats,
                                    const float* __restrict__ g,
                                    const float* __restrict__ bta,
                                    float* __restrict__ hT) {
    __shared__ float tile[32][33];
    int b  = blockIdx.z;
    int s0 = blockIdx.x * 32, d0 = blockIdx.y * 32;
    int tx = threadIdx.x, ty = threadIdx.y;
    float gg = g[d0 + tx], bb = bta[d0 + tx];
#pragma unroll
    for (int i = 0; i < 4; i++) {
        int s = s0 + ty + i * 8;
        float2 st = stats[b * S_ + s];
        float v = x[((size_t)(b * S_ + s)) * D_ + d0 + tx];
        tile[ty + i * 8][tx] = (v - st.x) * st.y * gg + bb;
    }
    __syncthreads();
#pragma unroll
    for (int i = 0; i < 4; i++) {
        int d = d0 + ty + i * 8;
        hT[((size_t)(b * D_ + d)) * S_ + s0 + tx] = tile[tx][ty + i * 8];
    }
}

// ---------------------------------------------------------------------------
// Final LN apply (row-major output for GEMM A)
// ---------------------------------------------------------------------------
__global__ void apply_ln_kernel(const float* __restrict__ x,
                                const float2* __restrict__ stats,
                                const float* __restrict__ g,
                                const float* __restrict__ b,
                                float* __restrict__ o) {
    int row = blockIdx.x;
    int d0 = threadIdx.x * 4;
    float2 st = stats[row];
    float4 v  = *(const float4*)(x + (size_t)row * D_ + d0);
    float4 gg = *(const float4*)(g + d0);
    float4 bb = *(const float4*)(b + d0);
    float4 r;
    r.x = (v.x - st.x) * st.y * gg.x + bb.x;
    r.y = (v.y - st.x) * st.y * gg.y + bb.y;
    r.z = (v.z - st.x) * st.y * gg.z + bb.z;
    r.w = (v.w - st.x) * st.y * gg.w + bb.w;
    *(float4*)(o + (size_t)row * D_ + d0) = r;
}

// ---------------------------------------------------------------------------
// Depthwise conv chain per (b,d) channel, fully in SMEM.
// g1 = conv3(c); g2 = conv64a(g1) + c; g3 = conv64b(g2); y = silu(g3*mix)
// conv64: out[t] = sum_{k=0..63} in[t-32+k] * w[k]   (zero padded)
// conv3 : out[t] = sum_{k=0..2}  in[t-1+k]  * w[k]
// ---------------------------------------------------------------------------
__global__ void __launch_bounds__(256) conv_kernel(const float* __restrict__ hT,
                                                   const float* __restrict__ lw,   // [D,3]
                                                   const float* __restrict__ fw,   // [2,D,64]
                                                   const float* __restrict__ mw,   // [D]
                                                   float* __restrict__ yT) {
    int bd = blockIdx.x;
    int d  = bd & (D_ - 1);
    __shared__ float bufA[S_ + 64];
    __shared__ float bufB[S_ + 64];
    __shared__ float w3[3], wA[64], wB[64];
    int tid = threadIdx.x;
    if (tid < 64) {
        wA[tid] = fw[(size_t)d * 64 + tid];
        wB[tid] = fw[(size_t)(D_ + d) * 64 + tid];
    }
    if (tid < 3) w3[tid] = lw[d * 3 + tid];
    if (tid < 32) {
        bufA[tid] = 0.f; bufA[S_ + 32 + tid] = 0.f;
        bufB[tid] = 0.f; bufB[S_ + 32 + tid] = 0.f;
    }
    const float* cin = hT + (size_t)bd * S_;
    for (int i = tid; i < S_ / 4; i += 256)
        ((float4*)(bufA + 32))[i] = ((const float4*)cin)[i];
    __syncthreads();
    // g1 = conv3(c) into bufB (data region offset +32)
    for (int s = tid; s < S_; s += 256)
        bufB[32 + s] = bufA[31 + s] * w3[0] + bufA[32 + s] * w3[1] + bufA[33 + s] * w3[2];
    __syncthreads();

    int s0 = tid * 8;
    float acc[8], win[8];
    // g2 = conv64a(g1) + c  (sliding window over bufB)
#pragma unroll
    for (int j = 0; j < 8; j++) { acc[j] = bufA[32 + s0 + j]; win[j] = bufB[s0 + j]; }
#pragma unroll
    for (int k = 0; k < 64; k++) {
        float wk = wA[k];
#pragma unroll
        for (int j = 0; j < 8; j++) acc[j] += win[j] * wk;
#pragma unroll
        for (int j = 0; j < 7; j++) win[j] = win[j + 1];
        win[7] = bufB[s0 + 8 + k];
    }
    __syncthreads();
#pragma unroll
    for (int j = 0; j < 8; j++) bufA[32 + s0 + j] = acc[j];   // g2 over bufA data region
    __syncthreads();
    // g3 = conv64b(g2)
    float mwd = mw[d];
#pragma unroll
    for (int j = 0; j < 8; j++) { acc[j] = 0.f; win[j] = bufA[s0 + j]; }
#pragma unroll
    for (int k = 0; k < 64; k++) {
        float wk = wB[k];
#pragma unroll
        for (int j = 0; j < 8; j++) acc[j] += win[j] * wk;
#pragma unroll
        for (int j = 0; j < 7; j++) win[j] = win[j + 1];
        win[7] = bufA[s0 + 8 + k];
    }
    float* outp = yT + (size_t)bd * S_;
#pragma unroll
    for (int j = 0; j < 8; j++) {
        float m = acc[j] * mwd;
        outp[s0 + j] = m / (1.0f + expf(-m));   // silu
    }
}

// ---------------------------------------------------------------------------
// SGEMM: C[m,n] = sum_k A(m,k) * B(n-or-k major) + epilogue
// ALAY: 0 = A row-major [M,K] ; 1 = A is yT: A[k][m] at b*K*S + k*S + s (m=b*S+s)
// BLAY: 0 = B row-major [N,K] (i.e. C=A*B^T) ; 1 = B row-major [K,N]
// EPI : 0 = +bias ; 1 = gate-combine: sigmoid(acc+bias)*refined + (1-sig)*orig
// Tiles: 128x128x16, 256 threads, 8x8 per thread. All dims divide exactly.
// ---------------------------------------------------------------------------
template<int ALAY, int BLAY, int EPI>
__global__ void __launch_bounds__(256) gemm_kernel(
        const float* __restrict__ A, const float* __restrict__ Bm,
        const float* __restrict__ bias,
        const float* __restrict__ refined, const float* __restrict__ orig,
        float* __restrict__ C, int M, int N, int K)
{
    const int BK = 16;
    const int LDS_ = 136;                 // padded row stride (floats)
    __shared__ float As[BK * LDS_];
    __shared__ float Bs[BK * LDS_];
    int tid = threadIdx.x;
    int m0 = blockIdx.y * 128, n0 = blockIdx.x * 128;
    int tm = (tid >> 4) * 8, tn = (tid & 15) * 8;

    float acc[8][8];
#pragma unroll
    for (int i = 0; i < 8; i++)
#pragma unroll
        for (int j = 0; j < 8; j++) acc[i][j] = 0.f;

    const float* Abase = A;
    if (ALAY == 1) {
        int bb = m0 / S_;
        Abase = A + (size_t)bb * K * S_ + (m0 % S_);
    }

    for (int k0 = 0; k0 < K; k0 += BK) {
        if (ALAY == 0) {
#pragma unroll
            for (int i = 0; i < 2; i++) {
                int idx = tid + i * 256;
                int row = idx >> 2, kc = (idx & 3) * 4;
                float4 v = *(const float4*)(A + (size_t)(m0 + row) * K + k0 + kc);
                As[(kc + 0) * LDS_ + row] = v.x;
                As[(kc + 1) * LDS_ + row] = v.y;
                As[(kc + 2) * LDS_ + row] = v.z;
                As[(kc + 3) * LDS_ + row] = v.w;
            }
        } else {
#pragma unroll
            for (int i = 0; i < 2; i++) {
                int idx = tid + i * 256;
                int kr = idx >> 5, mc = (idx & 31) * 4;
                float4 v = *(const float4*)(Abase + (size_t)(k0 + kr) * S_ + mc);
                *(float4*)(As + kr * LDS_ + mc) = v;
            }
        }
        if (BLAY == 0) {
#pragma unroll
            for (int i = 0; i < 2; i++) {
                int idx = tid + i * 256;
                int row = idx >> 2, kc = (idx & 3) * 4;
                float4 v = *(const float4*)(Bm + (size_t)(n0 + row) * K + k0 + kc);
                Bs[(kc + 0) * LDS_ + row] = v.x;
                Bs[(kc + 1) * LDS_ + row] = v.y;
                Bs[(kc + 2) * LDS_ + row] = v.z;
                Bs[(kc + 3) * LDS_ + row] = v.w;
            }
        } else {
#pragma unroll
            for (int i = 0; i < 2; i++) {
                int idx = tid + i * 256;
                int kr = idx >> 5, nc = (idx & 31) * 4;
                float4 v = *(const float4*)(Bm + (size_t)(k0 + kr) * N + n0 + nc);
                *(float4*)(Bs + kr * LDS_ + nc) = v;
            }
        }
        __syncthreads();
#pragma unroll
        for (int k = 0; k < BK; k++) {
            float4 a0 = *(const float4*)(As + k * LDS_ + tm);
            float4 a1 = *(const float4*)(As + k * LDS_ + tm + 4);
            float4 b0 = *(const float4*)(Bs + k * LDS_ + tn);
            float4 b1 = *(const float4*)(Bs + k * LDS_ + tn + 4);
            float av[8] = {a0.x, a0.y, a0.z, a0.w, a1.x, a1.y, a1.z, a1.w};
            float bv[8] = {b0.x, b0.y, b0.z, b0.w, b1.x, b1.y, b1.z, b1.w};
#pragma unroll
            for (int i = 0; i < 8; i++)
#pragma unroll
                for (int j = 0; j < 8; j++) acc[i][j] += av[i] * bv[j];
        }
        __syncthreads();
    }

    float4 bias0 = *(const float4*)(bias + n0 + tn);
    float4 bias1 = *(const float4*)(bias + n0 + tn + 4);
    float bv8[8] = {bias0.x, bias0.y, bias0.z, bias0.w, bias1.x, bias1.y, bias1.z, bias1.w};

#pragma unroll
    for (int i = 0; i < 8; i++) {
        size_t row = (size_t)(m0 + tm + i);
        size_t off = row * N + n0 + tn;
        if (EPI == 0) {
            float4 o0, o1;
            o0.x = acc[i][0] + bv8[0]; o0.y = acc[i][1] + bv8[1];
            o0.z = acc[i][2] + bv8[2]; o0.w = acc[i][3] + bv8[3];
            o1.x = acc[i][4] + bv8[4]; o1.y = acc[i][5] + bv8[5];
            o1.z = acc[i][6] + bv8[6]; o1.w = acc[i][7] + bv8[7];
            *(float4*)(C + off)     = o0;
            *(float4*)(C + off + 4) = o1;
        } else {
            float4 r0 = *(const float4*)(refined + off);
            float4 r1 = *(const float4*)(refined + off + 4);
            float4 x0 = *(const float4*)(orig + off);
            float4 x1 = *(const float4*)(orig + off + 4);
            float rr[8] = {r0.x, r0.y, r0.z, r0.w, r1.x, r1.y, r1.z, r1.w};
            float xx[8] = {x0.x, x0.y, x0.z, x0.w, x1.x, x1.y, x1.z, x1.w};
            float oo[8];
#pragma unroll
            for (int j = 0; j < 8; j++) {
                float gte = 1.0f / (1.0f + expf(-(acc[i][j] + bv8[j])));
                oo[j] = gte * rr[j] + (1.0f - gte) * xx[j];
            }
            float4 o0 = {oo[0], oo[1], oo[2], oo[3]};
            float4 o1 = {oo[4], oo[5], oo[6], oo[7]};
            *(float4*)(C + off)     = o0;
            *(float4*)(C + off + 4) = o1;
        }
    }
}

// ---------------------------------------------------------------------------
// Host orchestration
// ---------------------------------------------------------------------------
static float* sym_addr(const void* sym) {
    void* p = nullptr;
    cudaGetSymbolAddress(&p, sym);
    return (float*)p;
}

extern "C" void kernel_launch(void* const* d_in, const int* in_sizes, int n_in,
                              void* d_out, int out_size) {
    (void)in_sizes; (void)n_in; (void)out_size;
    const int*   ids   = (const int*)d_in[0];
    const float* emb   = (const float*)d_in[1];
    const float* lw    = (const float*)d_in[2];   // (NL, D, 3)
    const float* fw    = (const float*)d_in[3];   // (NL, 2, D, 64)
    const float* mw    = (const float*)d_in[4];   // (NL, D)
    const float* ln1g  = (const float*)d_in[5];
    const float* ln1b  = (const float*)d_in[6];
    const float* refW  = (const float*)d_in[7];   // (NL, D, D)
    const float* refb  = (const float*)d_in[8];
    const float* gateW = (const float*)d_in[9];
    const float* gateb = (const float*)d_in[10];
    const float* lnfg  = (const float*)d_in[11];
    const float* lnfb  = (const float*)d_in[12];
    const float* outW  = (const float*)d_in[13];  // (D, V)
    const float* outb  = (const float*)d_in[14];
    float* out = (float*)d_out;

    float*  x0  = sym_addr(g_x0);
    float*  x1  = sym_addr(g_x1);
    float*  hT  = sym_addr(g_hT);
    float*  yT  = sym_addr(g_yT);
    float*  rf  = sym_addr(g_ref);
    float*  xf  = sym_addr(g_xf);
    float2* st  = (float2*)sym_addr(g_stats);

    embed_kernel<<<M_, 256>>>(ids, emb, x0);

    float* cur = x0;
    float* nxt = x1;
    for (int l = 0; l < NL_; l++) {
        ln_stats_kernel<<<M_, 256>>>(cur, st);
        ln_transpose_kernel<<<dim3(S_/32, D_/32, B_), dim3(32, 8)>>>(
            cur, st, ln1g + (size_t)l * D_, ln1b + (size_t)l * D_, hT);
        conv_kernel<<<B_*D_, 256>>>(
            hT, lw + (size_t)l * D_ * 3, fw + (size_t)l * 2 * D_ * 64,
            mw + (size_t)l * D_, yT);
        gemm_kernel<1, 0, 0><<<dim3(D_/128, M_/128), 256>>>(
            yT, refW + (size_t)l * D_ * D_, refb + (size_t)l * D_,
            nullptr, nullptr, rf, M_, D_, D_);
        gemm_kernel<0, 0, 1><<<dim3(D_/128, M_/128), 256>>>(
            cur, gateW + (size_t)l * D_ * D_, gateb + (size_t)l * D_,
            rf, cur, nxt, M_, D_, D_);
        float* t = cur; cur = nxt; nxt = t;
    }

    ln_stats_kernel<<<M_, 256>>>(cur, st);
    apply_ln_kernel<<<M_, 256>>>(cur, st, lnfg, lnfb, xf);
    gemm_kernel<0, 1, 0><<<dim3(V_/128, M_/128), 256>>>(
        xf, outW, outb, nullptr, nullptr, out, M_, V_, D_);
}

// round 3
// speedup vs baseline: 1.9148x; 1.9148x over previous
#include <cuda_runtime.h>
#include <cuda_bf16.h>
#include <math.h>
#include <stdint.h>

#define B_  2
#define S_  2048
#define D_  1024
#define V_  32000
#define NL_ 6
#define M_  (B_*S_)   // 4096 tokens

// ---------------------------------------------------------------------------
// Scratch
// ---------------------------------------------------------------------------
__device__ float  g_x0[M_*D_];
__device__ float  g_x1[M_*D_];
__device__ float  g_hT[M_*D_];     // (B, D, S) LN output (channel-major)
__device__ float  g_yT[M_*D_];     // (B, D, S) conv+silu output
__device__ float  g_ref[M_*D_];    // refined (M, D)
__device__ float2 g_stats[M_];

__device__ __nv_bfloat16 g_x0h[M_*D_], g_x0l[M_*D_];
__device__ __nv_bfloat16 g_x1h[M_*D_], g_x1l[M_*D_];
__device__ __nv_bfloat16 g_yh [M_*D_], g_yl [M_*D_];
__device__ __nv_bfloat16 g_xfh[M_*D_], g_xfl[M_*D_];
__device__ __nv_bfloat16 g_wrh[NL_*D_*D_], g_wrl[NL_*D_*D_];
__device__ __nv_bfloat16 g_wgh[NL_*D_*D_], g_wgl[NL_*D_*D_];
__device__ __nv_bfloat16 g_woh[(size_t)V_*D_], g_wol[(size_t)V_*D_];

__device__ __forceinline__ void bf_split(float x, __nv_bfloat16& h, __nv_bfloat16& l) {
    h = __float2bfloat16(x);
    l = __float2bfloat16(x - __bfloat162float(h));
}

// ---------------------------------------------------------------------------
// Embedding + sinusoidal PE (+ hi/lo split for layer-0 gate GEMM)
// ---------------------------------------------------------------------------
__global__ void embed_kernel(const int* __restrict__ ids,
                             const float* __restrict__ emb,
                             float* __restrict__ x,
                             __nv_bfloat16* __restrict__ xh,
                             __nv_bfloat16* __restrict__ xl) {
    int row = blockIdx.x;
    int s   = row & (S_ - 1);
    int tok = ids[row];
    int d0  = threadIdx.x * 4;
    float4 e = *(const float4*)(emb + (size_t)tok * D_ + d0);
    const float cln = -logf(10000.0f) / (float)D_;
    float pe[4];
#pragma unroll
    for (int j = 0; j < 4; j += 2) {
        float freq = expf(cln * (float)(d0 + j));
        float a = (float)s * freq;
        pe[j]   = sinf(a);
        pe[j+1] = cosf(a);
    }
    float o[4] = {e.x + pe[0], e.y + pe[1], e.z + pe[2], e.w + pe[3]};
    *(float4*)(x + (size_t)row * D_ + d0) = *(float4*)o;
    ushort4 h4, l4;
    __nv_bfloat16 h, l;
    bf_split(o[0], h, l); h4.x = *(unsigned short*)&h; l4.x = *(unsigned short*)&l;
    bf_split(o[1], h, l); h4.y = *(unsigned short*)&h; l4.y = *(unsigned short*)&l;
    bf_split(o[2], h, l); h4.z = *(unsigned short*)&h; l4.z = *(unsigned short*)&l;
    bf_split(o[3], h, l); h4.w = *(unsigned short*)&h; l4.w = *(unsigned short*)&l;
    *(ushort4*)(xh + (size_t)row * D_ + d0) = h4;
    *(ushort4*)(xl + (size_t)row * D_ + d0) = l4;
}

// ---------------------------------------------------------------------------
// Weight split (element-wise): w fp32 -> hi/lo bf16
// ---------------------------------------------------------------------------
__global__ void split_kernel(const float* __restrict__ w,
                             __nv_bfloat16* __restrict__ hi,
                             __nv_bfloat16* __restrict__ lo, int n4) {
    int i = blockIdx.x * 256 + threadIdx.x;
    if (i >= n4) return;
    float4 v = ((const float4*)w)[i];
    ushort4 h4, l4; __nv_bfloat16 h, l;
    bf_split(v.x, h, l); h4.x = *(unsigned short*)&h; l4.x = *(unsigned short*)&l;
    bf_split(v.y, h, l); h4.y = *(unsigned short*)&h; l4.y = *(unsigned short*)&l;
    bf_split(v.z, h, l); h4.z = *(unsigned short*)&h; l4.z = *(unsigned short*)&l;
    bf_split(v.w, h, l); h4.w = *(unsigned short*)&h; l4.w = *(unsigned short*)&l;
    ((ushort4*)hi)[i] = h4;
    ((ushort4*)lo)[i] = l4;
}

// ---------------------------------------------------------------------------
// outW (D,V) -> transposed [V][D] hi/lo bf16
// grid (V/32, D/32), block (32,8)
// ---------------------------------------------------------------------------
__global__ void wout_tsplit_kernel(const float* __restrict__ w,
                                   __nv_bfloat16* __restrict__ hi,
                                   __nv_bfloat16* __restrict__ lo) {
    __shared__ float tile[32][33];
    int v0 = blockIdx.x * 32, d0 = blockIdx.y * 32;
    int tx = threadIdx.x, ty = threadIdx.y;
#pragma unroll
    for (int i = 0; i < 4; i++)
        tile[ty + i * 8][tx] = w[(size_t)(d0 + ty + i * 8) * V_ + v0 + tx];
    __syncthreads();
#pragma unroll
    for (int i = 0; i < 4; i++) {
        float val = tile[tx][ty + i * 8];
        __nv_bfloat16 h, l;
        bf_split(val, h, l);
        size_t o = (size_t)(v0 + ty + i * 8) * D_ + d0 + tx;
        hi[o] = h; lo[o] = l;
    }
}

// ---------------------------------------------------------------------------
// LayerNorm statistics
// ---------------------------------------------------------------------------
__global__ void ln_stats_kernel(const float* __restrict__ x, float2* __restrict__ stats) {
    int row = blockIdx.x;
    float4 v = ((const float4*)(x + (size_t)row * D_))[threadIdx.x];
    float s = v.x + v.y + v.z + v.w;
    float q = v.x*v.x + v.y*v.y + v.z*v.z + v.w*v.w;
#pragma unroll
    for (int o = 16; o; o >>= 1) {
        s += __shfl_xor_sync(0xffffffffu, s, o);
        q += __shfl_xor_sync(0xffffffffu, q, o);
    }
    __shared__ float ss[8], sq[8];
    int w = threadIdx.x >> 5;
    if ((threadIdx.x & 31) == 0) { ss[w] = s; sq[w] = q; }
    __syncthreads();
    if (threadIdx.x == 0) {
        float S = 0.f, Q = 0.f;
#pragma unroll
        for (int i = 0; i < 8; i++) { S += ss[i]; Q += sq[i]; }
        float mu  = S / (float)D_;
        float var = Q / (float)D_ - mu * mu;
        stats[row] = make_float2(mu, rsqrtf(var + 1e-5f));
    }
}

// ---------------------------------------------------------------------------
// Apply LN while transposing (B,S,D)->(B,D,S) for the conv
// ---------------------------------------------------------------------------
__global__ void ln_transpose_kernel(const float* __restrict__ x,
                                    const float2* __restrict__ stats,
                                    const float* __restrict__ g,
                                    const float* __restrict__ bta,
                                    float* __restrict__ hT) {
    __shared__ float tile[32][33];
    int b  = blockIdx.z;
    int s0 = blockIdx.x * 32, d0 = blockIdx.y * 32;
    int tx = threadIdx.x, ty = threadIdx.y;
    float gg = g[d0 + tx], bb = bta[d0 + tx];
#pragma unroll
    for (int i = 0; i < 4; i++) {
        int s = s0 + ty + i * 8;
        float2 st = stats[b * S_ + s];
        float v = x[((size_t)(b * S_ + s)) * D_ + d0 + tx];
        tile[ty + i * 8][tx] = (v - st.x) * st.y * gg + bb;
    }
    __syncthreads();
#pragma unroll
    for (int i = 0; i < 4; i++) {
        int d = d0 + ty + i * 8;
        hT[((size_t)(b * D_ + d)) * S_ + s0 + tx] = tile[tx][ty + i * 8];
    }
}

// ---------------------------------------------------------------------------
// Final LN apply -> hi/lo bf16 (token-major), for output GEMM A
// ---------------------------------------------------------------------------
__global__ void apply_ln_kernel(const float* __restrict__ x,
                                const float2* __restrict__ stats,
                                const float* __restrict__ g,
                                const float* __restrict__ b,
                                __nv_bfloat16* __restrict__ oh,
                                __nv_bfloat16* __restrict__ ol) {
    int row = blockIdx.x;
    int d0 = threadIdx.x * 4;
    float2 st = stats[row];
    float4 v  = *(const float4*)(x + (size_t)row * D_ + d0);
    float4 gg = *(const float4*)(g + d0);
    float4 bb = *(const float4*)(b + d0);
    float r[4];
    r[0] = (v.x - st.x) * st.y * gg.x + bb.x;
    r[1] = (v.y - st.x) * st.y * gg.y + bb.y;
    r[2] = (v.z - st.x) * st.y * gg.z + bb.z;
    r[3] = (v.w - st.x) * st.y * gg.w + bb.w;
    ushort4 h4, l4; __nv_bfloat16 h, l;
    bf_split(r[0], h, l); h4.x = *(unsigned short*)&h; l4.x = *(unsigned short*)&l;
    bf_split(r[1], h, l); h4.y = *(unsigned short*)&h; l4.y = *(unsigned short*)&l;
    bf_split(r[2], h, l); h4.z = *(unsigned short*)&h; l4.z = *(unsigned short*)&l;
    bf_split(r[3], h, l); h4.w = *(unsigned short*)&h; l4.w = *(unsigned short*)&l;
    *(ushort4*)(oh + (size_t)row * D_ + d0) = h4;
    *(ushort4*)(ol + (size_t)row * D_ + d0) = l4;
}

// ---------------------------------------------------------------------------
// Depthwise conv chain per (b,d) channel (fp32, unchanged — 38us total)
// ---------------------------------------------------------------------------
__global__ void __launch_bounds__(256) conv_kernel(const float* __restrict__ hT,
                                                   const float* __restrict__ lw,
                                                   const float* __restrict__ fw,
                                                   const float* __restrict__ mw,
                                                   float* __restrict__ yT) {
    int bd = blockIdx.x;
    int d  = bd & (D_ - 1);
    __shared__ float bufA[S_ + 64];
    __shared__ float bufB[S_ + 64];
    __shared__ float w3[3], wA[64], wB[64];
    int tid = threadIdx.x;
    if (tid < 64) {
        wA[tid] = fw[(size_t)d * 64 + tid];
        wB[tid] = fw[(size_t)(D_ + d) * 64 + tid];
    }
    if (tid < 3) w3[tid] = lw[d * 3 + tid];
    if (tid < 32) {
        bufA[tid] = 0.f; bufA[S_ + 32 + tid] = 0.f;
        bufB[tid] = 0.f; bufB[S_ + 32 + tid] = 0.f;
    }
    const float* cin = hT + (size_t)bd * S_;
    for (int i = tid; i < S_ / 4; i += 256)
        ((float4*)(bufA + 32))[i] = ((const float4*)cin)[i];
    __syncthreads();
    for (int s = tid; s < S_; s += 256)
        bufB[32 + s] = bufA[31 + s] * w3[0] + bufA[32 + s] * w3[1] + bufA[33 + s] * w3[2];
    __syncthreads();

    int s0 = tid * 8;
    float acc[8], win[8];
#pragma unroll
    for (int j = 0; j < 8; j++) { acc[j] = bufA[32 + s0 + j]; win[j] = bufB[s0 + j]; }
#pragma unroll
    for (int k = 0; k < 64; k++) {
        float wk = wA[k];
#pragma unroll
        for (int j = 0; j < 8; j++) acc[j] += win[j] * wk;
#pragma unroll
        for (int j = 0; j < 7; j++) win[j] = win[j + 1];
        win[7] = bufB[s0 + 8 + k];
    }
    __syncthreads();
#pragma unroll
    for (int j = 0; j < 8; j++) bufA[32 + s0 + j] = acc[j];
    __syncthreads();
    float mwd = mw[d];
#pragma unroll
    for (int j = 0; j < 8; j++) { acc[j] = 0.f; win[j] = bufA[s0 + j]; }
#pragma unroll
    for (int k = 0; k < 64; k++) {
        float wk = wB[k];
#pragma unroll
        for (int j = 0; j < 8; j++) acc[j] += win[j] * wk;
#pragma unroll
        for (int j = 0; j < 7; j++) win[j] = win[j + 1];
        win[7] = bufA[s0 + 8 + k];
    }
    float* outp = yT + (size_t)bd * S_;
#pragma unroll
    for (int j = 0; j < 8; j++) {
        float m = acc[j] * mwd;
        outp[s0 + j] = m / (1.0f + expf(-m));
    }
}

// ---------------------------------------------------------------------------
// yT (B,D,S) fp32 -> y (B,S,D) hi/lo bf16 (A matrix of refine GEMM)
// grid (S/32, D/32, B), block (32,8)
// ---------------------------------------------------------------------------
__global__ void y_tsplit_kernel(const float* __restrict__ yT,
                                __nv_bfloat16* __restrict__ yh,
                                __nv_bfloat16* __restrict__ yl) {
    __shared__ float tile[32][33];
    int b  = blockIdx.z;
    int s0 = blockIdx.x * 32, d0 = blockIdx.y * 32;
    int tx = threadIdx.x, ty = threadIdx.y;
#pragma unroll
    for (int i = 0; i < 4; i++)
        tile[ty + i * 8][tx] = yT[((size_t)(b * D_ + d0 + ty + i * 8)) * S_ + s0 + tx];
    __syncthreads();
#pragma unroll
    for (int i = 0; i < 4; i++) {
        float val = tile[tx][ty + i * 8];
        __nv_bfloat16 h, l;
        bf_split(val, h, l);
        size_t o = (size_t)(b * S_ + s0 + ty + i * 8) * D_ + d0 + tx;
        yh[o] = h; yl[o] = l;
    }
}

// ---------------------------------------------------------------------------
// Split-2 bf16 tensor-core GEMM:
//   C = (Ahi+Alo)(Bhi+Blo)^T  ≈  Ahi·Bhi + Ahi·Blo + Alo·Bhi   (fp32 accum)
// A [M][K], B [N][K], both row-major bf16 (k contiguous).
// CTA 128x128, BK=16, 8 warps (64x32 warp tiles), cp.async double-buffered.
// EPI 0: C = acc + bias (fp32)
// EPI 1: gate combine: s=sigmoid(acc+bias); C = s*refined+(1-s)*orig,
//        also emits hi/lo bf16 of C for the next layer's gate GEMM.
// ---------------------------------------------------------------------------
__device__ __forceinline__ void cp16(void* s, const void* g) {
    uint32_t sa = (uint32_t)__cvta_generic_to_shared(s);
    asm volatile("cp.async.cg.shared.global [%0], [%1], 16;\n" :: "r"(sa), "l"(g));
}
__device__ __forceinline__ void cp_commit() {
    asm volatile("cp.async.commit_group;\n" ::: "memory");
}
template<int N_> __device__ __forceinline__ void cp_wait() {
    asm volatile("cp.async.wait_group %0;\n" :: "n"(N_) : "memory");
}
__device__ __forceinline__ void mma_bf16(float* c, const uint32_t* a, const uint32_t* b) {
    asm volatile(
        "mma.sync.aligned.m16n8k16.row.col.f32.bf16.bf16.f32 "
        "{%0,%1,%2,%3}, {%4,%5,%6,%7}, {%8,%9}, {%0,%1,%2,%3};"
        : "+f"(c[0]), "+f"(c[1]), "+f"(c[2]), "+f"(c[3])
        : "r"(a[0]), "r"(a[1]), "r"(a[2]), "r"(a[3]), "r"(b[0]), "r"(b[1]));
}

template<int EPI>
__global__ void __launch_bounds__(256, 2) gemm_bf(
        const __nv_bfloat16* __restrict__ Ahi, const __nv_bfloat16* __restrict__ Alo,
        const __nv_bfloat16* __restrict__ Bhi, const __nv_bfloat16* __restrict__ Blo,
        const float* __restrict__ bias,
        const float* __restrict__ refined, const float* __restrict__ orig,
        float* __restrict__ C,
        __nv_bfloat16* __restrict__ Chi, __nv_bfloat16* __restrict__ Clo,
        int M, int N, int K)
{
    constexpr int ST = 24;   // bf16 elems per smem row (48B -> conflict-free g*12+t)
    __shared__ __nv_bfloat16 sAh[2][128 * ST], sAl[2][128 * ST];
    __shared__ __nv_bfloat16 sBh[2][128 * ST], sBl[2][128 * ST];   // 48KB total

    int tid  = threadIdx.x;
    int lane = tid & 31;
    int warp = tid >> 5;
    int g = lane >> 2, t = lane & 3;
    int wm = (warp >> 2) * 64;
    int wn = (warp & 3) * 32;
    int m0 = blockIdx.x * 128, n0 = blockIdx.y * 128;

    int lrow = tid >> 1, lkc = (tid & 1) * 8;

    float acc[4][4][4];
#pragma unroll
    for (int mi = 0; mi < 4; mi++)
#pragma unroll
        for (int ni = 0; ni < 4; ni++)
#pragma unroll
            for (int r = 0; r < 4; r++) acc[mi][ni][r] = 0.f;

    auto load_tiles = [&](int buf, int k0) {
        size_t ga = (size_t)(m0 + lrow) * K + k0 + lkc;
        size_t gb = (size_t)(n0 + lrow) * K + k0 + lkc;
        int so = lrow * ST + lkc;
        cp16(&sAh[buf][so], Ahi + ga);
        cp16(&sAl[buf][so], Alo + ga);
        cp16(&sBh[buf][so], Bhi + gb);
        cp16(&sBl[buf][so], Blo + gb);
    };

    int KT = K >> 4;
    load_tiles(0, 0); cp_commit();

    for (int kt = 0; kt < KT; kt++) {
        int cur = kt & 1;
        if (kt + 1 < KT) {
            load_tiles(cur ^ 1, (kt + 1) * 16);
            cp_commit();
            cp_wait<1>();
        } else {
            cp_wait<0>();
        }
        __syncthreads();

        uint32_t bh[4][2], bl[4][2];
#pragma unroll
        for (int ni = 0; ni < 4; ni++) {
            int base = (wn + ni * 8 + g) * ST + 2 * t;
            bh[ni][0] = *(const uint32_t*)&sBh[cur][base];
            bh[ni][1] = *(const uint32_t*)&sBh[cur][base + 8];
            bl[ni][0] = *(const uint32_t*)&sBl[cur][base];
            bl[ni][1] = *(const uint32_t*)&sBl[cur][base + 8];
        }
#pragma unroll
        for (int mi = 0; mi < 4; mi++) {
            int b0 = (wm + mi * 16 + g) * ST + 2 * t;
            uint32_t ah[4], al[4];
            ah[0] = *(const uint32_t*)&sAh[cur][b0];
            ah[1] = *(const uint32_t*)&sAh[cur][b0 + 8 * ST];
            ah[2] = *(const uint32_t*)&sAh[cur][b0 + 8];
            ah[3] = *(const uint32_t*)&sAh[cur][b0 + 8 * ST + 8];
            al[0] = *(const uint32_t*)&sAl[cur][b0];
            al[1] = *(const uint32_t*)&sAl[cur][b0 + 8 * ST];
            al[2] = *(const uint32_t*)&sAl[cur][b0 + 8];
            al[3] = *(const uint32_t*)&sAl[cur][b0 + 8 * ST + 8];
#pragma unroll
            for (int ni = 0; ni < 4; ni++) {
                mma_bf16(acc[mi][ni], ah, bh[ni]);
                mma_bf16(acc[mi][ni], ah, bl[ni]);
                mma_bf16(acc[mi][ni], al, bh[ni]);
            }
        }
        __syncthreads();
    }

    // Epilogue. c0:(g,2t) c1:(g,2t+1) c2:(g+8,2t) c3:(g+8,2t+1)
#pragma unroll
    for (int mi = 0; mi < 4; mi++) {
        int r0 = m0 + wm + mi * 16 + g;
#pragma unroll
        for (int ni = 0; ni < 4; ni++) {
            int c0 = n0 + wn + ni * 8 + t * 2;
            float bv0 = bias[c0], bv1 = bias[c0 + 1];
            size_t o0 = (size_t)r0 * N + c0;
            size_t o1 = (size_t)(r0 + 8) * N + c0;
            float* a4 = acc[mi][ni];
            if (EPI == 0) {
                C[o0]     = a4[0] + bv0;
                C[o0 + 1] = a4[1] + bv1;
                C[o1]     = a4[2] + bv0;
                C[o1 + 1] = a4[3] + bv1;
            } else {
                float pre[4] = {a4[0] + bv0, a4[1] + bv1, a4[2] + bv0, a4[3] + bv1};
                size_t offs[4] = {o0, o0 + 1, o1, o1 + 1};
#pragma unroll
                for (int j = 0; j < 4; j++) {
                    float gt = 1.f / (1.f + expf(-pre[j]));
                    float res = gt * refined[offs[j]] + (1.f - gt) * orig[offs[j]];
                    C[offs[j]] = res;
                    __nv_bfloat16 h, l;
                    bf_split(res, h, l);
                    Chi[offs[j]] = h;
                    Clo[offs[j]] = l;
                }
            }
        }
    }
}

// ---------------------------------------------------------------------------
// Host orchestration
// ---------------------------------------------------------------------------
static void* sym_addr(const void* sym) {
    void* p = nullptr;
    cudaGetSymbolAddress(&p, sym);
    return p;
}

extern "C" void kernel_launch(void* const* d_in, const int* in_sizes, int n_in,
                              void* d_out, int out_size) {
    (void)in_sizes; (void)n_in; (void)out_size;
    const int*   ids   = (const int*)d_in[0];
    const float* emb   = (const float*)d_in[1];
    const float* lw    = (const float*)d_in[2];   // (NL, D, 3)
    const float* fw    = (const float*)d_in[3];   // (NL, 2, D, 64)
    const float* mw    = (const float*)d_in[4];   // (NL, D)
    const float* ln1g  = (const float*)d_in[5];
    const float* ln1b  = (const float*)d_in[6];
    const float* refW  = (const float*)d_in[7];   // (NL, D, D)  [N][K]
    const float* refb  = (const float*)d_in[8];
    const float* gateW = (const float*)d_in[9];   // (NL, D, D)  [N][K]
    const float* gateb = (const float*)d_in[10];
    const float* lnfg  = (const float*)d_in[11];
    const float* lnfb  = (const float*)d_in[12];
    const float* outW  = (const float*)d_in[13];  // (D, V) -> transposed to [V][D]
    const float* outb  = (const float*)d_in[14];
    float* out = (float*)d_out;

    float*  x0  = (float*)sym_addr(g_x0);
    float*  x1  = (float*)sym_addr(g_x1);
    float*  hT  = (float*)sym_addr(g_hT);
    float*  yT  = (float*)sym_addr(g_yT);
    float*  rf  = (float*)sym_addr(g_ref);
    float2* st  = (float2*)sym_addr(g_stats);
    __nv_bfloat16* x0h = (__nv_bfloat16*)sym_addr(g_x0h);
    __nv_bfloat16* x0l = (__nv_bfloat16*)sym_addr(g_x0l);
    __nv_bfloat16* x1h = (__nv_bfloat16*)sym_addr(g_x1h);
    __nv_bfloat16* x1l = (__nv_bfloat16*)sym_addr(g_x1l);
    __nv_bfloat16* yh  = (__nv_bfloat16*)sym_addr(g_yh);
    __nv_bfloat16* yl  = (__nv_bfloat16*)sym_addr(g_yl);
    __nv_bfloat16* xfh = (__nv_bfloat16*)sym_addr(g_xfh);
    __nv_bfloat16* xfl = (__nv_bfloat16*)sym_addr(g_xfl);
    __nv_bfloat16* wrh = (__nv_bfloat16*)sym_addr(g_wrh);
    __nv_bfloat16* wrl = (__nv_bfloat16*)sym_addr(g_wrl);
    __nv_bfloat16* wgh = (__nv_bfloat16*)sym_addr(g_wgh);
    __nv_bfloat16* wgl = (__nv_bfloat16*)sym_addr(g_wgl);
    __nv_bfloat16* woh = (__nv_bfloat16*)sym_addr(g_woh);
    __nv_bfloat16* wol = (__nv_bfloat16*)sym_addr(g_wol);

    // Weight preprocessing (every call; deterministic)
    {
        int n4 = NL_ * D_ * D_ / 4;
        split_kernel<<<(n4 + 255) / 256, 256>>>(refW,  wrh, wrl, n4);
        split_kernel<<<(n4 + 255) / 256, 256>>>(gateW, wgh, wgl, n4);
        wout_tsplit_kernel<<<dim3(V_ / 32, D_ / 32), dim3(32, 8)>>>(outW, woh, wol);
    }

    embed_kernel<<<M_, 256>>>(ids, emb, x0, x0h, x0l);

    float* cur = x0;        float* nxt = x1;
    __nv_bfloat16 *curh = x0h, *curl = x0l, *nxth = x1h, *nxtl = x1l;
    for (int l = 0; l < NL_; l++) {
        ln_stats_kernel<<<M_, 256>>>(cur, st);
        ln_transpose_kernel<<<dim3(S_/32, D_/32, B_), dim3(32, 8)>>>(
            cur, st, ln1g + (size_t)l * D_, ln1b + (size_t)l * D_, hT);
        conv_kernel<<<B_*D_, 256>>>(
            hT, lw + (size_t)l * D_ * 3, fw + (size_t)l * 2 * D_ * 64,
            mw + (size_t)l * D_, yT);
        y_tsplit_kernel<<<dim3(S_/32, D_/32, B_), dim3(32, 8)>>>(yT, yh, yl);
        gemm_bf<0><<<dim3(M_/128, D_/128), 256>>>(
            yh, yl, wrh + (size_t)l * D_ * D_, wrl + (size_t)l * D_ * D_,
            refb + (size_t)l * D_, nullptr, nullptr, rf, nullptr, nullptr,
            M_, D_, D_);
        gemm_bf<1><<<dim3(M_/128, D_/128), 256>>>(
            curh, curl, wgh + (size_t)l * D_ * D_, wgl + (size_t)l * D_ * D_,
            gateb + (size_t)l * D_, rf, cur, nxt, nxth, nxtl,
            M_, D_, D_);
        { float* tf = cur; cur = nxt; nxt = tf; }
        { __nv_bfloat16* tb;
          tb = curh; curh = nxth; nxth = tb;
          tb = curl; curl = nxtl; nxtl = tb; }
    }

    ln_stats_kernel<<<M_, 256>>>(cur, st);
    apply_ln_kernel<<<M_, 256>>>(cur, st, lnfg, lnfb, xfh, xfl);
    gemm_bf<0><<<dim3(M_/128, V_/128), 256>>>(
        xfh, xfl, woh, wol, outb, nullptr, nullptr, out, nullptr, nullptr,
        M_, V_, D_);
}

// round 5
// speedup vs baseline: 2.1128x; 1.1034x over previous
#include <cuda_runtime.h>
#include <cuda_bf16.h>
#include <math.h>
#include <stdint.h>

#define B_  2
#define S_  2048
#define D_  1024
#define V_  32000
#define NL_ 6
#define M_  (B_*S_)   // 4096 tokens

// ---------------------------------------------------------------------------
// Scratch
// ---------------------------------------------------------------------------
__device__ float  g_x0[M_*D_];
__device__ float  g_x1[M_*D_];
__device__ float  g_hT[M_*D_];
__device__ float  g_yT[M_*D_];
__device__ float  g_ref[M_*D_];
__device__ float2 g_stats[M_];

__device__ __nv_bfloat16 g_x0h[M_*D_], g_x0l[M_*D_];
__device__ __nv_bfloat16 g_x1h[M_*D_], g_x1l[M_*D_];
__device__ __nv_bfloat16 g_yh [M_*D_], g_yl [M_*D_];
__device__ __nv_bfloat16 g_xfh[M_*D_], g_xfl[M_*D_];
__device__ __nv_bfloat16 g_wrh[NL_*D_*D_], g_wrl[NL_*D_*D_];
__device__ __nv_bfloat16 g_wgh[NL_*D_*D_], g_wgl[NL_*D_*D_];
__device__ __nv_bfloat16 g_woh[(size_t)V_*D_], g_wol[(size_t)V_*D_];

__device__ __forceinline__ void bf_split(float x, __nv_bfloat16& h, __nv_bfloat16& l) {
    h = __float2bfloat16(x);
    l = __float2bfloat16(x - __bfloat162float(h));
}

// ---------------------------------------------------------------------------
// PTX helpers
// ---------------------------------------------------------------------------
__device__ __forceinline__ uint32_t smem_u32(const void* p) {
    uint32_t a;
    asm("{ .reg .u64 t; cvta.to.shared.u64 t, %1; cvt.u32.u64 %0, t; }" : "=r"(a) : "l"(p));
    return a;
}
__device__ __forceinline__ void cp16s(uint32_t saddr, const void* g) {
    asm volatile("cp.async.cg.shared.global [%0], [%1], 16;\n" :: "r"(saddr), "l"(g));
}
__device__ __forceinline__ void cp_commit() {
    asm volatile("cp.async.commit_group;\n" ::: "memory");
}
template<int N_> __device__ __forceinline__ void cp_wait() {
    asm volatile("cp.async.wait_group %0;\n" :: "n"(N_) : "memory");
}
__device__ __forceinline__ void mma_bf16(float* c, const uint32_t* a, const uint32_t* b) {
    asm volatile(
        "mma.sync.aligned.m16n8k16.row.col.f32.bf16.bf16.f32 "
        "{%0,%1,%2,%3}, {%4,%5,%6,%7}, {%8,%9}, {%0,%1,%2,%3};"
        : "+f"(c[0]), "+f"(c[1]), "+f"(c[2]), "+f"(c[3])
        : "r"(a[0]), "r"(a[1]), "r"(a[2]), "r"(a[3]), "r"(b[0]), "r"(b[1]));
}
#define LDSM4(r0, r1, r2, r3, addr) \
    asm volatile("ldmatrix.sync.aligned.m8n8.x4.shared.b16 {%0,%1,%2,%3}, [%4];" \
        : "=r"(r0), "=r"(r1), "=r"(r2), "=r"(r3) : "r"(addr))

// ---------------------------------------------------------------------------
// Split-2 bf16 tensor GEMM with ldmatrix + 3-stage cp.async pipeline.
//   C = Ahi*Bhi + Ahi*Blo + Alo*Bhi  (fp32 accum)
// A [M][K], B [N][K] bf16 k-contiguous. CTA 128x128, BK=16, 8 warps (64x32).
// smem row stride 48B (24 bf16): bank-rotation 3/8 -> conflict-free ldmatrix.
// EPI 0: C = acc + bias.  EPI 1: sigmoid-gate combine + hi/lo re-split.
// ---------------------------------------------------------------------------
#define RSTR   48                    // bytes per smem row
#define TILE_B (128 * RSTR)          // 6144 B per operand tile
#define STAGE_B (4 * TILE_B)         // 24576 B per stage
#define GEMM_SMEM (3 * STAGE_B)      // 73728 B

template<int EPI>
__global__ void __launch_bounds__(256, 2) gemm_bf(
        const __nv_bfloat16* __restrict__ Ahi, const __nv_bfloat16* __restrict__ Alo,
        const __nv_bfloat16* __restrict__ Bhi, const __nv_bfloat16* __restrict__ Blo,
        const float* __restrict__ bias,
        const float* __restrict__ refined, const float* __restrict__ orig,
        float* __restrict__ C,
        __nv_bfloat16* __restrict__ Chi, __nv_bfloat16* __restrict__ Clo,
        int M, int N, int K)
{
    extern __shared__ char smem[];
    uint32_t sb = smem_u32(smem);

    int tid  = threadIdx.x;
    int lane = tid & 31;
    int warp = tid >> 5;
    int g = lane >> 2, t = lane & 3;
    int wm = (warp >> 2) * 64;
    int wn = (warp & 3) * 32;
    int m0 = blockIdx.x * 128, n0 = blockIdx.y * 128;

    // ldmatrix per-lane byte offsets within a tile
    // A .x4: m0=(rows0-7,k0) m1=(rows8-15,k0) m2=(rows0-7,k8) m3=(rows8-15,k8)
    uint32_t aoff = (uint32_t)((((lane & 7) + ((lane >> 3) & 1) * 8) * RSTR) + ((lane >> 4) & 1) * 16);
    // B .x4: m0=(n0-7,k0) m1=(n0-7,k8) m2=(n8-15,k0) m3=(n8-15,k8)
    uint32_t boff = (uint32_t)((((lane & 7) + ((lane >> 4) & 1) * 8) * RSTR) + ((lane >> 3) & 1) * 16);

    // cp.async mapping: 128 rows x 2 chunks of 16B
    int lr = tid >> 1;
    int lc8 = (tid & 1) * 8;             // elem offset
    uint32_t so = (uint32_t)(lr * RSTR + (tid & 1) * 16);

    float acc[4][4][4];
#pragma unroll
    for (int mi = 0; mi < 4; mi++)
#pragma unroll
        for (int ni = 0; ni < 4; ni++)
#pragma unroll
            for (int r = 0; r < 4; r++) acc[mi][ni][r] = 0.f;

    auto load_stage = [&](int st, int kt) {
        int k0 = kt * 16;
        uint32_t base = sb + (uint32_t)st * STAGE_B;
        size_t ga = (size_t)(m0 + lr) * K + k0 + lc8;
        size_t gb = (size_t)(n0 + lr) * K + k0 + lc8;
        cp16s(base + so,              Ahi + ga);
        cp16s(base + TILE_B + so,     Alo + ga);
        cp16s(base + 2 * TILE_B + so, Bhi + gb);
        cp16s(base + 3 * TILE_B + so, Blo + gb);
    };

    int KT = K >> 4;
    load_stage(0, 0); cp_commit();
    load_stage(1, 1); cp_commit();

    for (int kt = 0; kt < KT; kt++) {
        if (kt == KT - 1) cp_wait<0>(); else cp_wait<1>();
        __syncthreads();
        if (kt + 2 < KT) { load_stage((kt + 2) % 3, kt + 2); cp_commit(); }

        uint32_t base = sb + (uint32_t)(kt % 3) * STAGE_B;
        uint32_t tAh = base, tAl = base + TILE_B;
        uint32_t tBh = base + 2 * TILE_B, tBl = base + 3 * TILE_B;

        uint32_t af[16], bh[8], bl[8];
        LDSM4(bh[0], bh[1], bh[2], bh[3], tBh + (uint32_t)(wn * RSTR) + boff);
        LDSM4(bh[4], bh[5], bh[6], bh[7], tBh + (uint32_t)((wn + 16) * RSTR) + boff);
#pragma unroll
        for (int mi = 0; mi < 4; mi++)
            LDSM4(af[mi*4], af[mi*4+1], af[mi*4+2], af[mi*4+3],
                  tAh + (uint32_t)((wm + mi * 16) * RSTR) + aoff);
#pragma unroll
        for (int mi = 0; mi < 4; mi++)
#pragma unroll
            for (int ni = 0; ni < 4; ni++)
                mma_bf16(acc[mi][ni], &af[mi*4], &bh[ni*2]);

        LDSM4(bl[0], bl[1], bl[2], bl[3], tBl + (uint32_t)(wn * RSTR) + boff);
        LDSM4(bl[4], bl[5], bl[6], bl[7], tBl + (uint32_t)((wn + 16) * RSTR) + boff);
#pragma unroll
        for (int mi = 0; mi < 4; mi++)
#pragma unroll
            for (int ni = 0; ni < 4; ni++)
                mma_bf16(acc[mi][ni], &af[mi*4], &bl[ni*2]);

#pragma unroll
        for (int mi = 0; mi < 4; mi++)
            LDSM4(af[mi*4], af[mi*4+1], af[mi*4+2], af[mi*4+3],
                  tAl + (uint32_t)((wm + mi * 16) * RSTR) + aoff);
#pragma unroll
        for (int mi = 0; mi < 4; mi++)
#pragma unroll
            for (int ni = 0; ni < 4; ni++)
                mma_bf16(acc[mi][ni], &af[mi*4], &bh[ni*2]);
    }

    // Epilogue. c0:(g,2t) c1:(g,2t+1) c2:(g+8,2t) c3:(g+8,2t+1)
#pragma unroll
    for (int mi = 0; mi < 4; mi++) {
        int r0 = m0 + wm + mi * 16 + g;
#pragma unroll
        for (int ni = 0; ni < 4; ni++) {
            int c0 = n0 + wn + ni * 8 + t * 2;
            float bv0 = bias[c0], bv1 = bias[c0 + 1];
            size_t o0 = (size_t)r0 * N + c0;
            size_t o1 = (size_t)(r0 + 8) * N + c0;
            float* a4 = acc[mi][ni];
            if (EPI == 0) {
                C[o0]     = a4[0] + bv0;
                C[o0 + 1] = a4[1] + bv1;
                C[o1]     = a4[2] + bv0;
                C[o1 + 1] = a4[3] + bv1;
            } else {
                float pre[4] = {a4[0] + bv0, a4[1] + bv1, a4[2] + bv0, a4[3] + bv1};
                size_t offs[4] = {o0, o0 + 1, o1, o1 + 1};
#pragma unroll
                for (int j = 0; j < 4; j++) {
                    float gt = 1.f / (1.f + expf(-pre[j]));
                    float res = gt * refined[offs[j]] + (1.f - gt) * orig[offs[j]];
                    C[offs[j]] = res;
                    __nv_bfloat16 h, l;
                    bf_split(res, h, l);
                    Chi[offs[j]] = h;
                    Clo[offs[j]] = l;
                }
            }
        }
    }
}

// ---------------------------------------------------------------------------
// Embedding + sinusoidal PE (+ hi/lo split)
// ---------------------------------------------------------------------------
__global__ void embed_kernel(const int* __restrict__ ids,
                             const float* __restrict__ emb,
                             float* __restrict__ x,
                             __nv_bfloat16* __restrict__ xh,
                             __nv_bfloat16* __restrict__ xl) {
    int row = blockIdx.x;
    int s   = row & (S_ - 1);
    int tok = ids[row];
    int d0  = threadIdx.x * 4;
    float4 e = *(const float4*)(emb + (size_t)tok * D_ + d0);
    const float cln = -logf(10000.0f) / (float)D_;
    float pe[4];
#pragma unroll
    for (int j = 0; j < 4; j += 2) {
        float freq = expf(cln * (float)(d0 + j));
        float a = (float)s * freq;
        pe[j]   = sinf(a);
        pe[j+1] = cosf(a);
    }
    float o[4] = {e.x + pe[0], e.y + pe[1], e.z + pe[2], e.w + pe[3]};
    *(float4*)(x + (size_t)row * D_ + d0) = *(float4*)o;
    ushort4 h4, l4;
    __nv_bfloat16 h, l;
    bf_split(o[0], h, l); h4.x = *(unsigned short*)&h; l4.x = *(unsigned short*)&l;
    bf_split(o[1], h, l); h4.y = *(unsigned short*)&h; l4.y = *(unsigned short*)&l;
    bf_split(o[2], h, l); h4.z = *(unsigned short*)&h; l4.z = *(unsigned short*)&l;
    bf_split(o[3], h, l); h4.w = *(unsigned short*)&h; l4.w = *(unsigned short*)&l;
    *(ushort4*)(xh + (size_t)row * D_ + d0) = h4;
    *(ushort4*)(xl + (size_t)row * D_ + d0) = l4;
}

// ---------------------------------------------------------------------------
// Weight split
// ---------------------------------------------------------------------------
__global__ void split_kernel(const float* __restrict__ w,
                             __nv_bfloat16* __restrict__ hi,
                             __nv_bfloat16* __restrict__ lo, int n4) {
    int i = blockIdx.x * 256 + threadIdx.x;
    if (i >= n4) return;
    float4 v = ((const float4*)w)[i];
    ushort4 h4, l4; __nv_bfloat16 h, l;
    bf_split(v.x, h, l); h4.x = *(unsigned short*)&h; l4.x = *(unsigned short*)&l;
    bf_split(v.y, h, l); h4.y = *(unsigned short*)&h; l4.y = *(unsigned short*)&l;
    bf_split(v.z, h, l); h4.z = *(unsigned short*)&h; l4.z = *(unsigned short*)&l;
    bf_split(v.w, h, l); h4.w = *(unsigned short*)&h; l4.w = *(unsigned short*)&l;
    ((ushort4*)hi)[i] = h4;
    ((ushort4*)lo)[i] = l4;
}

// ---------------------------------------------------------------------------
// outW (D,V) -> [V][D] hi/lo bf16
// ---------------------------------------------------------------------------
__global__ void wout_tsplit_kernel(const float* __restrict__ w,
                                   __nv_bfloat16* __restrict__ hi,
                                   __nv_bfloat16* __restrict__ lo) {
    __shared__ float tile[32][33];
    int v0 = blockIdx.x * 32, d0 = blockIdx.y * 32;
    int tx = threadIdx.x, ty = threadIdx.y;
#pragma unroll
    for (int i = 0; i < 4; i++)
        tile[ty + i * 8][tx] = w[(size_t)(d0 + ty + i * 8) * V_ + v0 + tx];
    __syncthreads();
#pragma unroll
    for (int i = 0; i < 4; i++) {
        float val = tile[tx][ty + i * 8];
        __nv_bfloat16 h, l;
        bf_split(val, h, l);
        size_t o = (size_t)(v0 + ty + i * 8) * D_ + d0 + tx;
        hi[o] = h; lo[o] = l;
    }
}

// ---------------------------------------------------------------------------
// LayerNorm statistics
// ---------------------------------------------------------------------------
__global__ void ln_stats_kernel(const float* __restrict__ x, float2* __restrict__ stats) {
    int row = blockIdx.x;
    float4 v = ((const float4*)(x + (size_t)row * D_))[threadIdx.x];
    float s = v.x + v.y + v.z + v.w;
    float q = v.x*v.x + v.y*v.y + v.z*v.z + v.w*v.w;
#pragma unroll
    for (int o = 16; o; o >>= 1) {
        s += __shfl_xor_sync(0xffffffffu, s, o);
        q += __shfl_xor_sync(0xffffffffu, q, o);
    }
    __shared__ float ss[8], sq[8];
    int w = threadIdx.x >> 5;
    if ((threadIdx.x & 31) == 0) { ss[w] = s; sq[w] = q; }
    __syncthreads();
    if (threadIdx.x == 0) {
        float S = 0.f, Q = 0.f;
#pragma unroll
        for (int i = 0; i < 8; i++) { S += ss[i]; Q += sq[i]; }
        float mu  = S / (float)D_;
        float var = Q / (float)D_ - mu * mu;
        stats[row] = make_float2(mu, rsqrtf(var + 1e-5f));
    }
}

// ---------------------------------------------------------------------------
// Apply LN while transposing (B,S,D)->(B,D,S)
// ---------------------------------------------------------------------------
__global__ void ln_transpose_kernel(const float* __restrict__ x,
                                    const float2* __restrict__ stats,
                                    const float* __restrict__ g,
                                    const float* __restrict__ bta,
                                    float* __restrict__ hT) {
    __shared__ float tile[32][33];
    int b  = blockIdx.z;
    int s0 = blockIdx.x * 32, d0 = blockIdx.y * 32;
    int tx = threadIdx.x, ty = threadIdx.y;
    float gg = g[d0 + tx], bb = bta[d0 + tx];
#pragma unroll
    for (int i = 0; i < 4; i++) {
        int s = s0 + ty + i * 8;
        float2 st = stats[b * S_ + s];
        float v = x[((size_t)(b * S_ + s)) * D_ + d0 + tx];
        tile[ty + i * 8][tx] = (v - st.x) * st.y * gg + bb;
    }
    __syncthreads();
#pragma unroll
    for (int i = 0; i < 4; i++) {
        int d = d0 + ty + i * 8;
        hT[((size_t)(b * D_ + d)) * S_ + s0 + tx] = tile[tx][ty + i * 8];
    }
}

// ---------------------------------------------------------------------------
// Final LN apply -> hi/lo bf16
// ---------------------------------------------------------------------------
__global__ void apply_ln_kernel(const float* __restrict__ x,
                                const float2* __restrict__ stats,
                                const float* __restrict__ g,
                                const float* __restrict__ b,
                                __nv_bfloat16* __restrict__ oh,
                                __nv_bfloat16* __restrict__ ol) {
    int row = blockIdx.x;
    int d0 = threadIdx.x * 4;
    float2 st = stats[row];
    float4 v  = *(const float4*)(x + (size_t)row * D_ + d0);
    float4 gg = *(const float4*)(g + d0);
    float4 bb = *(const float4*)(b + d0);
    float r[4];
    r[0] = (v.x - st.x) * st.y * gg.x + bb.x;
    r[1] = (v.y - st.x) * st.y * gg.y + bb.y;
    r[2] = (v.z - st.x) * st.y * gg.z + bb.z;
    r[3] = (v.w - st.x) * st.y * gg.w + bb.w;
    ushort4 h4, l4; __nv_bfloat16 h, l;
    bf_split(r[0], h, l); h4.x = *(unsigned short*)&h; l4.x = *(unsigned short*)&l;
    bf_split(r[1], h, l); h4.y = *(unsigned short*)&h; l4.y = *(unsigned short*)&l;
    bf_split(r[2], h, l); h4.z = *(unsigned short*)&h; l4.z = *(unsigned short*)&l;
    bf_split(r[3], h, l); h4.w = *(unsigned short*)&h; l4.w = *(unsigned short*)&l;
    *(ushort4*)(oh + (size_t)row * D_ + d0) = h4;
    *(ushort4*)(ol + (size_t)row * D_ + d0) = l4;
}

// ---------------------------------------------------------------------------
// Depthwise conv chain per (b,d) channel
// ---------------------------------------------------------------------------
__global__ void __launch_bounds__(256) conv_kernel(const float* __restrict__ hT,
                                                   const float* __restrict__ lw,
                                                   const float* __restrict__ fw,
                                                   const float* __restrict__ mw,
                                                   float* __restrict__ yT) {
    int bd = blockIdx.x;
    int d  = bd & (D_ - 1);
    __shared__ float bufA[S_ + 64];
    __shared__ float bufB[S_ + 64];
    __shared__ float w3[3], wA[64], wB[64];
    int tid = threadIdx.x;
    if (tid < 64) {
        wA[tid] = fw[(size_t)d * 64 + tid];
        wB[tid] = fw[(size_t)(D_ + d) * 64 + tid];
    }
    if (tid < 3) w3[tid] = lw[d * 3 + tid];
    if (tid < 32) {
        bufA[tid] = 0.f; bufA[S_ + 32 + tid] = 0.f;
        bufB[tid] = 0.f; bufB[S_ + 32 + tid] = 0.f;
    }
    const float* cin = hT + (size_t)bd * S_;
    for (int i = tid; i < S_ / 4; i += 256)
        ((float4*)(bufA + 32))[i] = ((const float4*)cin)[i];
    __syncthreads();
    for (int s = tid; s < S_; s += 256)
        bufB[32 + s] = bufA[31 + s] * w3[0] + bufA[32 + s] * w3[1] + bufA[33 + s] * w3[2];
    __syncthreads();

    int s0 = tid * 8;
    float acc[8], win[8];
#pragma unroll
    for (int j = 0; j < 8; j++) { acc[j] = bufA[32 + s0 + j]; win[j] = bufB[s0 + j]; }
#pragma unroll
    for (int k = 0; k < 64; k++) {
        float wk = wA[k];
#pragma unroll
        for (int j = 0; j < 8; j++) acc[j] += win[j] * wk;
#pragma unroll
        for (int j = 0; j < 7; j++) win[j] = win[j + 1];
        win[7] = bufB[s0 + 8 + k];
    }
    __syncthreads();
#pragma unroll
    for (int j = 0; j < 8; j++) bufA[32 + s0 + j] = acc[j];
    __syncthreads();
    float mwd = mw[d];
#pragma unroll
    for (int j = 0; j < 8; j++) { acc[j] = 0.f; win[j] = bufA[s0 + j]; }
#pragma unroll
    for (int k = 0; k < 64; k++) {
        float wk = wB[k];
#pragma unroll
        for (int j = 0; j < 8; j++) acc[j] += win[j] * wk;
#pragma unroll
        for (int j = 0; j < 7; j++) win[j] = win[j + 1];
        win[7] = bufA[s0 + 8 + k];
    }
    float* outp = yT + (size_t)bd * S_;
#pragma unroll
    for (int j = 0; j < 8; j++) {
        float m = acc[j] * mwd;
        outp[s0 + j] = m / (1.0f + expf(-m));
    }
}

// ---------------------------------------------------------------------------
// yT (B,D,S) -> y (B,S,D) hi/lo bf16
// ---------------------------------------------------------------------------
__global__ void y_tsplit_kernel(const float* __restrict__ yT,
                                __nv_bfloat16* __restrict__ yh,
                                __nv_bfloat16* __restrict__ yl) {
    __shared__ float tile[32][33];
    int b  = blockIdx.z;
    int s0 = blockIdx.x * 32, d0 = blockIdx.y * 32;
    int tx = threadIdx.x, ty = threadIdx.y;
#pragma unroll
    for (int i = 0; i < 4; i++)
        tile[ty + i * 8][tx] = yT[((size_t)(b * D_ + d0 + ty + i * 8)) * S_ + s0 + tx];
    __syncthreads();
#pragma unroll
    for (int i = 0; i < 4; i++) {
        float val = tile[tx][ty + i * 8];
        __nv_bfloat16 h, l;
        bf_split(val, h, l);
        size_t o = (size_t)(b * S_ + s0 + ty + i * 8) * D_ + d0 + tx;
        yh[o] = h; yl[o] = l;
    }
}

// ---------------------------------------------------------------------------
// Host orchestration
// ---------------------------------------------------------------------------
static void* sym_addr(const void* sym) {
    void* p = nullptr;
    cudaGetSymbolAddress(&p, sym);
    return p;
}

extern "C" void kernel_launch(void* const* d_in, const int* in_sizes, int n_in,
                              void* d_out, int out_size) {
    (void)in_sizes; (void)n_in; (void)out_size;
    const int*   ids   = (const int*)d_in[0];
    const float* emb   = (const float*)d_in[1];
    const float* lw    = (const float*)d_in[2];
    const float* fw    = (const float*)d_in[3];
    const float* mw    = (const float*)d_in[4];
    const float* ln1g  = (const float*)d_in[5];
    const float* ln1b  = (const float*)d_in[6];
    const float* refW  = (const float*)d_in[7];
    const float* refb  = (const float*)d_in[8];
    const float* gateW = (const float*)d_in[9];
    const float* gateb = (const float*)d_in[10];
    const float* lnfg  = (const float*)d_in[11];
    const float* lnfb  = (const float*)d_in[12];
    const float* outW  = (const float*)d_in[13];
    const float* outb  = (const float*)d_in[14];
    float* out = (float*)d_out;

    float*  x0  = (float*)sym_addr(g_x0);
    float*  x1  = (float*)sym_addr(g_x1);
    float*  hT  = (float*)sym_addr(g_hT);
    float*  yT  = (float*)sym_addr(g_yT);
    float*  rf  = (float*)sym_addr(g_ref);
    float2* st  = (float2*)sym_addr(g_stats);
    __nv_bfloat16* x0h = (__nv_bfloat16*)sym_addr(g_x0h);
    __nv_bfloat16* x0l = (__nv_bfloat16*)sym_addr(g_x0l);
    __nv_bfloat16* x1h = (__nv_bfloat16*)sym_addr(g_x1h);
    __nv_bfloat16* x1l = (__nv_bfloat16*)sym_addr(g_x1l);
    __nv_bfloat16* yh  = (__nv_bfloat16*)sym_addr(g_yh);
    __nv_bfloat16* yl  = (__nv_bfloat16*)sym_addr(g_yl);
    __nv_bfloat16* xfh = (__nv_bfloat16*)sym_addr(g_xfh);
    __nv_bfloat16* xfl = (__nv_bfloat16*)sym_addr(g_xfl);
    __nv_bfloat16* wrh = (__nv_bfloat16*)sym_addr(g_wrh);
    __nv_bfloat16* wrl = (__nv_bfloat16*)sym_addr(g_wrl);
    __nv_bfloat16* wgh = (__nv_bfloat16*)sym_addr(g_wgh);
    __nv_bfloat16* wgl = (__nv_bfloat16*)sym_addr(g_wgl);
    __nv_bfloat16* woh = (__nv_bfloat16*)sym_addr(g_woh);
    __nv_bfloat16* wol = (__nv_bfloat16*)sym_addr(g_wol);

    cudaFuncSetAttribute(gemm_bf<0>, cudaFuncAttributeMaxDynamicSharedMemorySize, GEMM_SMEM);
    cudaFuncSetAttribute(gemm_bf<1>, cudaFuncAttributeMaxDynamicSharedMemorySize, GEMM_SMEM);

    {
        int n4 = NL_ * D_ * D_ / 4;
        split_kernel<<<(n4 + 255) / 256, 256>>>(refW,  wrh, wrl, n4);
        split_kernel<<<(n4 + 255) / 256, 256>>>(gateW, wgh, wgl, n4);
        wout_tsplit_kernel<<<dim3(V_ / 32, D_ / 32), dim3(32, 8)>>>(outW, woh, wol);
    }

    embed_kernel<<<M_, 256>>>(ids, emb, x0, x0h, x0l);

    float* cur = x0;        float* nxt = x1;
    __nv_bfloat16 *curh = x0h, *curl = x0l, *nxth = x1h, *nxtl = x1l;
    for (int l = 0; l < NL_; l++) {
        ln_stats_kernel<<<M_, 256>>>(cur, st);
        ln_transpose_kernel<<<dim3(S_/32, D_/32, B_), dim3(32, 8)>>>(
            cur, st, ln1g + (size_t)l * D_, ln1b + (size_t)l * D_, hT);
        conv_kernel<<<B_*D_, 256>>>(
            hT, lw + (size_t)l * D_ * 3, fw + (size_t)l * 2 * D_ * 64,
            mw + (size_t)l * D_, yT);
        y_tsplit_kernel<<<dim3(S_/32, D_/32, B_), dim3(32, 8)>>>(yT, yh, yl);
        gemm_bf<0><<<dim3(M_/128, D_/128), 256, GEMM_SMEM>>>(
            yh, yl, wrh + (size_t)l * D_ * D_, wrl + (size_t)l * D_ * D_,
            refb + (size_t)l * D_, nullptr, nullptr, rf, nullptr, nullptr,
            M_, D_, D_);
        gemm_bf<1><<<dim3(M_/128, D_/128), 256, GEMM_SMEM>>>(
            curh, curl, wgh + (size_t)l * D_ * D_, wgl + (size_t)l * D_ * D_,
            gateb + (size_t)l * D_, rf, cur, nxt, nxth, nxtl,
            M_, D_, D_);
        { float* tf = cur; cur = nxt; nxt = tf; }
        { __nv_bfloat16* tb;
          tb = curh; curh = nxth; nxth = tb;
          tb = curl; curl = nxtl; nxtl = tb; }
    }

    ln_stats_kernel<<<M_, 256>>>(cur, st);
    apply_ln_kernel<<<M_, 256>>>(cur, st, lnfg, lnfb, xfh, xfl);
    gemm_bf<0><<<dim3(M_/128, V_/128), 256, GEMM_SMEM>>>(
        xfh, xfl, woh, wol, outb, nullptr, nullptr, out, nullptr, nullptr,
        M_, V_, D_);
}

// round 6
// speedup vs baseline: 3.2805x; 1.5527x over previous
#include <cuda_runtime.h>
#include <cuda_bf16.h>
#include <cuda_fp16.h>
#include <math.h>
#include <stdint.h>

#define B_  2
#define S_  2048
#define D_  1024
#define V_  32000
#define NL_ 6
#define M_  (B_*S_)   // 4096 tokens

// ---------------------------------------------------------------------------
// Scratch
// ---------------------------------------------------------------------------
__device__ float  g_x0[M_*D_];
__device__ float  g_x1[M_*D_];
__device__ float  g_hT[M_*D_];
__device__ float  g_yT[M_*D_];
__device__ float  g_ref[M_*D_];
__device__ float2 g_stats[M_];

__device__ __nv_bfloat16 g_x0h[M_*D_], g_x0l[M_*D_];
__device__ __nv_bfloat16 g_x1h[M_*D_], g_x1l[M_*D_];
__device__ __nv_bfloat16 g_yh [M_*D_], g_yl [M_*D_];
__device__ __nv_bfloat16 g_wrh[NL_*D_*D_], g_wrl[NL_*D_*D_];
__device__ __nv_bfloat16 g_wgh[NL_*D_*D_], g_wgl[NL_*D_*D_];
__device__ __half        g_xf16[M_*D_];
__device__ __half        g_wo16[(size_t)V_*D_];

__device__ __forceinline__ void bf_split(float x, __nv_bfloat16& h, __nv_bfloat16& l) {
    h = __float2bfloat16(x);
    l = __float2bfloat16(x - __bfloat162float(h));
}

// ---------------------------------------------------------------------------
// PTX helpers
// ---------------------------------------------------------------------------
__device__ __forceinline__ uint32_t smem_u32(const void* p) {
    uint32_t a;
    asm("{ .reg .u64 t; cvta.to.shared.u64 t, %1; cvt.u32.u64 %0, t; }" : "=r"(a) : "l"(p));
    return a;
}
__device__ __forceinline__ void cp16s(uint32_t saddr, const void* g) {
    asm volatile("cp.async.cg.shared.global [%0], [%1], 16;\n" :: "r"(saddr), "l"(g));
}
__device__ __forceinline__ void cp_commit() {
    asm volatile("cp.async.commit_group;\n" ::: "memory");
}
template<int N_> __device__ __forceinline__ void cp_wait() {
    asm volatile("cp.async.wait_group %0;\n" :: "n"(N_) : "memory");
}
__device__ __forceinline__ void mma_bf16(float* c, const uint32_t* a, const uint32_t* b) {
    asm volatile(
        "mma.sync.aligned.m16n8k16.row.col.f32.bf16.bf16.f32 "
        "{%0,%1,%2,%3}, {%4,%5,%6,%7}, {%8,%9}, {%0,%1,%2,%3};"
        : "+f"(c[0]), "+f"(c[1]), "+f"(c[2]), "+f"(c[3])
        : "r"(a[0]), "r"(a[1]), "r"(a[2]), "r"(a[3]), "r"(b[0]), "r"(b[1]));
}
__device__ __forceinline__ void mma_fp16(float* c, const uint32_t* a, const uint32_t* b) {
    asm volatile(
        "mma.sync.aligned.m16n8k16.row.col.f32.f16.f16.f32 "
        "{%0,%1,%2,%3}, {%4,%5,%6,%7}, {%8,%9}, {%0,%1,%2,%3};"
        : "+f"(c[0]), "+f"(c[1]), "+f"(c[2]), "+f"(c[3])
        : "r"(a[0]), "r"(a[1]), "r"(a[2]), "r"(a[3]), "r"(b[0]), "r"(b[1]));
}
#define LDSM4(r0, r1, r2, r3, addr) \
    asm volatile("ldmatrix.sync.aligned.m8n8.x4.shared.b16 {%0,%1,%2,%3}, [%4];" \
        : "=r"(r0), "=r"(r1), "=r"(r2), "=r"(r3) : "r"(addr))

#define RSTR   48                    // bytes per smem row
#define TILE_B (128 * RSTR)          // 6144 B per operand tile

// ---------------------------------------------------------------------------
// Split-2 bf16 tensor GEMM (layer GEMMs).
//   C = Ahi*Bhi + Ahi*Blo + Alo*Bhi  (fp32 accum)
// CTA 128x128, BK=16, 8 warps (64x32), 3-stage cp.async pipeline.
// EPI 0: C = acc + bias.  EPI 1: sigmoid-gate combine + hi/lo re-split.
// ---------------------------------------------------------------------------
#define STAGE_B (4 * TILE_B)         // 24576 B per stage
#define GEMM_SMEM (3 * STAGE_B)      // 73728 B

template<int EPI>
__global__ void __launch_bounds__(256, 2) gemm_bf(
        const __nv_bfloat16* __restrict__ Ahi, const __nv_bfloat16* __restrict__ Alo,
        const __nv_bfloat16* __restrict__ Bhi, const __nv_bfloat16* __restrict__ Blo,
        const float* __restrict__ bias,
        const float* __restrict__ refined, const float* __restrict__ orig,
        float* __restrict__ C,
        __nv_bfloat16* __restrict__ Chi, __nv_bfloat16* __restrict__ Clo,
        int M, int N, int K)
{
    extern __shared__ char smem[];
    uint32_t sb = smem_u32(smem);

    int tid  = threadIdx.x;
    int lane = tid & 31;
    int warp = tid >> 5;
    int g = lane >> 2, t = lane & 3;
    int wm = (warp >> 2) * 64;
    int wn = (warp & 3) * 32;
    int m0 = blockIdx.x * 128, n0 = blockIdx.y * 128;

    uint32_t aoff = (uint32_t)((((lane & 7) + ((lane >> 3) & 1) * 8) * RSTR) + ((lane >> 4) & 1) * 16);
    uint32_t boff = (uint32_t)((((lane & 7) + ((lane >> 4) & 1) * 8) * RSTR) + ((lane >> 3) & 1) * 16);

    int lr = tid >> 1;
    int lc8 = (tid & 1) * 8;
    uint32_t so = (uint32_t)(lr * RSTR + (tid & 1) * 16);

    float acc[4][4][4];
#pragma unroll
    for (int mi = 0; mi < 4; mi++)
#pragma unroll
        for (int ni = 0; ni < 4; ni++)
#pragma unroll
            for (int r = 0; r < 4; r++) acc[mi][ni][r] = 0.f;

    auto load_stage = [&](int st, int kt) {
        int k0 = kt * 16;
        uint32_t base = sb + (uint32_t)st * STAGE_B;
        size_t ga = (size_t)(m0 + lr) * K + k0 + lc8;
        size_t gb = (size_t)(n0 + lr) * K + k0 + lc8;
        cp16s(base + so,              Ahi + ga);
        cp16s(base + TILE_B + so,     Alo + ga);
        cp16s(base + 2 * TILE_B + so, Bhi + gb);
        cp16s(base + 3 * TILE_B + so, Blo + gb);
    };

    int KT = K >> 4;
    load_stage(0, 0); cp_commit();
    load_stage(1, 1); cp_commit();

    for (int kt = 0; kt < KT; kt++) {
        if (kt == KT - 1) cp_wait<0>(); else cp_wait<1>();
        __syncthreads();
        if (kt + 2 < KT) { load_stage((kt + 2) % 3, kt + 2); cp_commit(); }

        uint32_t base = sb + (uint32_t)(kt % 3) * STAGE_B;
        uint32_t tAh = base, tAl = base + TILE_B;
        uint32_t tBh = base + 2 * TILE_B, tBl = base + 3 * TILE_B;

        uint32_t af[16], bh[8], bl[8];
        LDSM4(bh[0], bh[1], bh[2], bh[3], tBh + (uint32_t)(wn * RSTR) + boff);
        LDSM4(bh[4], bh[5], bh[6], bh[7], tBh + (uint32_t)((wn + 16) * RSTR) + boff);
#pragma unroll
        for (int mi = 0; mi < 4; mi++)
            LDSM4(af[mi*4], af[mi*4+1], af[mi*4+2], af[mi*4+3],
                  tAh + (uint32_t)((wm + mi * 16) * RSTR) + aoff);
#pragma unroll
        for (int mi = 0; mi < 4; mi++)
#pragma unroll
            for (int ni = 0; ni < 4; ni++)
                mma_bf16(acc[mi][ni], &af[mi*4], &bh[ni*2]);

        LDSM4(bl[0], bl[1], bl[2], bl[3], tBl + (uint32_t)(wn * RSTR) + boff);
        LDSM4(bl[4], bl[5], bl[6], bl[7], tBl + (uint32_t)((wn + 16) * RSTR) + boff);
#pragma unroll
        for (int mi = 0; mi < 4; mi++)
#pragma unroll
            for (int ni = 0; ni < 4; ni++)
                mma_bf16(acc[mi][ni], &af[mi*4], &bl[ni*2]);

#pragma unroll
        for (int mi = 0; mi < 4; mi++)
            LDSM4(af[mi*4], af[mi*4+1], af[mi*4+2], af[mi*4+3],
                  tAl + (uint32_t)((wm + mi * 16) * RSTR) + aoff);
#pragma unroll
        for (int mi = 0; mi < 4; mi++)
#pragma unroll
            for (int ni = 0; ni < 4; ni++)
                mma_bf16(acc[mi][ni], &af[mi*4], &bh[ni*2]);
    }

#pragma unroll
    for (int mi = 0; mi < 4; mi++) {
        int r0 = m0 + wm + mi * 16 + g;
#pragma unroll
        for (int ni = 0; ni < 4; ni++) {
            int c0 = n0 + wn + ni * 8 + t * 2;
            float bv0 = bias[c0], bv1 = bias[c0 + 1];
            size_t o0 = (size_t)r0 * N + c0;
            size_t o1 = (size_t)(r0 + 8) * N + c0;
            float* a4 = acc[mi][ni];
            if (EPI == 0) {
                C[o0]     = a4[0] + bv0;
                C[o0 + 1] = a4[1] + bv1;
                C[o1]     = a4[2] + bv0;
                C[o1 + 1] = a4[3] + bv1;
            } else {
                float pre[4] = {a4[0] + bv0, a4[1] + bv1, a4[2] + bv0, a4[3] + bv1};
                size_t offs[4] = {o0, o0 + 1, o1, o1 + 1};
#pragma unroll
                for (int j = 0; j < 4; j++) {
                    float gt = 1.f / (1.f + expf(-pre[j]));
                    float res = gt * refined[offs[j]] + (1.f - gt) * orig[offs[j]];
                    C[offs[j]] = res;
                    __nv_bfloat16 h, l;
                    bf_split(res, h, l);
                    Chi[offs[j]] = h;
                    Clo[offs[j]] = l;
                }
            }
        }
    }
}

// ---------------------------------------------------------------------------
// Output GEMM: single-product fp16 (non-compounding final projection).
//   C[m,v] = sum_k A[m][k]*B[v][k] + bias[v]  (fp32 accum)
// Same skeleton: CTA 128x128, 3-stage, ldmatrix. Stage = A tile + B tile.
// ---------------------------------------------------------------------------
#define OSTAGE_B (2 * TILE_B)          // 12288 B
#define OGEMM_SMEM (3 * OSTAGE_B)      // 36864 B

__global__ void __launch_bounds__(256, 2) gemm_out(
        const __half* __restrict__ A, const __half* __restrict__ Bm,
        const float* __restrict__ bias,
        float* __restrict__ C, int M, int N, int K)
{
    extern __shared__ char smem[];
    uint32_t sb = smem_u32(smem);

    int tid  = threadIdx.x;
    int lane = tid & 31;
    int warp = tid >> 5;
    int g = lane >> 2, t = lane & 3;
    int wm = (warp >> 2) * 64;
    int wn = (warp & 3) * 32;
    int m0 = blockIdx.x * 128, n0 = blockIdx.y * 128;

    uint32_t aoff = (uint32_t)((((lane & 7) + ((lane >> 3) & 1) * 8) * RSTR) + ((lane >> 4) & 1) * 16);
    uint32_t boff = (uint32_t)((((lane & 7) + ((lane >> 4) & 1) * 8) * RSTR) + ((lane >> 3) & 1) * 16);

    int lr = tid >> 1;
    int lc8 = (tid & 1) * 8;
    uint32_t so = (uint32_t)(lr * RSTR + (tid & 1) * 16);

    float acc[4][4][4];
#pragma unroll
    for (int mi = 0; mi < 4; mi++)
#pragma unroll
        for (int ni = 0; ni < 4; ni++)
#pragma unroll
            for (int r = 0; r < 4; r++) acc[mi][ni][r] = 0.f;

    auto load_stage = [&](int st, int kt) {
        int k0 = kt * 16;
        uint32_t base = sb + (uint32_t)st * OSTAGE_B;
        cp16s(base + so,          A  + (size_t)(m0 + lr) * K + k0 + lc8);
        cp16s(base + TILE_B + so, Bm + (size_t)(n0 + lr) * K + k0 + lc8);
    };

    int KT = K >> 4;
    load_stage(0, 0); cp_commit();
    load_stage(1, 1); cp_commit();

    for (int kt = 0; kt < KT; kt++) {
        if (kt == KT - 1) cp_wait<0>(); else cp_wait<1>();
        __syncthreads();
        if (kt + 2 < KT) { load_stage((kt + 2) % 3, kt + 2); cp_commit(); }

        uint32_t base = sb + (uint32_t)(kt % 3) * OSTAGE_B;
        uint32_t tA = base, tB = base + TILE_B;

        uint32_t af[16], bf[8];
        LDSM4(bf[0], bf[1], bf[2], bf[3], tB + (uint32_t)(wn * RSTR) + boff);
        LDSM4(bf[4], bf[5], bf[6], bf[7], tB + (uint32_t)((wn + 16) * RSTR) + boff);
#pragma unroll
        for (int mi = 0; mi < 4; mi++)
            LDSM4(af[mi*4], af[mi*4+1], af[mi*4+2], af[mi*4+3],
                  tA + (uint32_t)((wm + mi * 16) * RSTR) + aoff);
#pragma unroll
        for (int mi = 0; mi < 4; mi++)
#pragma unroll
            for (int ni = 0; ni < 4; ni++)
                mma_fp16(acc[mi][ni], &af[mi*4], &bf[ni*2]);
    }

#pragma unroll
    for (int mi = 0; mi < 4; mi++) {
        int r0 = m0 + wm + mi * 16 + g;
#pragma unroll
        for (int ni = 0; ni < 4; ni++) {
            int c0 = n0 + wn + ni * 8 + t * 2;
            float bv0 = bias[c0], bv1 = bias[c0 + 1];
            size_t o0 = (size_t)r0 * N + c0;
            size_t o1 = (size_t)(r0 + 8) * N + c0;
            float* a4 = acc[mi][ni];
            C[o0]     = a4[0] + bv0;
            C[o0 + 1] = a4[1] + bv1;
            C[o1]     = a4[2] + bv0;
            C[o1 + 1] = a4[3] + bv1;
        }
    }
}

// ---------------------------------------------------------------------------
// Embedding + sinusoidal PE (+ hi/lo split)
// ---------------------------------------------------------------------------
__global__ void embed_kernel(const int* __restrict__ ids,
                             const float* __restrict__ emb,
                             float* __restrict__ x,
                             __nv_bfloat16* __restrict__ xh,
                             __nv_bfloat16* __restrict__ xl) {
    int row = blockIdx.x;
    int s   = row & (S_ - 1);
    int tok = ids[row];
    int d0  = threadIdx.x * 4;
    float4 e = *(const float4*)(emb + (size_t)tok * D_ + d0);
    const float cln = -logf(10000.0f) / (float)D_;
    float pe[4];
#pragma unroll
    for (int j = 0; j < 4; j += 2) {
        float freq = expf(cln * (float)(d0 + j));
        float a = (float)s * freq;
        pe[j]   = sinf(a);
        pe[j+1] = cosf(a);
    }
    float o[4] = {e.x + pe[0], e.y + pe[1], e.z + pe[2], e.w + pe[3]};
    *(float4*)(x + (size_t)row * D_ + d0) = *(float4*)o;
    ushort4 h4, l4;
    __nv_bfloat16 h, l;
    bf_split(o[0], h, l); h4.x = *(unsigned short*)&h; l4.x = *(unsigned short*)&l;
    bf_split(o[1], h, l); h4.y = *(unsigned short*)&h; l4.y = *(unsigned short*)&l;
    bf_split(o[2], h, l); h4.z = *(unsigned short*)&h; l4.z = *(unsigned short*)&l;
    bf_split(o[3], h, l); h4.w = *(unsigned short*)&h; l4.w = *(unsigned short*)&l;
    *(ushort4*)(xh + (size_t)row * D_ + d0) = h4;
    *(ushort4*)(xl + (size_t)row * D_ + d0) = l4;
}

// ---------------------------------------------------------------------------
// Weight split (bf16 hi/lo, layer weights)
// ---------------------------------------------------------------------------
__global__ void split_kernel(const float* __restrict__ w,
                             __nv_bfloat16* __restrict__ hi,
                             __nv_bfloat16* __restrict__ lo, int n4) {
    int i = blockIdx.x * 256 + threadIdx.x;
    if (i >= n4) return;
    float4 v = ((const float4*)w)[i];
    ushort4 h4, l4; __nv_bfloat16 h, l;
    bf_split(v.x, h, l); h4.x = *(unsigned short*)&h; l4.x = *(unsigned short*)&l;
    bf_split(v.y, h, l); h4.y = *(unsigned short*)&h; l4.y = *(unsigned short*)&l;
    bf_split(v.z, h, l); h4.z = *(unsigned short*)&h; l4.z = *(unsigned short*)&l;
    bf_split(v.w, h, l); h4.w = *(unsigned short*)&h; l4.w = *(unsigned short*)&l;
    ((ushort4*)hi)[i] = h4;
    ((ushort4*)lo)[i] = l4;
}

// ---------------------------------------------------------------------------
// outW (D,V) -> [V][D] fp16 (single precision level; final GEMM B)
// ---------------------------------------------------------------------------
__global__ void wout_t16_kernel(const float* __restrict__ w,
                                __half* __restrict__ o16) {
    __shared__ float tile[32][33];
    int v0 = blockIdx.x * 32, d0 = blockIdx.y * 32;
    int tx = threadIdx.x, ty = threadIdx.y;
#pragma unroll
    for (int i = 0; i < 4; i++)
        tile[ty + i * 8][tx] = w[(size_t)(d0 + ty + i * 8) * V_ + v0 + tx];
    __syncthreads();
#pragma unroll
    for (int i = 0; i < 4; i++) {
        size_t o = (size_t)(v0 + ty + i * 8) * D_ + d0 + tx;
        o16[o] = __float2half(tile[tx][ty + i * 8]);
    }
}

// ---------------------------------------------------------------------------
// LayerNorm statistics
// ---------------------------------------------------------------------------
__global__ void ln_stats_kernel(const float* __restrict__ x, float2* __restrict__ stats) {
    int row = blockIdx.x;
    float4 v = ((const float4*)(x + (size_t)row * D_))[threadIdx.x];
    float s = v.x + v.y + v.z + v.w;
    float q = v.x*v.x + v.y*v.y + v.z*v.z + v.w*v.w;
#pragma unroll
    for (int o = 16; o; o >>= 1) {
        s += __shfl_xor_sync(0xffffffffu, s, o);
        q += __shfl_xor_sync(0xffffffffu, q, o);
    }
    __shared__ float ss[8], sq[8];
    int w = threadIdx.x >> 5;
    if ((threadIdx.x & 31) == 0) { ss[w] = s; sq[w] = q; }
    __syncthreads();
    if (threadIdx.x == 0) {
        float S = 0.f, Q = 0.f;
#pragma unroll
        for (int i = 0; i < 8; i++) { S += ss[i]; Q += sq[i]; }
        float mu  = S / (float)D_;
        float var = Q / (float)D_ - mu * mu;
        stats[row] = make_float2(mu, rsqrtf(var + 1e-5f));
    }
}

// ---------------------------------------------------------------------------
// Apply LN while transposing (B,S,D)->(B,D,S)
// ---------------------------------------------------------------------------
__global__ void ln_transpose_kernel(const float* __restrict__ x,
                                    const float2* __restrict__ stats,
                                    const float* __restrict__ g,
                                    const float* __restrict__ bta,
                                    float* __restrict__ hT) {
    __shared__ float tile[32][33];
    int b  = blockIdx.z;
    int s0 = blockIdx.x * 32, d0 = blockIdx.y * 32;
    int tx = threadIdx.x, ty = threadIdx.y;
    float gg = g[d0 + tx], bb = bta[d0 + tx];
#pragma unroll
    for (int i = 0; i < 4; i++) {
        int s = s0 + ty + i * 8;
        float2 st = stats[b * S_ + s];
        float v = x[((size_t)(b * S_ + s)) * D_ + d0 + tx];
        tile[ty + i * 8][tx] = (v - st.x) * st.y * gg + bb;
    }
    __syncthreads();
#pragma unroll
    for (int i = 0; i < 4; i++) {
        int d = d0 + ty + i * 8;
        hT[((size_t)(b * D_ + d)) * S_ + s0 + tx] = tile[tx][ty + i * 8];
    }
}

// ---------------------------------------------------------------------------
// Final LN apply -> fp16 (token-major), for output GEMM A
// ---------------------------------------------------------------------------
__global__ void apply_ln_kernel(const float* __restrict__ x,
                                const float2* __restrict__ stats,
                                const float* __restrict__ g,
                                const float* __restrict__ b,
                                __half* __restrict__ o16) {
    int row = blockIdx.x;
    int d0 = threadIdx.x * 4;
    float2 st = stats[row];
    float4 v  = *(const float4*)(x + (size_t)row * D_ + d0);
    float4 gg = *(const float4*)(g + d0);
    float4 bb = *(const float4*)(b + d0);
    __half2 p0 = __floats2half2_rn((v.x - st.x) * st.y * gg.x + bb.x,
                                   (v.y - st.x) * st.y * gg.y + bb.y);
    __half2 p1 = __floats2half2_rn((v.z - st.x) * st.y * gg.z + bb.z,
                                   (v.w - st.x) * st.y * gg.w + bb.w);
    uint2 packed = {*(uint32_t*)&p0, *(uint32_t*)&p1};
    *(uint2*)(o16 + (size_t)row * D_ + d0) = packed;
}

// ---------------------------------------------------------------------------
// Depthwise conv chain per (b,d) channel
// ---------------------------------------------------------------------------
__global__ void __launch_bounds__(256) conv_kernel(const float* __restrict__ hT,
                                                   const float* __restrict__ lw,
                                                   const float* __restrict__ fw,
                                                   const float* __restrict__ mw,
                                                   float* __restrict__ yT) {
    int bd = blockIdx.x;
    int d  = bd & (D_ - 1);
    __shared__ float bufA[S_ + 64];
    __shared__ float bufB[S_ + 64];
    __shared__ float w3[3], wA[64], wB[64];
    int tid = threadIdx.x;
    if (tid < 64) {
        wA[tid] = fw[(size_t)d * 64 + tid];
        wB[tid] = fw[(size_t)(D_ + d) * 64 + tid];
    }
    if (tid < 3) w3[tid] = lw[d * 3 + tid];
    if (tid < 32) {
        bufA[tid] = 0.f; bufA[S_ + 32 + tid] = 0.f;
        bufB[tid] = 0.f; bufB[S_ + 32 + tid] = 0.f;
    }
    const float* cin = hT + (size_t)bd * S_;
    for (int i = tid; i < S_ / 4; i += 256)
        ((float4*)(bufA + 32))[i] = ((const float4*)cin)[i];
    __syncthreads();
    for (int s = tid; s < S_; s += 256)
        bufB[32 + s] = bufA[31 + s] * w3[0] + bufA[32 + s] * w3[1] + bufA[33 + s] * w3[2];
    __syncthreads();

    int s0 = tid * 8;
    float acc[8], win[8];
#pragma unroll
    for (int j = 0; j < 8; j++) { acc[j] = bufA[32 + s0 + j]; win[j] = bufB[s0 + j]; }
#pragma unroll
    for (int k = 0; k < 64; k++) {
        float wk = wA[k];
#pragma unroll
        for (int j = 0; j < 8; j++) acc[j] += win[j] * wk;
#pragma unroll
        for (int j = 0; j < 7; j++) win[j] = win[j + 1];
        win[7] = bufB[s0 + 8 + k];
    }
    __syncthreads();
#pragma unroll
    for (int j = 0; j < 8; j++) bufA[32 + s0 + j] = acc[j];
    __syncthreads();
    float mwd = mw[d];
#pragma unroll
    for (int j = 0; j < 8; j++) { acc[j] = 0.f; win[j] = bufA[s0 + j]; }
#pragma unroll
    for (int k = 0; k < 64; k++) {
        float wk = wB[k];
#pragma unroll
        for (int j = 0; j < 8; j++) acc[j] += win[j] * wk;
#pragma unroll
        for (int j = 0; j < 7; j++) win[j] = win[j + 1];
        win[7] = bufA[s0 + 8 + k];
    }
    float* outp = yT + (size_t)bd * S_;
#pragma unroll
    for (int j = 0; j < 8; j++) {
        float m = acc[j] * mwd;
        outp[s0 + j] = m / (1.0f + expf(-m));
    }
}

// ---------------------------------------------------------------------------
// yT (B,D,S) -> y (B,S,D) hi/lo bf16
// ---------------------------------------------------------------------------
__global__ void y_tsplit_kernel(const float* __restrict__ yT,
                                __nv_bfloat16* __restrict__ yh,
                                __nv_bfloat16* __restrict__ yl) {
    __shared__ float tile[32][33];
    int b  = blockIdx.z;
    int s0 = blockIdx.x * 32, d0 = blockIdx.y * 32;
    int tx = threadIdx.x, ty = threadIdx.y;
#pragma unroll
    for (int i = 0; i < 4; i++)
        tile[ty + i * 8][tx] = yT[((size_t)(b * D_ + d0 + ty + i * 8)) * S_ + s0 + tx];
    __syncthreads();
#pragma unroll
    for (int i = 0; i < 4; i++) {
        float val = tile[tx][ty + i * 8];
        __nv_bfloat16 h, l;
        bf_split(val, h, l);
        size_t o = (size_t)(b * S_ + s0 + ty + i * 8) * D_ + d0 + tx;
        yh[o] = h; yl[o] = l;
    }
}

// ---------------------------------------------------------------------------
// Host orchestration
// ---------------------------------------------------------------------------
static void* sym_addr(const void* sym) {
    void* p = nullptr;
    cudaGetSymbolAddress(&p, sym);
    return p;
}

extern "C" void kernel_launch(void* const* d_in, const int* in_sizes, int n_in,
                              void* d_out, int out_size) {
    (void)in_sizes; (void)n_in; (void)out_size;
    const int*   ids   = (const int*)d_in[0];
    const float* emb   = (const float*)d_in[1];
    const float* lw    = (const float*)d_in[2];
    const float* fw    = (const float*)d_in[3];
    const float* mw    = (const float*)d_in[4];
    const float* ln1g  = (const float*)d_in[5];
    const float* ln1b  = (const float*)d_in[6];
    const float* refW  = (const float*)d_in[7];
    const float* refb  = (const float*)d_in[8];
    const float* gateW = (const float*)d_in[9];
    const float* gateb = (const float*)d_in[10];
    const float* lnfg  = (const float*)d_in[11];
    const float* lnfb  = (const float*)d_in[12];
    const float* outW  = (const float*)d_in[13];
    const float* outb  = (const float*)d_in[14];
    float* out = (float*)d_out;

    float*  x0  = (float*)sym_addr(g_x0);
    float*  x1  = (float*)sym_addr(g_x1);
    float*  hT  = (float*)sym_addr(g_hT);
    float*  yT  = (float*)sym_addr(g_yT);
    float*  rf  = (float*)sym_addr(g_ref);
    float2* st  = (float2*)sym_addr(g_stats);
    __nv_bfloat16* x0h = (__nv_bfloat16*)sym_addr(g_x0h);
    __nv_bfloat16* x0l = (__nv_bfloat16*)sym_addr(g_x0l);
    __nv_bfloat16* x1h = (__nv_bfloat16*)sym_addr(g_x1h);
    __nv_bfloat16* x1l = (__nv_bfloat16*)sym_addr(g_x1l);
    __nv_bfloat16* yh  = (__nv_bfloat16*)sym_addr(g_yh);
    __nv_bfloat16* yl  = (__nv_bfloat16*)sym_addr(g_yl);
    __nv_bfloat16* wrh = (__nv_bfloat16*)sym_addr(g_wrh);
    __nv_bfloat16* wrl = (__nv_bfloat16*)sym_addr(g_wrl);
    __nv_bfloat16* wgh = (__nv_bfloat16*)sym_addr(g_wgh);
    __nv_bfloat16* wgl = (__nv_bfloat16*)sym_addr(g_wgl);
    __half* xf16 = (__half*)sym_addr(g_xf16);
    __half* wo16 = (__half*)sym_addr(g_wo16);

    cudaFuncSetAttribute(gemm_bf<0>, cudaFuncAttributeMaxDynamicSharedMemorySize, GEMM_SMEM);
    cudaFuncSetAttribute(gemm_bf<1>, cudaFuncAttributeMaxDynamicSharedMemorySize, GEMM_SMEM);
    cudaFuncSetAttribute(gemm_out, cudaFuncAttributeMaxDynamicSharedMemorySize, OGEMM_SMEM);

    {
        int n4 = NL_ * D_ * D_ / 4;
        split_kernel<<<(n4 + 255) / 256, 256>>>(refW,  wrh, wrl, n4);
        split_kernel<<<(n4 + 255) / 256, 256>>>(gateW, wgh, wgl, n4);
        wout_t16_kernel<<<dim3(V_ / 32, D_ / 32), dim3(32, 8)>>>(outW, wo16);
    }

    embed_kernel<<<M_, 256>>>(ids, emb, x0, x0h, x0l);

    float* cur = x0;        float* nxt = x1;
    __nv_bfloat16 *curh = x0h, *curl = x0l, *nxth = x1h, *nxtl = x1l;
    for (int l = 0; l < NL_; l++) {
        ln_stats_kernel<<<M_, 256>>>(cur, st);
        ln_transpose_kernel<<<dim3(S_/32, D_/32, B_), dim3(32, 8)>>>(
            cur, st, ln1g + (size_t)l * D_, ln1b + (size_t)l * D_, hT);
        conv_kernel<<<B_*D_, 256>>>(
            hT, lw + (size_t)l * D_ * 3, fw + (size_t)l * 2 * D_ * 64,
            mw + (size_t)l * D_, yT);
        y_tsplit_kernel<<<dim3(S_/32, D_/32, B_), dim3(32, 8)>>>(yT, yh, yl);
        gemm_bf<0><<<dim3(M_/128, D_/128), 256, GEMM_SMEM>>>(
            yh, yl, wrh + (size_t)l * D_ * D_, wrl + (size_t)l * D_ * D_,
            refb + (size_t)l * D_, nullptr, nullptr, rf, nullptr, nullptr,
            M_, D_, D_);
        gemm_bf<1><<<dim3(M_/128, D_/128), 256, GEMM_SMEM>>>(
            curh, curl, wgh + (size_t)l * D_ * D_, wgl + (size_t)l * D_ * D_,
            gateb + (size_t)l * D_, rf, cur, nxt, nxth, nxtl,
            M_, D_, D_);
        { float* tf = cur; cur = nxt; nxt = tf; }
        { __nv_bfloat16* tb;
          tb = curh; curh = nxth; nxth = tb;
          tb = curl; curl = nxtl; nxtl = tb; }
    }

    ln_stats_kernel<<<M_, 256>>>(cur, st);
    apply_ln_kernel<<<M_, 256>>>(cur, st, lnfg, lnfb, xf16);
    gemm_out<<<dim3(M_/128, V_/128), 256, OGEMM_SMEM>>>(
        xf16, wo16, outb, out, M_, V_, D_);
}

// round 7
// speedup vs baseline: 3.6744x; 1.1201x over previous
#include <cuda_runtime.h>
#include <cuda_bf16.h>
#include <cuda_fp16.h>
#include <math.h>
#include <stdint.h>

#define B_  2
#define S_  2048
#define D_  1024
#define V_  32000
#define NL_ 6
#define M_  (B_*S_)   // 4096 tokens

// ---------------------------------------------------------------------------
// Scratch
// ---------------------------------------------------------------------------
__device__ float  g_x0[M_*D_];
__device__ float  g_x1[M_*D_];
__device__ float  g_hT[M_*D_];
__device__ float  g_yT[M_*D_];
__device__ float  g_ref[M_*D_];
__device__ float2 g_stats[M_];

__device__ __half        g_x016[M_*D_], g_x116[M_*D_];
__device__ __nv_bfloat16 g_yh [M_*D_], g_yl [M_*D_];
__device__ __nv_bfloat16 g_wrh[NL_*D_*D_], g_wrl[NL_*D_*D_];
__device__ __half        g_wgh16[NL_*D_*D_], g_wgl16[NL_*D_*D_];
__device__ __half        g_xf16[M_*D_];
__device__ __half        g_wo16[(size_t)V_*D_];

__device__ __forceinline__ void bf_split(float x, __nv_bfloat16& h, __nv_bfloat16& l) {
    h = __float2bfloat16(x);
    l = __float2bfloat16(x - __bfloat162float(h));
}

// ---------------------------------------------------------------------------
// PTX helpers
// ---------------------------------------------------------------------------
__device__ __forceinline__ uint32_t smem_u32(const void* p) {
    uint32_t a;
    asm("{ .reg .u64 t; cvta.to.shared.u64 t, %1; cvt.u32.u64 %0, t; }" : "=r"(a) : "l"(p));
    return a;
}
__device__ __forceinline__ void cp16s(uint32_t saddr, const void* g) {
    asm volatile("cp.async.cg.shared.global [%0], [%1], 16;\n" :: "r"(saddr), "l"(g));
}
__device__ __forceinline__ void cp_commit() {
    asm volatile("cp.async.commit_group;\n" ::: "memory");
}
template<int N_> __device__ __forceinline__ void cp_wait() {
    asm volatile("cp.async.wait_group %0;\n" :: "n"(N_) : "memory");
}
__device__ __forceinline__ void mma_bf16(float* c, const uint32_t* a, const uint32_t* b) {
    asm volatile(
        "mma.sync.aligned.m16n8k16.row.col.f32.bf16.bf16.f32 "
        "{%0,%1,%2,%3}, {%4,%5,%6,%7}, {%8,%9}, {%0,%1,%2,%3};"
        : "+f"(c[0]), "+f"(c[1]), "+f"(c[2]), "+f"(c[3])
        : "r"(a[0]), "r"(a[1]), "r"(a[2]), "r"(a[3]), "r"(b[0]), "r"(b[1]));
}
__device__ __forceinline__ void mma_fp16(float* c, const uint32_t* a, const uint32_t* b) {
    asm volatile(
        "mma.sync.aligned.m16n8k16.row.col.f32.f16.f16.f32 "
        "{%0,%1,%2,%3}, {%4,%5,%6,%7}, {%8,%9}, {%0,%1,%2,%3};"
        : "+f"(c[0]), "+f"(c[1]), "+f"(c[2]), "+f"(c[3])
        : "r"(a[0]), "r"(a[1]), "r"(a[2]), "r"(a[3]), "r"(b[0]), "r"(b[1]));
}
#define LDSM4(r0, r1, r2, r3, addr) \
    asm volatile("ldmatrix.sync.aligned.m8n8.x4.shared.b16 {%0,%1,%2,%3}, [%4];" \
        : "=r"(r0), "=r"(r1), "=r"(r2), "=r"(r3) : "r"(addr))

#define RSTR   48                    // bytes per smem row
#define TILE_B (128 * RSTR)          // 6144 B per operand tile

// ---------------------------------------------------------------------------
// Refine GEMM: split-2 bf16, 3 products (unattenuated error path).
//   C = Ahi*Bhi + Ahi*Blo + Alo*Bhi + bias   (fp32 accum)
// CTA 128x128, BK=16, 8 warps (64x32), 3-stage cp.async pipeline.
// ---------------------------------------------------------------------------
#define STAGE_B (4 * TILE_B)         // 24576 B per stage
#define GEMM_SMEM (3 * STAGE_B)      // 73728 B

__global__ void __launch_bounds__(256, 2) gemm_bf(
        const __nv_bfloat16* __restrict__ Ahi, const __nv_bfloat16* __restrict__ Alo,
        const __nv_bfloat16* __restrict__ Bhi, const __nv_bfloat16* __restrict__ Blo,
        const float* __restrict__ bias,
        float* __restrict__ C, int M, int N, int K)
{
    extern __shared__ char smem[];
    uint32_t sb = smem_u32(smem);

    int tid  = threadIdx.x;
    int lane = tid & 31;
    int warp = tid >> 5;
    int g = lane >> 2, t = lane & 3;
    int wm = (warp >> 2) * 64;
    int wn = (warp & 3) * 32;
    int m0 = blockIdx.x * 128, n0 = blockIdx.y * 128;

    uint32_t aoff = (uint32_t)((((lane & 7) + ((lane >> 3) & 1) * 8) * RSTR) + ((lane >> 4) & 1) * 16);
    uint32_t boff = (uint32_t)((((lane & 7) + ((lane >> 4) & 1) * 8) * RSTR) + ((lane >> 3) & 1) * 16);

    int lr = tid >> 1;
    int lc8 = (tid & 1) * 8;
    uint32_t so = (uint32_t)(lr * RSTR + (tid & 1) * 16);

    float acc[4][4][4];
#pragma unroll
    for (int mi = 0; mi < 4; mi++)
#pragma unroll
        for (int ni = 0; ni < 4; ni++)
#pragma unroll
            for (int r = 0; r < 4; r++) acc[mi][ni][r] = 0.f;

    auto load_stage = [&](int st, int kt) {
        int k0 = kt * 16;
        uint32_t base = sb + (uint32_t)st * STAGE_B;
        size_t ga = (size_t)(m0 + lr) * K + k0 + lc8;
        size_t gb = (size_t)(n0 + lr) * K + k0 + lc8;
        cp16s(base + so,              Ahi + ga);
        cp16s(base + TILE_B + so,     Alo + ga);
        cp16s(base + 2 * TILE_B + so, Bhi + gb);
        cp16s(base + 3 * TILE_B + so, Blo + gb);
    };

    int KT = K >> 4;
    load_stage(0, 0); cp_commit();
    load_stage(1, 1); cp_commit();

    for (int kt = 0; kt < KT; kt++) {
        if (kt == KT - 1) cp_wait<0>(); else cp_wait<1>();
        __syncthreads();
        if (kt + 2 < KT) { load_stage((kt + 2) % 3, kt + 2); cp_commit(); }

        uint32_t base = sb + (uint32_t)(kt % 3) * STAGE_B;
        uint32_t tAh = base, tAl = base + TILE_B;
        uint32_t tBh = base + 2 * TILE_B, tBl = base + 3 * TILE_B;

        uint32_t af[16], bh[8], bl[8];
        LDSM4(bh[0], bh[1], bh[2], bh[3], tBh + (uint32_t)(wn * RSTR) + boff);
        LDSM4(bh[4], bh[5], bh[6], bh[7], tBh + (uint32_t)((wn + 16) * RSTR) + boff);
#pragma unroll
        for (int mi = 0; mi < 4; mi++)
            LDSM4(af[mi*4], af[mi*4+1], af[mi*4+2], af[mi*4+3],
                  tAh + (uint32_t)((wm + mi * 16) * RSTR) + aoff);
#pragma unroll
        for (int mi = 0; mi < 4; mi++)
#pragma unroll
            for (int ni = 0; ni < 4; ni++)
                mma_bf16(acc[mi][ni], &af[mi*4], &bh[ni*2]);

        LDSM4(bl[0], bl[1], bl[2], bl[3], tBl + (uint32_t)(wn * RSTR) + boff);
        LDSM4(bl[4], bl[5], bl[6], bl[7], tBl + (uint32_t)((wn + 16) * RSTR) + boff);
#pragma unroll
        for (int mi = 0; mi < 4; mi++)
#pragma unroll
            for (int ni = 0; ni < 4; ni++)
                mma_bf16(acc[mi][ni], &af[mi*4], &bl[ni*2]);

#pragma unroll
        for (int mi = 0; mi < 4; mi++)
            LDSM4(af[mi*4], af[mi*4+1], af[mi*4+2], af[mi*4+3],
                  tAl + (uint32_t)((wm + mi * 16) * RSTR) + aoff);
#pragma unroll
        for (int mi = 0; mi < 4; mi++)
#pragma unroll
            for (int ni = 0; ni < 4; ni++)
                mma_bf16(acc[mi][ni], &af[mi*4], &bh[ni*2]);
    }

#pragma unroll
    for (int mi = 0; mi < 4; mi++) {
        int r0 = m0 + wm + mi * 16 + g;
#pragma unroll
        for (int ni = 0; ni < 4; ni++) {
            int c0 = n0 + wn + ni * 8 + t * 2;
            float bv0 = bias[c0], bv1 = bias[c0 + 1];
            size_t o0 = (size_t)r0 * N + c0;
            size_t o1 = (size_t)(r0 + 8) * N + c0;
            float* a4 = acc[mi][ni];
            C[o0]     = a4[0] + bv0;
            C[o0 + 1] = a4[1] + bv1;
            C[o1]     = a4[2] + bv0;
            C[o1 + 1] = a4[3] + bv1;
        }
    }
}

// ---------------------------------------------------------------------------
// Gate GEMM: fp16 2-product (sigmoid-attenuated error path).
//   z = A16*Bhi + (A16*2^-10)*(Blo*2^10)   (fp32 accum; B to ~21 bits)
// Scaled-A made in registers (HMUL2 on frags) -> only 3 tiles per stage.
// Epilogue: s=sigmoid(z+bias); x' = s*refined+(1-s)*orig -> fp32 + fp16.
// ---------------------------------------------------------------------------
#define GSTAGE_B (3 * TILE_B)          // 18432 B
#define GGEMM_SMEM (3 * GSTAGE_B)      // 55296 B

__global__ void __launch_bounds__(256, 2) gemm_gate(
        const __half* __restrict__ A,
        const __half* __restrict__ Bhi, const __half* __restrict__ Blo,
        const float* __restrict__ bias,
        const float* __restrict__ refined, const float* __restrict__ orig,
        float* __restrict__ C, __half* __restrict__ C16,
        int M, int N, int K)
{
    extern __shared__ char smem[];
    uint32_t sb = smem_u32(smem);

    int tid  = threadIdx.x;
    int lane = tid & 31;
    int warp = tid >> 5;
    int g = lane >> 2, t = lane & 3;
    int wm = (warp >> 2) * 64;
    int wn = (warp & 3) * 32;
    int m0 = blockIdx.x * 128, n0 = blockIdx.y * 128;

    uint32_t aoff = (uint32_t)((((lane & 7) + ((lane >> 3) & 1) * 8) * RSTR) + ((lane >> 4) & 1) * 16);
    uint32_t boff = (uint32_t)((((lane & 7) + ((lane >> 4) & 1) * 8) * RSTR) + ((lane >> 3) & 1) * 16);

    int lr = tid >> 1;
    int lc8 = (tid & 1) * 8;
    uint32_t so = (uint32_t)(lr * RSTR + (tid & 1) * 16);

    const __half2 sc = __floats2half2_rn(9.765625e-4f, 9.765625e-4f);  // 2^-10

    float acc[4][4][4];
#pragma unroll
    for (int mi = 0; mi < 4; mi++)
#pragma unroll
        for (int ni = 0; ni < 4; ni++)
#pragma unroll
            for (int r = 0; r < 4; r++) acc[mi][ni][r] = 0.f;

    auto load_stage = [&](int st, int kt) {
        int k0 = kt * 16;
        uint32_t base = sb + (uint32_t)st * GSTAGE_B;
        size_t ga = (size_t)(m0 + lr) * K + k0 + lc8;
        size_t gb = (size_t)(n0 + lr) * K + k0 + lc8;
        cp16s(base + so,              A   + ga);
        cp16s(base + TILE_B + so,     Bhi + gb);
        cp16s(base + 2 * TILE_B + so, Blo + gb);
    };

    int KT = K >> 4;
    load_stage(0, 0); cp_commit();
    load_stage(1, 1); cp_commit();

    for (int kt = 0; kt < KT; kt++) {
        if (kt == KT - 1) cp_wait<0>(); else cp_wait<1>();
        __syncthreads();
        if (kt + 2 < KT) { load_stage((kt + 2) % 3, kt + 2); cp_commit(); }

        uint32_t base = sb + (uint32_t)(kt % 3) * GSTAGE_B;
        uint32_t tA = base, tBh = base + TILE_B, tBl = base + 2 * TILE_B;

        uint32_t af[16], bh[8], bl[8];
        LDSM4(bh[0], bh[1], bh[2], bh[3], tBh + (uint32_t)(wn * RSTR) + boff);
        LDSM4(bh[4], bh[5], bh[6], bh[7], tBh + (uint32_t)((wn + 16) * RSTR) + boff);
        LDSM4(bl[0], bl[1], bl[2], bl[3], tBl + (uint32_t)(wn * RSTR) + boff);
        LDSM4(bl[4], bl[5], bl[6], bl[7], tBl + (uint32_t)((wn + 16) * RSTR) + boff);
#pragma unroll
        for (int mi = 0; mi < 4; mi++)
            LDSM4(af[mi*4], af[mi*4+1], af[mi*4+2], af[mi*4+3],
                  tA + (uint32_t)((wm + mi * 16) * RSTR) + aoff);

#pragma unroll
        for (int mi = 0; mi < 4; mi++)
#pragma unroll
            for (int ni = 0; ni < 4; ni++)
                mma_fp16(acc[mi][ni], &af[mi*4], &bh[ni*2]);

        // scale A frags by 2^-10 in registers
#pragma unroll
        for (int i = 0; i < 16; i++) {
            __half2 v = *(__half2*)&af[i];
            v = __hmul2(v, sc);
            af[i] = *(uint32_t*)&v;
        }
#pragma unroll
        for (int mi = 0; mi < 4; mi++)
#pragma unroll
            for (int ni = 0; ni < 4; ni++)
                mma_fp16(acc[mi][ni], &af[mi*4], &bl[ni*2]);
    }

#pragma unroll
    for (int mi = 0; mi < 4; mi++) {
        int r0 = m0 + wm + mi * 16 + g;
#pragma unroll
        for (int ni = 0; ni < 4; ni++) {
            int c0 = n0 + wn + ni * 8 + t * 2;
            float bv0 = bias[c0], bv1 = bias[c0 + 1];
            size_t o0 = (size_t)r0 * N + c0;
            size_t o1 = (size_t)(r0 + 8) * N + c0;
            float* a4 = acc[mi][ni];
            float pre[4] = {a4[0] + bv0, a4[1] + bv1, a4[2] + bv0, a4[3] + bv1};
            size_t offs[4] = {o0, o0 + 1, o1, o1 + 1};
#pragma unroll
            for (int j = 0; j < 4; j++) {
                float gt = 1.f / (1.f + expf(-pre[j]));
                float res = gt * refined[offs[j]] + (1.f - gt) * orig[offs[j]];
                C[offs[j]] = res;
                C16[offs[j]] = __float2half(res);
            }
        }
    }
}

// ---------------------------------------------------------------------------
// Output GEMM: single-product fp16 (non-compounding final projection).
// ---------------------------------------------------------------------------
#define OSTAGE_B (2 * TILE_B)          // 12288 B
#define OGEMM_SMEM (3 * OSTAGE_B)      // 36864 B

__global__ void __launch_bounds__(256, 2) gemm_out(
        const __half* __restrict__ A, const __half* __restrict__ Bm,
        const float* __restrict__ bias,
        float* __restrict__ C, int M, int N, int K)
{
    extern __shared__ char smem[];
    uint32_t sb = smem_u32(smem);

    int tid  = threadIdx.x;
    int lane = tid & 31;
    int warp = tid >> 5;
    int g = lane >> 2, t = lane & 3;
    int wm = (warp >> 2) * 64;
    int wn = (warp & 3) * 32;
    int m0 = blockIdx.x * 128, n0 = blockIdx.y * 128;

    uint32_t aoff = (uint32_t)((((lane & 7) + ((lane >> 3) & 1) * 8) * RSTR) + ((lane >> 4) & 1) * 16);
    uint32_t boff = (uint32_t)((((lane & 7) + ((lane >> 4) & 1) * 8) * RSTR) + ((lane >> 3) & 1) * 16);

    int lr = tid >> 1;
    int lc8 = (tid & 1) * 8;
    uint32_t so = (uint32_t)(lr * RSTR + (tid & 1) * 16);

    float acc[4][4][4];
#pragma unroll
    for (int mi = 0; mi < 4; mi++)
#pragma unroll
        for (int ni = 0; ni < 4; ni++)
#pragma unroll
            for (int r = 0; r < 4; r++) acc[mi][ni][r] = 0.f;

    auto load_stage = [&](int st, int kt) {
        int k0 = kt * 16;
        uint32_t base = sb + (uint32_t)st * OSTAGE_B;
        cp16s(base + so,          A  + (size_t)(m0 + lr) * K + k0 + lc8);
        cp16s(base + TILE_B + so, Bm + (size_t)(n0 + lr) * K + k0 + lc8);
    };

    int KT = K >> 4;
    load_stage(0, 0); cp_commit();
    load_stage(1, 1); cp_commit();

    for (int kt = 0; kt < KT; kt++) {
        if (kt == KT - 1) cp_wait<0>(); else cp_wait<1>();
        __syncthreads();
        if (kt + 2 < KT) { load_stage((kt + 2) % 3, kt + 2); cp_commit(); }

        uint32_t base = sb + (uint32_t)(kt % 3) * OSTAGE_B;
        uint32_t tA = base, tB = base + TILE_B;

        uint32_t af[16], bf[8];
        LDSM4(bf[0], bf[1], bf[2], bf[3], tB + (uint32_t)(wn * RSTR) + boff);
        LDSM4(bf[4], bf[5], bf[6], bf[7], tB + (uint32_t)((wn + 16) * RSTR) + boff);
#pragma unroll
        for (int mi = 0; mi < 4; mi++)
            LDSM4(af[mi*4], af[mi*4+1], af[mi*4+2], af[mi*4+3],
                  tA + (uint32_t)((wm + mi * 16) * RSTR) + aoff);
#pragma unroll
        for (int mi = 0; mi < 4; mi++)
#pragma unroll
            for (int ni = 0; ni < 4; ni++)
                mma_fp16(acc[mi][ni], &af[mi*4], &bf[ni*2]);
    }

#pragma unroll
    for (int mi = 0; mi < 4; mi++) {
        int r0 = m0 + wm + mi * 16 + g;
#pragma unroll
        for (int ni = 0; ni < 4; ni++) {
            int c0 = n0 + wn + ni * 8 + t * 2;
            float bv0 = bias[c0], bv1 = bias[c0 + 1];
            size_t o0 = (size_t)r0 * N + c0;
            size_t o1 = (size_t)(r0 + 8) * N + c0;
            float* a4 = acc[mi][ni];
            C[o0]     = a4[0] + bv0;
            C[o0 + 1] = a4[1] + bv1;
            C[o1]     = a4[2] + bv0;
            C[o1 + 1] = a4[3] + bv1;
        }
    }
}

// ---------------------------------------------------------------------------
// Embedding + sinusoidal PE (+ fp16 copy for layer-0 gate A)
// ---------------------------------------------------------------------------
__global__ void embed_kernel(const int* __restrict__ ids,
                             const float* __restrict__ emb,
                             float* __restrict__ x,
                             __half* __restrict__ x16) {
    int row = blockIdx.x;
    int s   = row & (S_ - 1);
    int tok = ids[row];
    int d0  = threadIdx.x * 4;
    float4 e = *(const float4*)(emb + (size_t)tok * D_ + d0);
    const float cln = -logf(10000.0f) / (float)D_;
    float pe[4];
#pragma unroll
    for (int j = 0; j < 4; j += 2) {
        float freq = expf(cln * (float)(d0 + j));
        float a = (float)s * freq;
        pe[j]   = sinf(a);
        pe[j+1] = cosf(a);
    }
    float o[4] = {e.x + pe[0], e.y + pe[1], e.z + pe[2], e.w + pe[3]};
    *(float4*)(x + (size_t)row * D_ + d0) = *(float4*)o;
    __half2 p0 = __floats2half2_rn(o[0], o[1]);
    __half2 p1 = __floats2half2_rn(o[2], o[3]);
    uint2 packed = {*(uint32_t*)&p0, *(uint32_t*)&p1};
    *(uint2*)(x16 + (size_t)row * D_ + d0) = packed;
}

// ---------------------------------------------------------------------------
// Weight splits
// ---------------------------------------------------------------------------
__global__ void split_kernel(const float* __restrict__ w,
                             __nv_bfloat16* __restrict__ hi,
                             __nv_bfloat16* __restrict__ lo, int n4) {
    int i = blockIdx.x * 256 + threadIdx.x;
    if (i >= n4) return;
    float4 v = ((const float4*)w)[i];
    ushort4 h4, l4; __nv_bfloat16 h, l;
    bf_split(v.x, h, l); h4.x = *(unsigned short*)&h; l4.x = *(unsigned short*)&l;
    bf_split(v.y, h, l); h4.y = *(unsigned short*)&h; l4.y = *(unsigned short*)&l;
    bf_split(v.z, h, l); h4.z = *(unsigned short*)&h; l4.z = *(unsigned short*)&l;
    bf_split(v.w, h, l); h4.w = *(unsigned short*)&h; l4.w = *(unsigned short*)&l;
    ((ushort4*)hi)[i] = h4;
    ((ushort4*)lo)[i] = l4;
}

// fp16 split: hi = fp16(w), lo = fp16((w - hi) * 2^10)
__global__ void split16_kernel(const float* __restrict__ w,
                               __half* __restrict__ hi,
                               __half* __restrict__ lo, int n4) {
    int i = blockIdx.x * 256 + threadIdx.x;
    if (i >= n4) return;
    float4 v = ((const float4*)w)[i];
    float vv[4] = {v.x, v.y, v.z, v.w};
    __half hh[4], ll[4];
#pragma unroll
    for (int j = 0; j < 4; j++) {
        hh[j] = __float2half(vv[j]);
        ll[j] = __float2half((vv[j] - __half2float(hh[j])) * 1024.0f);
    }
    ((ushort4*)hi)[i] = *(ushort4*)hh;
    ((ushort4*)lo)[i] = *(ushort4*)ll;
}

// ---------------------------------------------------------------------------
// outW (D,V) -> [V][D] fp16
// ---------------------------------------------------------------------------
__global__ void wout_t16_kernel(const float* __restrict__ w,
                                __half* __restrict__ o16) {
    __shared__ float tile[32][33];
    int v0 = blockIdx.x * 32, d0 = blockIdx.y * 32;
    int tx = threadIdx.x, ty = threadIdx.y;
#pragma unroll
    for (int i = 0; i < 4; i++)
        tile[ty + i * 8][tx] = w[(size_t)(d0 + ty + i * 8) * V_ + v0 + tx];
    __syncthreads();
#pragma unroll
    for (int i = 0; i < 4; i++) {
        size_t o = (size_t)(v0 + ty + i * 8) * D_ + d0 + tx;
        o16[o] = __float2half(tile[tx][ty + i * 8]);
    }
}

// ---------------------------------------------------------------------------
// LayerNorm statistics
// ---------------------------------------------------------------------------
__global__ void ln_stats_kernel(const float* __restrict__ x, float2* __restrict__ stats) {
    int row = blockIdx.x;
    float4 v = ((const float4*)(x + (size_t)row * D_))[threadIdx.x];
    float s = v.x + v.y + v.z + v.w;
    float q = v.x*v.x + v.y*v.y + v.z*v.z + v.w*v.w;
#pragma unroll
    for (int o = 16; o; o >>= 1) {
        s += __shfl_xor_sync(0xffffffffu, s, o);
        q += __shfl_xor_sync(0xffffffffu, q, o);
    }
    __shared__ float ss[8], sq[8];
    int w = threadIdx.x >> 5;
    if ((threadIdx.x & 31) == 0) { ss[w] = s; sq[w] = q; }
    __syncthreads();
    if (threadIdx.x == 0) {
        float S = 0.f, Q = 0.f;
#pragma unroll
        for (int i = 0; i < 8; i++) { S += ss[i]; Q += sq[i]; }
        float mu  = S / (float)D_;
        float var = Q / (float)D_ - mu * mu;
        stats[row] = make_float2(mu, rsqrtf(var + 1e-5f));
    }
}

// ---------------------------------------------------------------------------
// Apply LN while transposing (B,S,D)->(B,D,S)
// ---------------------------------------------------------------------------
__global__ void ln_transpose_kernel(const float* __restrict__ x,
                                    const float2* __restrict__ stats,
                                    const float* __restrict__ g,
                                    const float* __restrict__ bta,
                                    float* __restrict__ hT) {
    __shared__ float tile[32][33];
    int b  = blockIdx.z;
    int s0 = blockIdx.x * 32, d0 = blockIdx.y * 32;
    int tx = threadIdx.x, ty = threadIdx.y;
    float gg = g[d0 + tx], bb = bta[d0 + tx];
#pragma unroll
    for (int i = 0; i < 4; i++) {
        int s = s0 + ty + i * 8;
        float2 st = stats[b * S_ + s];
        float v = x[((size_t)(b * S_ + s)) * D_ + d0 + tx];
        tile[ty + i * 8][tx] = (v - st.x) * st.y * gg + bb;
    }
    __syncthreads();
#pragma unroll
    for (int i = 0; i < 4; i++) {
        int d = d0 + ty + i * 8;
        hT[((size_t)(b * D_ + d)) * S_ + s0 + tx] = tile[tx][ty + i * 8];
    }
}

// ---------------------------------------------------------------------------
// Final LN apply -> fp16
// ---------------------------------------------------------------------------
__global__ void apply_ln_kernel(const float* __restrict__ x,
                                const float2* __restrict__ stats,
                                const float* __restrict__ g,
                                const float* __restrict__ b,
                                __half* __restrict__ o16) {
    int row = blockIdx.x;
    int d0 = threadIdx.x * 4;
    float2 st = stats[row];
    float4 v  = *(const float4*)(x + (size_t)row * D_ + d0);
    float4 gg = *(const float4*)(g + d0);
    float4 bb = *(const float4*)(b + d0);
    __half2 p0 = __floats2half2_rn((v.x - st.x) * st.y * gg.x + bb.x,
                                   (v.y - st.x) * st.y * gg.y + bb.y);
    __half2 p1 = __floats2half2_rn((v.z - st.x) * st.y * gg.z + bb.z,
                                   (v.w - st.x) * st.y * gg.w + bb.w);
    uint2 packed = {*(uint32_t*)&p0, *(uint32_t*)&p1};
    *(uint2*)(o16 + (size_t)row * D_ + d0) = packed;
}

// ---------------------------------------------------------------------------
// Depthwise conv chain per (b,d) channel. k unrolled by 8 against a
// double register window (static indexing -> no per-tap MOV chain).
// ---------------------------------------------------------------------------
__global__ void __launch_bounds__(256) conv_kernel(const float* __restrict__ hT,
                                                   const float* __restrict__ lw,
                                                   const float* __restrict__ fw,
                                                   const float* __restrict__ mw,
                                                   float* __restrict__ yT) {
    int bd = blockIdx.x;
    int d  = bd & (D_ - 1);
    __shared__ float bufA[S_ + 64];
    __shared__ float bufB[S_ + 64];
    __shared__ float w3[3], wA[64], wB[64];
    int tid = threadIdx.x;
    if (tid < 64) {
        wA[tid] = fw[(size_t)d * 64 + tid];
        wB[tid] = fw[(size_t)(D_ + d) * 64 + tid];
    }
    if (tid < 3) w3[tid] = lw[d * 3 + tid];
    if (tid < 32) {
        bufA[tid] = 0.f; bufA[S_ + 32 + tid] = 0.f;
        bufB[tid] = 0.f; bufB[S_ + 32 + tid] = 0.f;
    }
    const float* cin = hT + (size_t)bd * S_;
    for (int i = tid; i < S_ / 4; i += 256)
        ((float4*)(bufA + 32))[i] = ((const float4*)cin)[i];
    __syncthreads();
    for (int s = tid; s < S_; s += 256)
        bufB[32 + s] = bufA[31 + s] * w3[0] + bufA[32 + s] * w3[1] + bufA[33 + s] * w3[2];
    __syncthreads();

    int s0 = tid * 8;
    float acc[8], win[8], nxt[8];

    // g2 = conv64a(g1) + c
#pragma unroll
    for (int j = 0; j < 8; j++) { acc[j] = bufA[32 + s0 + j]; win[j] = bufB[s0 + j]; }
#pragma unroll
    for (int k0 = 0; k0 < 64; k0 += 8) {
#pragma unroll
        for (int j = 0; j < 8; j++) nxt[j] = bufB[s0 + 8 + k0 + j];
#pragma unroll
        for (int kk = 0; kk < 8; kk++) {
            float wk = wA[k0 + kk];
#pragma unroll
            for (int j = 0; j < 8; j++) {
                int ix = j + kk;
                acc[j] += (ix < 8 ? win[ix] : nxt[ix - 8]) * wk;
            }
        }
#pragma unroll
        for (int j = 0; j < 8; j++) win[j] = nxt[j];
    }
    __syncthreads();
#pragma unroll
    for (int j = 0; j < 8; j++) bufA[32 + s0 + j] = acc[j];
    __syncthreads();

    // g3 = conv64b(g2)
    float mwd = mw[d];
#pragma unroll
    for (int j = 0; j < 8; j++) { acc[j] = 0.f; win[j] = bufA[s0 + j]; }
#pragma unroll
    for (int k0 = 0; k0 < 64; k0 += 8) {
#pragma unroll
        for (int j = 0; j < 8; j++) nxt[j] = bufA[s0 + 8 + k0 + j];
#pragma unroll
        for (int kk = 0; kk < 8; kk++) {
            float wk = wB[k0 + kk];
#pragma unroll
            for (int j = 0; j < 8; j++) {
                int ix = j + kk;
                acc[j] += (ix < 8 ? win[ix] : nxt[ix - 8]) * wk;
            }
        }
#pragma unroll
        for (int j = 0; j < 8; j++) win[j] = nxt[j];
    }
    float* outp = yT + (size_t)bd * S_;
#pragma unroll
    for (int j = 0; j < 8; j++) {
        float m = acc[j] * mwd;
        outp[s0 + j] = m / (1.0f + expf(-m));
    }
}

// ---------------------------------------------------------------------------
// yT (B,D,S) -> y (B,S,D) hi/lo bf16 (refine GEMM A)
// ---------------------------------------------------------------------------
__global__ void y_tsplit_kernel(const float* __restrict__ yT,
                                __nv_bfloat16* __restrict__ yh,
                                __nv_bfloat16* __restrict__ yl) {
    __shared__ float tile[32][33];
    int b  = blockIdx.z;
    int s0 = blockIdx.x * 32, d0 = blockIdx.y * 32;
    int tx = threadIdx.x, ty = threadIdx.y;
#pragma unroll
    for (int i = 0; i < 4; i++)
        tile[ty + i * 8][tx] = yT[((size_t)(b * D_ + d0 + ty + i * 8)) * S_ + s0 + tx];
    __syncthreads();
#pragma unroll
    for (int i = 0; i < 4; i++) {
        float val = tile[tx][ty + i * 8];
        __nv_bfloat16 h, l;
        bf_split(val, h, l);
        size_t o = (size_t)(b * S_ + s0 + ty + i * 8) * D_ + d0 + tx;
        yh[o] = h; yl[o] = l;
    }
}

// ---------------------------------------------------------------------------
// Host orchestration
// ---------------------------------------------------------------------------
static void* sym_addr(const void* sym) {
    void* p = nullptr;
    cudaGetSymbolAddress(&p, sym);
    return p;
}

extern "C" void kernel_launch(void* const* d_in, const int* in_sizes, int n_in,
                              void* d_out, int out_size) {
    (void)in_sizes; (void)n_in; (void)out_size;
    const int*   ids   = (const int*)d_in[0];
    const float* emb   = (const float*)d_in[1];
    const float* lw    = (const float*)d_in[2];
    const float* fw    = (const float*)d_in[3];
    const float* mw    = (const float*)d_in[4];
    const float* ln1g  = (const float*)d_in[5];
    const float* ln1b  = (const float*)d_in[6];
    const float* refW  = (const float*)d_in[7];
    const float* refb  = (const float*)d_in[8];
    const float* gateW = (const float*)d_in[9];
    const float* gateb = (const float*)d_in[10];
    const float* lnfg  = (const float*)d_in[11];
    const float* lnfb  = (const float*)d_in[12];
    const float* outW  = (const float*)d_in[13];
    const float* outb  = (const float*)d_in[14];
    float* out = (float*)d_out;

    float*  x0  = (float*)sym_addr(g_x0);
    float*  x1  = (float*)sym_addr(g_x1);
    float*  hT  = (float*)sym_addr(g_hT);
    float*  yT  = (float*)sym_addr(g_yT);
    float*  rf  = (float*)sym_addr(g_ref);
    float2* st  = (float2*)sym_addr(g_stats);
    __half* x016 = (__half*)sym_addr(g_x016);
    __half* x116 = (__half*)sym_addr(g_x116);
    __nv_bfloat16* yh  = (__nv_bfloat16*)sym_addr(g_yh);
    __nv_bfloat16* yl  = (__nv_bfloat16*)sym_addr(g_yl);
    __nv_bfloat16* wrh = (__nv_bfloat16*)sym_addr(g_wrh);
    __nv_bfloat16* wrl = (__nv_bfloat16*)sym_addr(g_wrl);
    __half* wgh16 = (__half*)sym_addr(g_wgh16);
    __half* wgl16 = (__half*)sym_addr(g_wgl16);
    __half* xf16 = (__half*)sym_addr(g_xf16);
    __half* wo16 = (__half*)sym_addr(g_wo16);

    cudaFuncSetAttribute(gemm_bf,   cudaFuncAttributeMaxDynamicSharedMemorySize, GEMM_SMEM);
    cudaFuncSetAttribute(gemm_gate, cudaFuncAttributeMaxDynamicSharedMemorySize, GGEMM_SMEM);
    cudaFuncSetAttribute(gemm_out,  cudaFuncAttributeMaxDynamicSharedMemorySize, OGEMM_SMEM);

    {
        int n4 = NL_ * D_ * D_ / 4;
        split_kernel<<<(n4 + 255) / 256, 256>>>(refW,  wrh, wrl, n4);
        split16_kernel<<<(n4 + 255) / 256, 256>>>(gateW, wgh16, wgl16, n4);
        wout_t16_kernel<<<dim3(V_ / 32, D_ / 32), dim3(32, 8)>>>(outW, wo16);
    }

    embed_kernel<<<M_, 256>>>(ids, emb, x0, x016);

    float* cur = x0;        float* nxt = x1;
    __half *cur16 = x016, *nxt16 = x116;
    for (int l = 0; l < NL_; l++) {
        ln_stats_kernel<<<M_, 256>>>(cur, st);
        ln_transpose_kernel<<<dim3(S_/32, D_/32, B_), dim3(32, 8)>>>(
            cur, st, ln1g + (size_t)l * D_, ln1b + (size_t)l * D_, hT);
        conv_kernel<<<B_*D_, 256>>>(
            hT, lw + (size_t)l * D_ * 3, fw + (size_t)l * 2 * D_ * 64,
            mw + (size_t)l * D_, yT);
        y_tsplit_kernel<<<dim3(S_/32, D_/32, B_), dim3(32, 8)>>>(yT, yh, yl);
        gemm_bf<<<dim3(M_/128, D_/128), 256, GEMM_SMEM>>>(
            yh, yl, wrh + (size_t)l * D_ * D_, wrl + (size_t)l * D_ * D_,
            refb + (size_t)l * D_, rf, M_, D_, D_);
        gemm_gate<<<dim3(M_/128, D_/128), 256, GGEMM_SMEM>>>(
            cur16, wgh16 + (size_t)l * D_ * D_, wgl16 + (size_t)l * D_ * D_,
            gateb + (size_t)l * D_, rf, cur, nxt, nxt16,
            M_, D_, D_);
        { float* tf = cur; cur = nxt; nxt = tf; }
        { __half* th = cur16; cur16 = nxt16; nxt16 = th; }
    }

    ln_stats_kernel<<<M_, 256>>>(cur, st);
    apply_ln_kernel<<<M_, 256>>>(cur, st, lnfg, lnfb, xf16);
    gemm_out<<<dim3(M_/128, V_/128), 256, OGEMM_SMEM>>>(
        xf16, wo16, outb, out, M_, V_, D_);
}

// round 8
// speedup vs baseline: 4.1550x; 1.1308x over previous
#include <cuda_runtime.h>
#include <cuda_fp16.h>
#include <math.h>
#include <stdint.h>

#define B_  2
#define S_  2048
#define D_  1024
#define V_  32000
#define NL_ 6
#define M_  (B_*S_)   // 4096 tokens

// ---------------------------------------------------------------------------
// Scratch
// ---------------------------------------------------------------------------
__device__ float  g_x0[M_*D_];
__device__ float  g_x1[M_*D_];
__device__ float  g_hT[M_*D_];
__device__ float  g_yT[M_*D_];
__device__ float  g_ref[M_*D_];
__device__ float2 g_stats[M_];

__device__ __half g_x016[M_*D_], g_x116[M_*D_];
__device__ __half g_y16[M_*D_];
__device__ __half g_wrh16[NL_*D_*D_], g_wrl16[NL_*D_*D_];
__device__ __half g_wgh16[NL_*D_*D_], g_wgl16[NL_*D_*D_];
__device__ __half g_xf16[M_*D_];
__device__ __half g_wo16[(size_t)V_*D_];

// ---------------------------------------------------------------------------
// PTX helpers
// ---------------------------------------------------------------------------
__device__ __forceinline__ uint32_t smem_u32(const void* p) {
    uint32_t a;
    asm("{ .reg .u64 t; cvta.to.shared.u64 t, %1; cvt.u32.u64 %0, t; }" : "=r"(a) : "l"(p));
    return a;
}
__device__ __forceinline__ void cp16s(uint32_t saddr, const void* g) {
    asm volatile("cp.async.cg.shared.global [%0], [%1], 16;\n" :: "r"(saddr), "l"(g));
}
__device__ __forceinline__ void cp_commit() {
    asm volatile("cp.async.commit_group;\n" ::: "memory");
}
template<int N_> __device__ __forceinline__ void cp_wait() {
    asm volatile("cp.async.wait_group %0;\n" :: "n"(N_) : "memory");
}
__device__ __forceinline__ void mma_fp16(float* c, const uint32_t* a, const uint32_t* b) {
    asm volatile(
        "mma.sync.aligned.m16n8k16.row.col.f32.f16.f16.f32 "
        "{%0,%1,%2,%3}, {%4,%5,%6,%7}, {%8,%9}, {%0,%1,%2,%3};"
        : "+f"(c[0]), "+f"(c[1]), "+f"(c[2]), "+f"(c[3])
        : "r"(a[0]), "r"(a[1]), "r"(a[2]), "r"(a[3]), "r"(b[0]), "r"(b[1]));
}
#define LDSM4(r0, r1, r2, r3, addr) \
    asm volatile("ldmatrix.sync.aligned.m8n8.x4.shared.b16 {%0,%1,%2,%3}, [%4];" \
        : "=r"(r0), "=r"(r1), "=r"(r2), "=r"(r3) : "r"(addr))

#define RSTR   48                    // bytes per smem row
#define TILE_B (128 * RSTR)          // 6144 B per operand tile

// ---------------------------------------------------------------------------
// Layer GEMM (refine & gate): fp16 2-product, B reconstructed to ~21 bits.
//   z = A16*Bhi + (A16*2^-10)*(Blo*2^10)   (fp32 accum)
// CTA 128x128, BK=16, 8 warps (64x32), 3-stage cp.async, ldmatrix frags.
// EPI 0 (refine): C = z + bias (fp32)
// EPI 1 (gate)  : s=sigmoid(z+bias); x' = s*refined+(1-s)*orig -> fp32+fp16
// ---------------------------------------------------------------------------
#define GSTAGE_B (3 * TILE_B)          // 18432 B
#define GGEMM_SMEM (3 * GSTAGE_B)      // 55296 B

template<int EPI>
__global__ void __launch_bounds__(256, 2) gemm_f16(
        const __half* __restrict__ A,
        const __half* __restrict__ Bhi, const __half* __restrict__ Blo,
        const float* __restrict__ bias,
        const float* __restrict__ refined, const float* __restrict__ orig,
        float* __restrict__ C, __half* __restrict__ C16,
        int M, int N, int K)
{
    extern __shared__ char smem[];
    uint32_t sb = smem_u32(smem);

    int tid  = threadIdx.x;
    int lane = tid & 31;
    int warp = tid >> 5;
    int g = lane >> 2, t = lane & 3;
    int wm = (warp >> 2) * 64;
    int wn = (warp & 3) * 32;
    int m0 = blockIdx.x * 128, n0 = blockIdx.y * 128;

    uint32_t aoff = (uint32_t)((((lane & 7) + ((lane >> 3) & 1) * 8) * RSTR) + ((lane >> 4) & 1) * 16);
    uint32_t boff = (uint32_t)((((lane & 7) + ((lane >> 4) & 1) * 8) * RSTR) + ((lane >> 3) & 1) * 16);

    int lr = tid >> 1;
    int lc8 = (tid & 1) * 8;
    uint32_t so = (uint32_t)(lr * RSTR + (tid & 1) * 16);

    const __half2 sc = __floats2half2_rn(9.765625e-4f, 9.765625e-4f);  // 2^-10

    float acc[4][4][4];
#pragma unroll
    for (int mi = 0; mi < 4; mi++)
#pragma unroll
        for (int ni = 0; ni < 4; ni++)
#pragma unroll
            for (int r = 0; r < 4; r++) acc[mi][ni][r] = 0.f;

    auto load_stage = [&](int st, int kt) {
        int k0 = kt * 16;
        uint32_t base = sb + (uint32_t)st * GSTAGE_B;
        size_t ga = (size_t)(m0 + lr) * K + k0 + lc8;
        size_t gb = (size_t)(n0 + lr) * K + k0 + lc8;
        cp16s(base + so,              A   + ga);
        cp16s(base + TILE_B + so,     Bhi + gb);
        cp16s(base + 2 * TILE_B + so, Blo + gb);
    };

    int KT = K >> 4;
    load_stage(0, 0); cp_commit();
    load_stage(1, 1); cp_commit();

    for (int kt = 0; kt < KT; kt++) {
        if (kt == KT - 1) cp_wait<0>(); else cp_wait<1>();
        __syncthreads();
        if (kt + 2 < KT) { load_stage((kt + 2) % 3, kt + 2); cp_commit(); }

        uint32_t base = sb + (uint32_t)(kt % 3) * GSTAGE_B;
        uint32_t tA = base, tBh = base + TILE_B, tBl = base + 2 * TILE_B;

        uint32_t af[16], bh[8], bl[8];
        LDSM4(bh[0], bh[1], bh[2], bh[3], tBh + (uint32_t)(wn * RSTR) + boff);
        LDSM4(bh[4], bh[5], bh[6], bh[7], tBh + (uint32_t)((wn + 16) * RSTR) + boff);
        LDSM4(bl[0], bl[1], bl[2], bl[3], tBl + (uint32_t)(wn * RSTR) + boff);
        LDSM4(bl[4], bl[5], bl[6], bl[7], tBl + (uint32_t)((wn + 16) * RSTR) + boff);
#pragma unroll
        for (int mi = 0; mi < 4; mi++)
            LDSM4(af[mi*4], af[mi*4+1], af[mi*4+2], af[mi*4+3],
                  tA + (uint32_t)((wm + mi * 16) * RSTR) + aoff);

#pragma unroll
        for (int mi = 0; mi < 4; mi++)
#pragma unroll
            for (int ni = 0; ni < 4; ni++)
                mma_fp16(acc[mi][ni], &af[mi*4], &bh[ni*2]);

        // scale A frags by 2^-10 in registers
#pragma unroll
        for (int i = 0; i < 16; i++) {
            __half2 v = *(__half2*)&af[i];
            v = __hmul2(v, sc);
            af[i] = *(uint32_t*)&v;
        }
#pragma unroll
        for (int mi = 0; mi < 4; mi++)
#pragma unroll
            for (int ni = 0; ni < 4; ni++)
                mma_fp16(acc[mi][ni], &af[mi*4], &bl[ni*2]);
    }

#pragma unroll
    for (int mi = 0; mi < 4; mi++) {
        int r0 = m0 + wm + mi * 16 + g;
#pragma unroll
        for (int ni = 0; ni < 4; ni++) {
            int c0 = n0 + wn + ni * 8 + t * 2;
            float bv0 = bias[c0], bv1 = bias[c0 + 1];
            size_t o0 = (size_t)r0 * N + c0;
            size_t o1 = (size_t)(r0 + 8) * N + c0;
            float* a4 = acc[mi][ni];
            if (EPI == 0) {
                C[o0]     = a4[0] + bv0;
                C[o0 + 1] = a4[1] + bv1;
                C[o1]     = a4[2] + bv0;
                C[o1 + 1] = a4[3] + bv1;
            } else {
                float pre[4] = {a4[0] + bv0, a4[1] + bv1, a4[2] + bv0, a4[3] + bv1};
                size_t offs[4] = {o0, o0 + 1, o1, o1 + 1};
#pragma unroll
                for (int j = 0; j < 4; j++) {
                    float gt = 1.f / (1.f + expf(-pre[j]));
                    float res = gt * refined[offs[j]] + (1.f - gt) * orig[offs[j]];
                    C[offs[j]] = res;
                    C16[offs[j]] = __float2half(res);
                }
            }
        }
    }
}

// ---------------------------------------------------------------------------
// Output GEMM: single-product fp16 (non-compounding final projection).
// ---------------------------------------------------------------------------
#define OSTAGE_B (2 * TILE_B)          // 12288 B
#define OGEMM_SMEM (3 * OSTAGE_B)      // 36864 B

__global__ void __launch_bounds__(256, 2) gemm_out(
        const __half* __restrict__ A, const __half* __restrict__ Bm,
        const float* __restrict__ bias,
        float* __restrict__ C, int M, int N, int K)
{
    extern __shared__ char smem[];
    uint32_t sb = smem_u32(smem);

    int tid  = threadIdx.x;
    int lane = tid & 31;
    int warp = tid >> 5;
    int g = lane >> 2, t = lane & 3;
    int wm = (warp >> 2) * 64;
    int wn = (warp & 3) * 32;
    int m0 = blockIdx.x * 128, n0 = blockIdx.y * 128;

    uint32_t aoff = (uint32_t)((((lane & 7) + ((lane >> 3) & 1) * 8) * RSTR) + ((lane >> 4) & 1) * 16);
    uint32_t boff = (uint32_t)((((lane & 7) + ((lane >> 4) & 1) * 8) * RSTR) + ((lane >> 3) & 1) * 16);

    int lr = tid >> 1;
    int lc8 = (tid & 1) * 8;
    uint32_t so = (uint32_t)(lr * RSTR + (tid & 1) * 16);

    float acc[4][4][4];
#pragma unroll
    for (int mi = 0; mi < 4; mi++)
#pragma unroll
        for (int ni = 0; ni < 4; ni++)
#pragma unroll
            for (int r = 0; r < 4; r++) acc[mi][ni][r] = 0.f;

    auto load_stage = [&](int st, int kt) {
        int k0 = kt * 16;
        uint32_t base = sb + (uint32_t)st * OSTAGE_B;
        cp16s(base + so,          A  + (size_t)(m0 + lr) * K + k0 + lc8);
        cp16s(base + TILE_B + so, Bm + (size_t)(n0 + lr) * K + k0 + lc8);
    };

    int KT = K >> 4;
    load_stage(0, 0); cp_commit();
    load_stage(1, 1); cp_commit();

    for (int kt = 0; kt < KT; kt++) {
        if (kt == KT - 1) cp_wait<0>(); else cp_wait<1>();
        __syncthreads();
        if (kt + 2 < KT) { load_stage((kt + 2) % 3, kt + 2); cp_commit(); }

        uint32_t base = sb + (uint32_t)(kt % 3) * OSTAGE_B;
        uint32_t tA = base, tB = base + TILE_B;

        uint32_t af[16], bf[8];
        LDSM4(bf[0], bf[1], bf[2], bf[3], tB + (uint32_t)(wn * RSTR) + boff);
        LDSM4(bf[4], bf[5], bf[6], bf[7], tB + (uint32_t)((wn + 16) * RSTR) + boff);
#pragma unroll
        for (int mi = 0; mi < 4; mi++)
            LDSM4(af[mi*4], af[mi*4+1], af[mi*4+2], af[mi*4+3],
                  tA + (uint32_t)((wm + mi * 16) * RSTR) + aoff);
#pragma unroll
        for (int mi = 0; mi < 4; mi++)
#pragma unroll
            for (int ni = 0; ni < 4; ni++)
                mma_fp16(acc[mi][ni], &af[mi*4], &bf[ni*2]);
    }

#pragma unroll
    for (int mi = 0; mi < 4; mi++) {
        int r0 = m0 + wm + mi * 16 + g;
#pragma unroll
        for (int ni = 0; ni < 4; ni++) {
            int c0 = n0 + wn + ni * 8 + t * 2;
            float bv0 = bias[c0], bv1 = bias[c0 + 1];
            size_t o0 = (size_t)r0 * N + c0;
            size_t o1 = (size_t)(r0 + 8) * N + c0;
            float* a4 = acc[mi][ni];
            C[o0]     = a4[0] + bv0;
            C[o0 + 1] = a4[1] + bv1;
            C[o1]     = a4[2] + bv0;
            C[o1 + 1] = a4[3] + bv1;
        }
    }
}

// ---------------------------------------------------------------------------
// Embedding + sinusoidal PE (+ fp16 copy for layer-0 gate A)
// ---------------------------------------------------------------------------
__global__ void embed_kernel(const int* __restrict__ ids,
                             const float* __restrict__ emb,
                             float* __restrict__ x,
                             __half* __restrict__ x16) {
    int row = blockIdx.x;
    int s   = row & (S_ - 1);
    int tok = ids[row];
    int d0  = threadIdx.x * 4;
    float4 e = *(const float4*)(emb + (size_t)tok * D_ + d0);
    const float cln = -logf(10000.0f) / (float)D_;
    float pe[4];
#pragma unroll
    for (int j = 0; j < 4; j += 2) {
        float freq = expf(cln * (float)(d0 + j));
        float a = (float)s * freq;
        pe[j]   = sinf(a);
        pe[j+1] = cosf(a);
    }
    float o[4] = {e.x + pe[0], e.y + pe[1], e.z + pe[2], e.w + pe[3]};
    *(float4*)(x + (size_t)row * D_ + d0) = *(float4*)o;
    __half2 p0 = __floats2half2_rn(o[0], o[1]);
    __half2 p1 = __floats2half2_rn(o[2], o[3]);
    uint2 packed = {*(uint32_t*)&p0, *(uint32_t*)&p1};
    *(uint2*)(x16 + (size_t)row * D_ + d0) = packed;
}

// ---------------------------------------------------------------------------
// fp16 split: hi = fp16(w), lo = fp16((w - hi) * 2^10)
// ---------------------------------------------------------------------------
__global__ void split16_kernel(const float* __restrict__ w,
                               __half* __restrict__ hi,
                               __half* __restrict__ lo, int n4) {
    int i = blockIdx.x * 256 + threadIdx.x;
    if (i >= n4) return;
    float4 v = ((const float4*)w)[i];
    float vv[4] = {v.x, v.y, v.z, v.w};
    __half hh[4], ll[4];
#pragma unroll
    for (int j = 0; j < 4; j++) {
        hh[j] = __float2half(vv[j]);
        ll[j] = __float2half((vv[j] - __half2float(hh[j])) * 1024.0f);
    }
    ((ushort4*)hi)[i] = *(ushort4*)hh;
    ((ushort4*)lo)[i] = *(ushort4*)ll;
}

// ---------------------------------------------------------------------------
// outW (D,V) -> [V][D] fp16
// ---------------------------------------------------------------------------
__global__ void wout_t16_kernel(const float* __restrict__ w,
                                __half* __restrict__ o16) {
    __shared__ float tile[32][33];
    int v0 = blockIdx.x * 32, d0 = blockIdx.y * 32;
    int tx = threadIdx.x, ty = threadIdx.y;
#pragma unroll
    for (int i = 0; i < 4; i++)
        tile[ty + i * 8][tx] = w[(size_t)(d0 + ty + i * 8) * V_ + v0 + tx];
    __syncthreads();
#pragma unroll
    for (int i = 0; i < 4; i++) {
        size_t o = (size_t)(v0 + ty + i * 8) * D_ + d0 + tx;
        o16[o] = __float2half(tile[tx][ty + i * 8]);
    }
}

// ---------------------------------------------------------------------------
// LayerNorm statistics
// ---------------------------------------------------------------------------
__global__ void ln_stats_kernel(const float* __restrict__ x, float2* __restrict__ stats) {
    int row = blockIdx.x;
    float4 v = ((const float4*)(x + (size_t)row * D_))[threadIdx.x];
    float s = v.x + v.y + v.z + v.w;
    float q = v.x*v.x + v.y*v.y + v.z*v.z + v.w*v.w;
#pragma unroll
    for (int o = 16; o; o >>= 1) {
        s += __shfl_xor_sync(0xffffffffu, s, o);
        q += __shfl_xor_sync(0xffffffffu, q, o);
    }
    __shared__ float ss[8], sq[8];
    int w = threadIdx.x >> 5;
    if ((threadIdx.x & 31) == 0) { ss[w] = s; sq[w] = q; }
    __syncthreads();
    if (threadIdx.x == 0) {
        float S = 0.f, Q = 0.f;
#pragma unroll
        for (int i = 0; i < 8; i++) { S += ss[i]; Q += sq[i]; }
        float mu  = S / (float)D_;
        float var = Q / (float)D_ - mu * mu;
        stats[row] = make_float2(mu, rsqrtf(var + 1e-5f));
    }
}

// ---------------------------------------------------------------------------
// Apply LN while transposing (B,S,D)->(B,D,S)
// ---------------------------------------------------------------------------
__global__ void ln_transpose_kernel(const float* __restrict__ x,
                                    const float2* __restrict__ stats,
                                    const float* __restrict__ g,
                                    const float* __restrict__ bta,
                                    float* __restrict__ hT) {
    __shared__ float tile[32][33];
    int b  = blockIdx.z;
    int s0 = blockIdx.x * 32, d0 = blockIdx.y * 32;
    int tx = threadIdx.x, ty = threadIdx.y;
    float gg = g[d0 + tx], bb = bta[d0 + tx];
#pragma unroll
    for (int i = 0; i < 4; i++) {
        int s = s0 + ty + i * 8;
        float2 st = stats[b * S_ + s];
        float v = x[((size_t)(b * S_ + s)) * D_ + d0 + tx];
        tile[ty + i * 8][tx] = (v - st.x) * st.y * gg + bb;
    }
    __syncthreads();
#pragma unroll
    for (int i = 0; i < 4; i++) {
        int d = d0 + ty + i * 8;
        hT[((size_t)(b * D_ + d)) * S_ + s0 + tx] = tile[tx][ty + i * 8];
    }
}

// ---------------------------------------------------------------------------
// Final LN apply -> fp16
// ---------------------------------------------------------------------------
__global__ void apply_ln_kernel(const float* __restrict__ x,
                                const float2* __restrict__ stats,
                                const float* __restrict__ g,
                                const float* __restrict__ b,
                                __half* __restrict__ o16) {
    int row = blockIdx.x;
    int d0 = threadIdx.x * 4;
    float2 st = stats[row];
    float4 v  = *(const float4*)(x + (size_t)row * D_ + d0);
    float4 gg = *(const float4*)(g + d0);
    float4 bb = *(const float4*)(b + d0);
    __half2 p0 = __floats2half2_rn((v.x - st.x) * st.y * gg.x + bb.x,
                                   (v.y - st.x) * st.y * gg.y + bb.y);
    __half2 p1 = __floats2half2_rn((v.z - st.x) * st.y * gg.z + bb.z,
                                   (v.w - st.x) * st.y * gg.w + bb.w);
    uint2 packed = {*(uint32_t*)&p0, *(uint32_t*)&p1};
    *(uint2*)(o16 + (size_t)row * D_ + d0) = packed;
}

// ---------------------------------------------------------------------------
// Depthwise conv chain per (b,d) channel. k unrolled by 8 against a
// double register window (static indexing -> no per-tap MOV chain).
// ---------------------------------------------------------------------------
__global__ void __launch_bounds__(256) conv_kernel(const float* __restrict__ hT,
                                                   const float* __restrict__ lw,
                                                   const float* __restrict__ fw,
                                                   const float* __restrict__ mw,
                                                   float* __restrict__ yT) {
    int bd = blockIdx.x;
    int d  = bd & (D_ - 1);
    __shared__ float bufA[S_ + 64];
    __shared__ float bufB[S_ + 64];
    __shared__ float w3[3], wA[64], wB[64];
    int tid = threadIdx.x;
    if (tid < 64) {
        wA[tid] = fw[(size_t)d * 64 + tid];
        wB[tid] = fw[(size_t)(D_ + d) * 64 + tid];
    }
    if (tid < 3) w3[tid] = lw[d * 3 + tid];
    if (tid < 32) {
        bufA[tid] = 0.f; bufA[S_ + 32 + tid] = 0.f;
        bufB[tid] = 0.f; bufB[S_ + 32 + tid] = 0.f;
    }
    const float* cin = hT + (size_t)bd * S_;
    for (int i = tid; i < S_ / 4; i += 256)
        ((float4*)(bufA + 32))[i] = ((const float4*)cin)[i];
    __syncthreads();
    for (int s = tid; s < S_; s += 256)
        bufB[32 + s] = bufA[31 + s] * w3[0] + bufA[32 + s] * w3[1] + bufA[33 + s] * w3[2];
    __syncthreads();

    int s0 = tid * 8;
    float acc[8], win[8], nxt[8];

#pragma unroll
    for (int j = 0; j < 8; j++) { acc[j] = bufA[32 + s0 + j]; win[j] = bufB[s0 + j]; }
#pragma unroll
    for (int k0 = 0; k0 < 64; k0 += 8) {
#pragma unroll
        for (int j = 0; j < 8; j++) nxt[j] = bufB[s0 + 8 + k0 + j];
#pragma unroll
        for (int kk = 0; kk < 8; kk++) {
            float wk = wA[k0 + kk];
#pragma unroll
            for (int j = 0; j < 8; j++) {
                int ix = j + kk;
                acc[j] += (ix < 8 ? win[ix] : nxt[ix - 8]) * wk;
            }
        }
#pragma unroll
        for (int j = 0; j < 8; j++) win[j] = nxt[j];
    }
    __syncthreads();
#pragma unroll
    for (int j = 0; j < 8; j++) bufA[32 + s0 + j] = acc[j];
    __syncthreads();

    float mwd = mw[d];
#pragma unroll
    for (int j = 0; j < 8; j++) { acc[j] = 0.f; win[j] = bufA[s0 + j]; }
#pragma unroll
    for (int k0 = 0; k0 < 64; k0 += 8) {
#pragma unroll
        for (int j = 0; j < 8; j++) nxt[j] = bufA[s0 + 8 + k0 + j];
#pragma unroll
        for (int kk = 0; kk < 8; kk++) {
            float wk = wB[k0 + kk];
#pragma unroll
            for (int j = 0; j < 8; j++) {
                int ix = j + kk;
                acc[j] += (ix < 8 ? win[ix] : nxt[ix - 8]) * wk;
            }
        }
#pragma unroll
        for (int j = 0; j < 8; j++) win[j] = nxt[j];
    }
    float* outp = yT + (size_t)bd * S_;
#pragma unroll
    for (int j = 0; j < 8; j++) {
        float m = acc[j] * mwd;
        outp[s0 + j] = m / (1.0f + expf(-m));
    }
}

// ---------------------------------------------------------------------------
// yT (B,D,S) -> y (B,S,D) fp16 (refine GEMM A)
// ---------------------------------------------------------------------------
__global__ void y_t16_kernel(const float* __restrict__ yT,
                             __half* __restrict__ y16) {
    __shared__ float tile[32][33];
    int b  = blockIdx.z;
    int s0 = blockIdx.x * 32, d0 = blockIdx.y * 32;
    int tx = threadIdx.x, ty = threadIdx.y;
#pragma unroll
    for (int i = 0; i < 4; i++)
        tile[ty + i * 8][tx] = yT[((size_t)(b * D_ + d0 + ty + i * 8)) * S_ + s0 + tx];
    __syncthreads();
#pragma unroll
    for (int i = 0; i < 4; i++) {
        size_t o = (size_t)(b * S_ + s0 + ty + i * 8) * D_ + d0 + tx;
        y16[o] = __float2half(tile[tx][ty + i * 8]);
    }
}

// ---------------------------------------------------------------------------
// Host orchestration
// ---------------------------------------------------------------------------
static void* sym_addr(const void* sym) {
    void* p = nullptr;
    cudaGetSymbolAddress(&p, sym);
    return p;
}

extern "C" void kernel_launch(void* const* d_in, const int* in_sizes, int n_in,
                              void* d_out, int out_size) {
    (void)in_sizes; (void)n_in; (void)out_size;
    const int*   ids   = (const int*)d_in[0];
    const float* emb   = (const float*)d_in[1];
    const float* lw    = (const float*)d_in[2];
    const float* fw    = (const float*)d_in[3];
    const float* mw    = (const float*)d_in[4];
    const float* ln1g  = (const float*)d_in[5];
    const float* ln1b  = (const float*)d_in[6];
    const float* refW  = (const float*)d_in[7];
    const float* refb  = (const float*)d_in[8];
    const float* gateW = (const float*)d_in[9];
    const float* gateb = (const float*)d_in[10];
    const float* lnfg  = (const float*)d_in[11];
    const float* lnfb  = (const float*)d_in[12];
    const float* outW  = (const float*)d_in[13];
    const float* outb  = (const float*)d_in[14];
    float* out = (float*)d_out;

    float*  x0  = (float*)sym_addr(g_x0);
    float*  x1  = (float*)sym_addr(g_x1);
    float*  hT  = (float*)sym_addr(g_hT);
    float*  yT  = (float*)sym_addr(g_yT);
    float*  rf  = (float*)sym_addr(g_ref);
    float2* st  = (float2*)sym_addr(g_stats);
    __half* x016 = (__half*)sym_addr(g_x016);
    __half* x116 = (__half*)sym_addr(g_x116);
    __half* y16  = (__half*)sym_addr(g_y16);
    __half* wrh16 = (__half*)sym_addr(g_wrh16);
    __half* wrl16 = (__half*)sym_addr(g_wrl16);
    __half* wgh16 = (__half*)sym_addr(g_wgh16);
    __half* wgl16 = (__half*)sym_addr(g_wgl16);
    __half* xf16 = (__half*)sym_addr(g_xf16);
    __half* wo16 = (__half*)sym_addr(g_wo16);

    cudaFuncSetAttribute(gemm_f16<0>, cudaFuncAttributeMaxDynamicSharedMemorySize, GGEMM_SMEM);
    cudaFuncSetAttribute(gemm_f16<1>, cudaFuncAttributeMaxDynamicSharedMemorySize, GGEMM_SMEM);
    cudaFuncSetAttribute(gemm_out,    cudaFuncAttributeMaxDynamicSharedMemorySize, OGEMM_SMEM);

    {
        int n4 = NL_ * D_ * D_ / 4;
        split16_kernel<<<(n4 + 255) / 256, 256>>>(refW,  wrh16, wrl16, n4);
        split16_kernel<<<(n4 + 255) / 256, 256>>>(gateW, wgh16, wgl16, n4);
        wout_t16_kernel<<<dim3(V_ / 32, D_ / 32), dim3(32, 8)>>>(outW, wo16);
    }

    embed_kernel<<<M_, 256>>>(ids, emb, x0, x016);

    float* cur = x0;        float* nxt = x1;
    __half *cur16 = x016, *nxt16 = x116;
    for (int l = 0; l < NL_; l++) {
        ln_stats_kernel<<<M_, 256>>>(cur, st);
        ln_transpose_kernel<<<dim3(S_/32, D_/32, B_), dim3(32, 8)>>>(
            cur, st, ln1g + (size_t)l * D_, ln1b + (size_t)l * D_, hT);
        conv_kernel<<<B_*D_, 256>>>(
            hT, lw + (size_t)l * D_ * 3, fw + (size_t)l * 2 * D_ * 64,
            mw + (size_t)l * D_, yT);
        y_t16_kernel<<<dim3(S_/32, D_/32, B_), dim3(32, 8)>>>(yT, y16);
        gemm_f16<0><<<dim3(M_/128, D_/128), 256, GGEMM_SMEM>>>(
            y16, wrh16 + (size_t)l * D_ * D_, wrl16 + (size_t)l * D_ * D_,
            refb + (size_t)l * D_, nullptr, nullptr, rf, nullptr,
            M_, D_, D_);
        gemm_f16<1><<<dim3(M_/128, D_/128), 256, GGEMM_SMEM>>>(
            cur16, wgh16 + (size_t)l * D_ * D_, wgl16 + (size_t)l * D_ * D_,
            gateb + (size_t)l * D_, rf, cur, nxt, nxt16,
            M_, D_, D_);
        { float* tf = cur; cur = nxt; nxt = tf; }
        { __half* th = cur16; cur16 = nxt16; nxt16 = th; }
    }

    ln_stats_kernel<<<M_, 256>>>(cur, st);
    apply_ln_kernel<<<M_, 256>>>(cur, st, lnfg, lnfb, xf16);
    gemm_out<<<dim3(M_/128, V_/128), 256, OGEMM_SMEM>>>(
        xf16, wo16, outb, out, M_, V_, D_);
}

// round 9
// speedup vs baseline: 4.5468x; 1.0943x over previous
#include <cuda_runtime.h>
#include <cuda_fp16.h>
#include <math.h>
#include <stdint.h>

#define B_  2
#define S_  2048
#define D_  1024
#define V_  32000
#define NL_ 6
#define M_  (B_*S_)   // 4096 tokens

// ---------------------------------------------------------------------------
// Scratch
// ---------------------------------------------------------------------------
__device__ float  g_x0[M_*D_];
__device__ float  g_x1[M_*D_];
__device__ float  g_hT[M_*D_];
__device__ float  g_ref[M_*D_];
__device__ float2 g_stats[M_];

__device__ __half g_x016[M_*D_], g_x116[M_*D_];
__device__ __half g_yT16[M_*D_];                       // conv out, (B,D,S) fp16
__device__ __half g_wrh16[NL_*D_*D_], g_wrl16[NL_*D_*D_];
__device__ __half g_wg16[NL_*D_*D_];
__device__ __half g_xf16[M_*D_];
__device__ __half g_wo16[(size_t)V_*D_];

// ---------------------------------------------------------------------------
// PTX helpers
// ---------------------------------------------------------------------------
__device__ __forceinline__ uint32_t smem_u32(const void* p) {
    uint32_t a;
    asm("{ .reg .u64 t; cvta.to.shared.u64 t, %1; cvt.u32.u64 %0, t; }" : "=r"(a) : "l"(p));
    return a;
}
__device__ __forceinline__ void cp16s(uint32_t saddr, const void* g) {
    asm volatile("cp.async.cg.shared.global [%0], [%1], 16;\n" :: "r"(saddr), "l"(g));
}
__device__ __forceinline__ void cp_commit() {
    asm volatile("cp.async.commit_group;\n" ::: "memory");
}
template<int N_> __device__ __forceinline__ void cp_wait() {
    asm volatile("cp.async.wait_group %0;\n" :: "n"(N_) : "memory");
}
__device__ __forceinline__ void mma_fp16(float* c, const uint32_t* a, const uint32_t* b) {
    asm volatile(
        "mma.sync.aligned.m16n8k16.row.col.f32.f16.f16.f32 "
        "{%0,%1,%2,%3}, {%4,%5,%6,%7}, {%8,%9}, {%0,%1,%2,%3};"
        : "+f"(c[0]), "+f"(c[1]), "+f"(c[2]), "+f"(c[3])
        : "r"(a[0]), "r"(a[1]), "r"(a[2]), "r"(a[3]), "r"(b[0]), "r"(b[1]));
}
#define LDSM4(r0, r1, r2, r3, addr) \
    asm volatile("ldmatrix.sync.aligned.m8n8.x4.shared.b16 {%0,%1,%2,%3}, [%4];" \
        : "=r"(r0), "=r"(r1), "=r"(r2), "=r"(r3) : "r"(addr))
#define LDSM4T(r0, r1, r2, r3, addr) \
    asm volatile("ldmatrix.sync.aligned.m8n8.x4.trans.shared.b16 {%0,%1,%2,%3}, [%4];" \
        : "=r"(r0), "=r"(r1), "=r"(r2), "=r"(r3) : "r"(addr))

#define RSTR   48                    // bytes per smem row (token-major tiles)
#define TILE_B (128 * RSTR)          // 6144 B per 128x16 fp16 tile

// ---------------------------------------------------------------------------
// Refine GEMM: A = yT16 (B,D,S) channel-major fp16 (ldmatrix.trans),
// B 2-level fp16 (~21 bit):  C = A*Bhi + (A*2^-10)*(Blo*2^10) + bias.
// CTA 128x128, BK=16, 8 warps (64x32), 3-stage cp.async pipeline.
// A^T smem tile: 16 k-rows x 256B, stride 272B (conflict-free trans ldmatrix).
// ---------------------------------------------------------------------------
#define ARSTR   272
#define ATILE_B (16 * ARSTR)                 // 4352 B
#define RSTAGE_B (ATILE_B + 2 * TILE_B)      // 16640 B
#define RGEMM_SMEM (3 * RSTAGE_B)            // 49920 B

__global__ void __launch_bounds__(256, 2) gemm_ref(
        const __half* __restrict__ AT,       // (B,D,S) fp16
        const __half* __restrict__ Bhi, const __half* __restrict__ Blo,
        const float* __restrict__ bias,
        float* __restrict__ C, int N, int K)
{
    extern __shared__ char smem[];
    uint32_t sb = smem_u32(smem);

    int tid  = threadIdx.x;
    int lane = tid & 31;
    int warp = tid >> 5;
    int g = lane >> 2, t = lane & 3;
    int wm = (warp >> 2) * 64;
    int wn = (warp & 3) * 32;
    int m0 = blockIdx.x * 128, n0 = blockIdx.y * 128;
    int bz = m0 / S_;
    int sm0 = m0 & (S_ - 1);

    // trans-ldmatrix per-lane offset into A^T tile (bytes)
    uint32_t aoffT = (uint32_t)((((lane & 7) + ((lane >> 4) & 1) * 8) * ARSTR) + ((lane >> 3) & 1) * 16);
    // B ldmatrix per-lane offset (token-major tile, stride 48B)
    uint32_t boff = (uint32_t)((((lane & 7) + ((lane >> 4) & 1) * 8) * RSTR) + ((lane >> 3) & 1) * 16);

    // cp.async mappings
    int ar = tid >> 4, ac = tid & 15;        // A^T: 16 rows x 16 chunks
    int lr = tid >> 1;                       // B: 128 rows x 2 chunks
    uint32_t aso = (uint32_t)(ar * ARSTR + ac * 16);
    uint32_t bso = (uint32_t)(lr * RSTR + (tid & 1) * 16);
    int lc8 = (tid & 1) * 8;

    const __half2 sc = __floats2half2_rn(9.765625e-4f, 9.765625e-4f);  // 2^-10

    float acc[4][4][4];
#pragma unroll
    for (int mi = 0; mi < 4; mi++)
#pragma unroll
        for (int ni = 0; ni < 4; ni++)
#pragma unroll
            for (int r = 0; r < 4; r++) acc[mi][ni][r] = 0.f;

    auto load_stage = [&](int st, int kt) {
        int k0 = kt * 16;
        uint32_t base = sb + (uint32_t)st * RSTAGE_B;
        cp16s(base + aso, AT + (size_t)(bz * D_ + k0 + ar) * S_ + sm0 + ac * 8);
        size_t gb = (size_t)(n0 + lr) * K + k0 + lc8;
        cp16s(base + ATILE_B + bso,          Bhi + gb);
        cp16s(base + ATILE_B + TILE_B + bso, Blo + gb);
    };

    int KT = K >> 4;
    load_stage(0, 0); cp_commit();
    load_stage(1, 1); cp_commit();

    for (int kt = 0; kt < KT; kt++) {
        if (kt == KT - 1) cp_wait<0>(); else cp_wait<1>();
        __syncthreads();
        if (kt + 2 < KT) { load_stage((kt + 2) % 3, kt + 2); cp_commit(); }

        uint32_t base = sb + (uint32_t)(kt % 3) * RSTAGE_B;
        uint32_t tA = base, tBh = base + ATILE_B, tBl = base + ATILE_B + TILE_B;

        uint32_t af[16], bh[8], bl[8];
        LDSM4(bh[0], bh[1], bh[2], bh[3], tBh + (uint32_t)(wn * RSTR) + boff);
        LDSM4(bh[4], bh[5], bh[6], bh[7], tBh + (uint32_t)((wn + 16) * RSTR) + boff);
        LDSM4(bl[0], bl[1], bl[2], bl[3], tBl + (uint32_t)(wn * RSTR) + boff);
        LDSM4(bl[4], bl[5], bl[6], bl[7], tBl + (uint32_t)((wn + 16) * RSTR) + boff);
#pragma unroll
        for (int mi = 0; mi < 4; mi++)
            LDSM4T(af[mi*4], af[mi*4+1], af[mi*4+2], af[mi*4+3],
                   tA + aoffT + (uint32_t)((wm + mi * 16) * 2));

#pragma unroll
        for (int mi = 0; mi < 4; mi++)
#pragma unroll
            for (int ni = 0; ni < 4; ni++)
                mma_fp16(acc[mi][ni], &af[mi*4], &bh[ni*2]);

#pragma unroll
        for (int i = 0; i < 16; i++) {
            __half2 v = *(__half2*)&af[i];
            v = __hmul2(v, sc);
            af[i] = *(uint32_t*)&v;
        }
#pragma unroll
        for (int mi = 0; mi < 4; mi++)
#pragma unroll
            for (int ni = 0; ni < 4; ni++)
                mma_fp16(acc[mi][ni], &af[mi*4], &bl[ni*2]);
    }

#pragma unroll
    for (int mi = 0; mi < 4; mi++) {
        int r0 = m0 + wm + mi * 16 + g;
#pragma unroll
        for (int ni = 0; ni < 4; ni++) {
            int c0 = n0 + wn + ni * 8 + t * 2;
            float bv0 = bias[c0], bv1 = bias[c0 + 1];
            size_t o0 = (size_t)r0 * N + c0;
            size_t o1 = (size_t)(r0 + 8) * N + c0;
            float* a4 = acc[mi][ni];
            C[o0]     = a4[0] + bv0;
            C[o0 + 1] = a4[1] + bv1;
            C[o1]     = a4[2] + bv0;
            C[o1 + 1] = a4[3] + bv1;
        }
    }
}

// ---------------------------------------------------------------------------
// Single-product fp16 GEMM (gate + output projection).
// EPI 0 (output): C = acc + bias (fp32)
// EPI 1 (gate)  : s=sigmoid(acc+bias); x' = s*refined+(1-s)*orig -> fp32+fp16
// ---------------------------------------------------------------------------
#define OSTAGE_B (2 * TILE_B)          // 12288 B
#define OGEMM_SMEM (3 * OSTAGE_B)      // 36864 B

template<int EPI>
__global__ void __launch_bounds__(256, 2) gemm_1p(
        const __half* __restrict__ A, const __half* __restrict__ Bm,
        const float* __restrict__ bias,
        const float* __restrict__ refined, const float* __restrict__ orig,
        float* __restrict__ C, __half* __restrict__ C16,
        int M, int N, int K)
{
    extern __shared__ char smem[];
    uint32_t sb = smem_u32(smem);

    int tid  = threadIdx.x;
    int lane = tid & 31;
    int warp = tid >> 5;
    int g = lane >> 2, t = lane & 3;
    int wm = (warp >> 2) * 64;
    int wn = (warp & 3) * 32;
    int m0 = blockIdx.x * 128, n0 = blockIdx.y * 128;

    uint32_t aoff = (uint32_t)((((lane & 7) + ((lane >> 3) & 1) * 8) * RSTR) + ((lane >> 4) & 1) * 16);
    uint32_t boff = (uint32_t)((((lane & 7) + ((lane >> 4) & 1) * 8) * RSTR) + ((lane >> 3) & 1) * 16);

    int lr = tid >> 1;
    int lc8 = (tid & 1) * 8;
    uint32_t so = (uint32_t)(lr * RSTR + (tid & 1) * 16);

    float acc[4][4][4];
#pragma unroll
    for (int mi = 0; mi < 4; mi++)
#pragma unroll
        for (int ni = 0; ni < 4; ni++)
#pragma unroll
            for (int r = 0; r < 4; r++) acc[mi][ni][r] = 0.f;

    auto load_stage = [&](int st, int kt) {
        int k0 = kt * 16;
        uint32_t base = sb + (uint32_t)st * OSTAGE_B;
        cp16s(base + so,          A  + (size_t)(m0 + lr) * K + k0 + lc8);
        cp16s(base + TILE_B + so, Bm + (size_t)(n0 + lr) * K + k0 + lc8);
    };

    int KT = K >> 4;
    load_stage(0, 0); cp_commit();
    load_stage(1, 1); cp_commit();

    for (int kt = 0; kt < KT; kt++) {
        if (kt == KT - 1) cp_wait<0>(); else cp_wait<1>();
        __syncthreads();
        if (kt + 2 < KT) { load_stage((kt + 2) % 3, kt + 2); cp_commit(); }

        uint32_t base = sb + (uint32_t)(kt % 3) * OSTAGE_B;
        uint32_t tA = base, tB = base + TILE_B;

        uint32_t af[16], bf[8];
        LDSM4(bf[0], bf[1], bf[2], bf[3], tB + (uint32_t)(wn * RSTR) + boff);
        LDSM4(bf[4], bf[5], bf[6], bf[7], tB + (uint32_t)((wn + 16) * RSTR) + boff);
#pragma unroll
        for (int mi = 0; mi < 4; mi++)
            LDSM4(af[mi*4], af[mi*4+1], af[mi*4+2], af[mi*4+3],
                  tA + (uint32_t)((wm + mi * 16) * RSTR) + aoff);
#pragma unroll
        for (int mi = 0; mi < 4; mi++)
#pragma unroll
            for (int ni = 0; ni < 4; ni++)
                mma_fp16(acc[mi][ni], &af[mi*4], &bf[ni*2]);
    }

#pragma unroll
    for (int mi = 0; mi < 4; mi++) {
        int r0 = m0 + wm + mi * 16 + g;
#pragma unroll
        for (int ni = 0; ni < 4; ni++) {
            int c0 = n0 + wn + ni * 8 + t * 2;
            float bv0 = bias[c0], bv1 = bias[c0 + 1];
            size_t o0 = (size_t)r0 * N + c0;
            size_t o1 = (size_t)(r0 + 8) * N + c0;
            float* a4 = acc[mi][ni];
            if (EPI == 0) {
                C[o0]     = a4[0] + bv0;
                C[o0 + 1] = a4[1] + bv1;
                C[o1]     = a4[2] + bv0;
                C[o1 + 1] = a4[3] + bv1;
            } else {
                float pre[4] = {a4[0] + bv0, a4[1] + bv1, a4[2] + bv0, a4[3] + bv1};
                size_t offs[4] = {o0, o0 + 1, o1, o1 + 1};
#pragma unroll
                for (int j = 0; j < 4; j++) {
                    float gt = 1.f / (1.f + expf(-pre[j]));
                    float res = gt * refined[offs[j]] + (1.f - gt) * orig[offs[j]];
                    C[offs[j]] = res;
                    C16[offs[j]] = __float2half(res);
                }
            }
        }
    }
}

// ---------------------------------------------------------------------------
// Embedding + sinusoidal PE (+ fp16 copy for layer-0 gate A)
// ---------------------------------------------------------------------------
__global__ void embed_kernel(const int* __restrict__ ids,
                             const float* __restrict__ emb,
                             float* __restrict__ x,
                             __half* __restrict__ x16) {
    int row = blockIdx.x;
    int s   = row & (S_ - 1);
    int tok = ids[row];
    int d0  = threadIdx.x * 4;
    float4 e = *(const float4*)(emb + (size_t)tok * D_ + d0);
    const float cln = -logf(10000.0f) / (float)D_;
    float pe[4];
#pragma unroll
    for (int j = 0; j < 4; j += 2) {
        float freq = expf(cln * (float)(d0 + j));
        float a = (float)s * freq;
        pe[j]   = sinf(a);
        pe[j+1] = cosf(a);
    }
    float o[4] = {e.x + pe[0], e.y + pe[1], e.z + pe[2], e.w + pe[3]};
    *(float4*)(x + (size_t)row * D_ + d0) = *(float4*)o;
    __half2 p0 = __floats2half2_rn(o[0], o[1]);
    __half2 p1 = __floats2half2_rn(o[2], o[3]);
    uint2 packed = {*(uint32_t*)&p0, *(uint32_t*)&p1};
    *(uint2*)(x16 + (size_t)row * D_ + d0) = packed;
}

// ---------------------------------------------------------------------------
// fp16 split: hi = fp16(w), lo = fp16((w - hi) * 2^10)
// ---------------------------------------------------------------------------
__global__ void split16_kernel(const float* __restrict__ w,
                               __half* __restrict__ hi,
                               __half* __restrict__ lo, int n4) {
    int i = blockIdx.x * 256 + threadIdx.x;
    if (i >= n4) return;
    float4 v = ((const float4*)w)[i];
    float vv[4] = {v.x, v.y, v.z, v.w};
    __half hh[4], ll[4];
#pragma unroll
    for (int j = 0; j < 4; j++) {
        hh[j] = __float2half(vv[j]);
        ll[j] = __float2half((vv[j] - __half2float(hh[j])) * 1024.0f);
    }
    ((ushort4*)hi)[i] = *(ushort4*)hh;
    ((ushort4*)lo)[i] = *(ushort4*)ll;
}

// ---------------------------------------------------------------------------
// fp16 convert (gate weights, single level)
// ---------------------------------------------------------------------------
__global__ void conv16_kernel(const float* __restrict__ w,
                              __half* __restrict__ o, int n4) {
    int i = blockIdx.x * 256 + threadIdx.x;
    if (i >= n4) return;
    float4 v = ((const float4*)w)[i];
    __half2 p0 = __floats2half2_rn(v.x, v.y);
    __half2 p1 = __floats2half2_rn(v.z, v.w);
    uint2 packed = {*(uint32_t*)&p0, *(uint32_t*)&p1};
    ((uint2*)o)[i] = packed;
}

// ---------------------------------------------------------------------------
// outW (D,V) -> [V][D] fp16
// ---------------------------------------------------------------------------
__global__ void wout_t16_kernel(const float* __restrict__ w,
                                __half* __restrict__ o16) {
    __shared__ float tile[32][33];
    int v0 = blockIdx.x * 32, d0 = blockIdx.y * 32;
    int tx = threadIdx.x, ty = threadIdx.y;
#pragma unroll
    for (int i = 0; i < 4; i++)
        tile[ty + i * 8][tx] = w[(size_t)(d0 + ty + i * 8) * V_ + v0 + tx];
    __syncthreads();
#pragma unroll
    for (int i = 0; i < 4; i++) {
        size_t o = (size_t)(v0 + ty + i * 8) * D_ + d0 + tx;
        o16[o] = __float2half(tile[tx][ty + i * 8]);
    }
}

// ---------------------------------------------------------------------------
// LayerNorm statistics
// ---------------------------------------------------------------------------
__global__ void ln_stats_kernel(const float* __restrict__ x, float2* __restrict__ stats) {
    int row = blockIdx.x;
    float4 v = ((const float4*)(x + (size_t)row * D_))[threadIdx.x];
    float s = v.x + v.y + v.z + v.w;
    float q = v.x*v.x + v.y*v.y + v.z*v.z + v.w*v.w;
#pragma unroll
    for (int o = 16; o; o >>= 1) {
        s += __shfl_xor_sync(0xffffffffu, s, o);
        q += __shfl_xor_sync(0xffffffffu, q, o);
    }
    __shared__ float ss[8], sq[8];
    int w = threadIdx.x >> 5;
    if ((threadIdx.x & 31) == 0) { ss[w] = s; sq[w] = q; }
    __syncthreads();
    if (threadIdx.x == 0) {
        float S = 0.f, Q = 0.f;
#pragma unroll
        for (int i = 0; i < 8; i++) { S += ss[i]; Q += sq[i]; }
        float mu  = S / (float)D_;
        float var = Q / (float)D_ - mu * mu;
        stats[row] = make_float2(mu, rsqrtf(var + 1e-5f));
    }
}

// ---------------------------------------------------------------------------
// Apply LN while transposing (B,S,D)->(B,D,S)
// ---------------------------------------------------------------------------
__global__ void ln_transpose_kernel(const float* __restrict__ x,
                                    const float2* __restrict__ stats,
                                    const float* __restrict__ g,
                                    const float* __restrict__ bta,
                                    float* __restrict__ hT) {
    __shared__ float tile[32][33];
    int b  = blockIdx.z;
    int s0 = blockIdx.x * 32, d0 = blockIdx.y * 32;
    int tx = threadIdx.x, ty = threadIdx.y;
    float gg = g[d0 + tx], bb = bta[d0 + tx];
#pragma unroll
    for (int i = 0; i < 4; i++) {
        int s = s0 + ty + i * 8;
        float2 st = stats[b * S_ + s];
        float v = x[((size_t)(b * S_ + s)) * D_ + d0 + tx];
        tile[ty + i * 8][tx] = (v - st.x) * st.y * gg + bb;
    }
    __syncthreads();
#pragma unroll
    for (int i = 0; i < 4; i++) {
        int d = d0 + ty + i * 8;
        hT[((size_t)(b * D_ + d)) * S_ + s0 + tx] = tile[tx][ty + i * 8];
    }
}

// ---------------------------------------------------------------------------
// Final LN apply -> fp16
// ---------------------------------------------------------------------------
__global__ void apply_ln_kernel(const float* __restrict__ x,
                                const float2* __restrict__ stats,
                                const float* __restrict__ g,
                                const float* __restrict__ b,
                                __half* __restrict__ o16) {
    int row = blockIdx.x;
    int d0 = threadIdx.x * 4;
    float2 st = stats[row];
    float4 v  = *(const float4*)(x + (size_t)row * D_ + d0);
    float4 gg = *(const float4*)(g + d0);
    float4 bb = *(const float4*)(b + d0);
    __half2 p0 = __floats2half2_rn((v.x - st.x) * st.y * gg.x + bb.x,
                                   (v.y - st.x) * st.y * gg.y + bb.y);
    __half2 p1 = __floats2half2_rn((v.z - st.x) * st.y * gg.z + bb.z,
                                   (v.w - st.x) * st.y * gg.w + bb.w);
    uint2 packed = {*(uint32_t*)&p0, *(uint32_t*)&p1};
    *(uint2*)(o16 + (size_t)row * D_ + d0) = packed;
}

// ---------------------------------------------------------------------------
// Depthwise conv chain per (b,d) channel -> fp16 (B,D,S) output.
// ---------------------------------------------------------------------------
__global__ void __launch_bounds__(256) conv_kernel(const float* __restrict__ hT,
                                                   const float* __restrict__ lw,
                                                   const float* __restrict__ fw,
                                                   const float* __restrict__ mw,
                                                   __half* __restrict__ yT16) {
    int bd = blockIdx.x;
    int d  = bd & (D_ - 1);
    __shared__ float bufA[S_ + 64];
    __shared__ float bufB[S_ + 64];
    __shared__ float w3[3], wA[64], wB[64];
    int tid = threadIdx.x;
    if (tid < 64) {
        wA[tid] = fw[(size_t)d * 64 + tid];
        wB[tid] = fw[(size_t)(D_ + d) * 64 + tid];
    }
    if (tid < 3) w3[tid] = lw[d * 3 + tid];
    if (tid < 32) {
        bufA[tid] = 0.f; bufA[S_ + 32 + tid] = 0.f;
        bufB[tid] = 0.f; bufB[S_ + 32 + tid] = 0.f;
    }
    const float* cin = hT + (size_t)bd * S_;
    for (int i = tid; i < S_ / 4; i += 256)
        ((float4*)(bufA + 32))[i] = ((const float4*)cin)[i];
    __syncthreads();
    for (int s = tid; s < S_; s += 256)
        bufB[32 + s] = bufA[31 + s] * w3[0] + bufA[32 + s] * w3[1] + bufA[33 + s] * w3[2];
    __syncthreads();

    int s0 = tid * 8;
    float acc[8], win[8], nxt[8];

#pragma unroll
    for (int j = 0; j < 8; j++) { acc[j] = bufA[32 + s0 + j]; win[j] = bufB[s0 + j]; }
#pragma unroll
    for (int k0 = 0; k0 < 64; k0 += 8) {
#pragma unroll
        for (int j = 0; j < 8; j++) nxt[j] = bufB[s0 + 8 + k0 + j];
#pragma unroll
        for (int kk = 0; kk < 8; kk++) {
            float wk = wA[k0 + kk];
#pragma unroll
            for (int j = 0; j < 8; j++) {
                int ix = j + kk;
                acc[j] += (ix < 8 ? win[ix] : nxt[ix - 8]) * wk;
            }
        }
#pragma unroll
        for (int j = 0; j < 8; j++) win[j] = nxt[j];
    }
    __syncthreads();
#pragma unroll
    for (int j = 0; j < 8; j++) bufA[32 + s0 + j] = acc[j];
    __syncthreads();

    float mwd = mw[d];
#pragma unroll
    for (int j = 0; j < 8; j++) { acc[j] = 0.f; win[j] = bufA[s0 + j]; }
#pragma unroll
    for (int k0 = 0; k0 < 64; k0 += 8) {
#pragma unroll
        for (int j = 0; j < 8; j++) nxt[j] = bufA[s0 + 8 + k0 + j];
#pragma unroll
        for (int kk = 0; kk < 8; kk++) {
            float wk = wB[k0 + kk];
#pragma unroll
            for (int j = 0; j < 8; j++) {
                int ix = j + kk;
                acc[j] += (ix < 8 ? win[ix] : nxt[ix - 8]) * wk;
            }
        }
#pragma unroll
        for (int j = 0; j < 8; j++) win[j] = nxt[j];
    }
    __half hv[8];
#pragma unroll
    for (int j = 0; j < 8; j++) {
        float m = acc[j] * mwd;
        hv[j] = __float2half(m / (1.0f + expf(-m)));
    }
    *(uint4*)(yT16 + (size_t)bd * S_ + s0) = *(uint4*)hv;
}

// ---------------------------------------------------------------------------
// Host orchestration
// ---------------------------------------------------------------------------
static void* sym_addr(const void* sym) {
    void* p = nullptr;
    cudaGetSymbolAddress(&p, sym);
    return p;
}

extern "C" void kernel_launch(void* const* d_in, const int* in_sizes, int n_in,
                              void* d_out, int out_size) {
    (void)in_sizes; (void)n_in; (void)out_size;
    const int*   ids   = (const int*)d_in[0];
    const float* emb   = (const float*)d_in[1];
    const float* lw    = (const float*)d_in[2];
    const float* fw    = (const float*)d_in[3];
    const float* mw    = (const float*)d_in[4];
    const float* ln1g  = (const float*)d_in[5];
    const float* ln1b  = (const float*)d_in[6];
    const float* refW  = (const float*)d_in[7];
    const float* refb  = (const float*)d_in[8];
    const float* gateW = (const float*)d_in[9];
    const float* gateb = (const float*)d_in[10];
    const float* lnfg  = (const float*)d_in[11];
    const float* lnfb  = (const float*)d_in[12];
    const float* outW  = (const float*)d_in[13];
    const float* outb  = (const float*)d_in[14];
    float* out = (float*)d_out;

    float*  x0  = (float*)sym_addr(g_x0);
    float*  x1  = (float*)sym_addr(g_x1);
    float*  hT  = (float*)sym_addr(g_hT);
    float*  rf  = (float*)sym_addr(g_ref);
    float2* st  = (float2*)sym_addr(g_stats);
    __half* x016 = (__half*)sym_addr(g_x016);
    __half* x116 = (__half*)sym_addr(g_x116);
    __half* yT16 = (__half*)sym_addr(g_yT16);
    __half* wrh16 = (__half*)sym_addr(g_wrh16);
    __half* wrl16 = (__half*)sym_addr(g_wrl16);
    __half* wg16  = (__half*)sym_addr(g_wg16);
    __half* xf16 = (__half*)sym_addr(g_xf16);
    __half* wo16 = (__half*)sym_addr(g_wo16);

    cudaFuncSetAttribute(gemm_ref,    cudaFuncAttributeMaxDynamicSharedMemorySize, RGEMM_SMEM);
    cudaFuncSetAttribute(gemm_1p<0>,  cudaFuncAttributeMaxDynamicSharedMemorySize, OGEMM_SMEM);
    cudaFuncSetAttribute(gemm_1p<1>,  cudaFuncAttributeMaxDynamicSharedMemorySize, OGEMM_SMEM);

    {
        int n4 = NL_ * D_ * D_ / 4;
        split16_kernel<<<(n4 + 255) / 256, 256>>>(refW, wrh16, wrl16, n4);
        conv16_kernel<<<(n4 + 255) / 256, 256>>>(gateW, wg16, n4);
        wout_t16_kernel<<<dim3(V_ / 32, D_ / 32), dim3(32, 8)>>>(outW, wo16);
    }

    embed_kernel<<<M_, 256>>>(ids, emb, x0, x016);

    float* cur = x0;        float* nxt = x1;
    __half *cur16 = x016, *nxt16 = x116;
    for (int l = 0; l < NL_; l++) {
        ln_stats_kernel<<<M_, 256>>>(cur, st);
        ln_transpose_kernel<<<dim3(S_/32, D_/32, B_), dim3(32, 8)>>>(
            cur, st, ln1g + (size_t)l * D_, ln1b + (size_t)l * D_, hT);
        conv_kernel<<<B_*D_, 256>>>(
            hT, lw + (size_t)l * D_ * 3, fw + (size_t)l * 2 * D_ * 64,
            mw + (size_t)l * D_, yT16);
        gemm_ref<<<dim3(M_/128, D_/128), 256, RGEMM_SMEM>>>(
            yT16, wrh16 + (size_t)l * D_ * D_, wrl16 + (size_t)l * D_ * D_,
            refb + (size_t)l * D_, rf, D_, D_);
        gemm_1p<1><<<dim3(M_/128, D_/128), 256, OGEMM_SMEM>>>(
            cur16, wg16 + (size_t)l * D_ * D_,
            gateb + (size_t)l * D_, rf, cur, nxt, nxt16,
            M_, D_, D_);
        { float* tf = cur; cur = nxt; nxt = tf; }
        { __half* th = cur16; cur16 = nxt16; nxt16 = th; }
    }

    ln_stats_kernel<<<M_, 256>>>(cur, st);
    apply_ln_kernel<<<M_, 256>>>(cur, st, lnfg, lnfb, xf16);
    gemm_1p<0><<<dim3(M_/128, V_/128), 256, OGEMM_SMEM>>>(
        xf16, wo16, outb, nullptr, nullptr, out, nullptr, M_, V_, D_);
}

// round 10
// speedup vs baseline: 4.7929x; 1.0541x over previous
#include <cuda_runtime.h>
#include <cuda_fp16.h>
#include <math.h>
#include <stdint.h>

#define B_  2
#define S_  2048
#define D_  1024
#define V_  32000
#define NL_ 6
#define M_  (B_*S_)   // 4096 tokens

// ---------------------------------------------------------------------------
// Scratch
// ---------------------------------------------------------------------------
__device__ float  g_x0[M_*D_];
__device__ float  g_x1[M_*D_];
__device__ float  g_hT[M_*D_];
__device__ float  g_ref[M_*D_];
__device__ float2 g_stats[M_];

__device__ __half g_x016[M_*D_], g_x116[M_*D_];
__device__ __half g_yT16[M_*D_];                       // conv out, (B,D,S) fp16
__device__ __half g_wr16[NL_*D_*D_];
__device__ __half g_wg16[NL_*D_*D_];
__device__ __half g_xf16[M_*D_];
__device__ __half g_wo16[(size_t)V_*D_];

// ---------------------------------------------------------------------------
// PTX helpers
// ---------------------------------------------------------------------------
__device__ __forceinline__ uint32_t smem_u32(const void* p) {
    uint32_t a;
    asm("{ .reg .u64 t; cvta.to.shared.u64 t, %1; cvt.u32.u64 %0, t; }" : "=r"(a) : "l"(p));
    return a;
}
__device__ __forceinline__ void cp16s(uint32_t saddr, const void* g) {
    asm volatile("cp.async.cg.shared.global [%0], [%1], 16;\n" :: "r"(saddr), "l"(g));
}
__device__ __forceinline__ void cp_commit() {
    asm volatile("cp.async.commit_group;\n" ::: "memory");
}
template<int N_> __device__ __forceinline__ void cp_wait() {
    asm volatile("cp.async.wait_group %0;\n" :: "n"(N_) : "memory");
}
__device__ __forceinline__ void mma_fp16(float* c, const uint32_t* a, const uint32_t* b) {
    asm volatile(
        "mma.sync.aligned.m16n8k16.row.col.f32.f16.f16.f32 "
        "{%0,%1,%2,%3}, {%4,%5,%6,%7}, {%8,%9}, {%0,%1,%2,%3};"
        : "+f"(c[0]), "+f"(c[1]), "+f"(c[2]), "+f"(c[3])
        : "r"(a[0]), "r"(a[1]), "r"(a[2]), "r"(a[3]), "r"(b[0]), "r"(b[1]));
}
#define LDSM4(r0, r1, r2, r3, addr) \
    asm volatile("ldmatrix.sync.aligned.m8n8.x4.shared.b16 {%0,%1,%2,%3}, [%4];" \
        : "=r"(r0), "=r"(r1), "=r"(r2), "=r"(r3) : "r"(addr))
#define LDSM4T(r0, r1, r2, r3, addr) \
    asm volatile("ldmatrix.sync.aligned.m8n8.x4.trans.shared.b16 {%0,%1,%2,%3}, [%4];" \
        : "=r"(r0), "=r"(r1), "=r"(r2), "=r"(r3) : "r"(addr))

#define RSTR   48                    // bytes per smem row (token-major tiles)
#define TILE_B (128 * RSTR)          // 6144 B per 128x16 fp16 tile

// ---------------------------------------------------------------------------
// Refine GEMM: A = yT16 (B,D,S) channel-major fp16 (ldmatrix.trans),
// B single fp16:  C = A*B + bias  (fp32 accum).
// CTA 128x128, BK=16, 8 warps (64x32), 3-stage cp.async pipeline.
// A^T smem tile: 16 k-rows x 256B, stride 272B (conflict-free trans ldmatrix).
// ---------------------------------------------------------------------------
#define ARSTR   272
#define ATILE_B (16 * ARSTR)                 // 4352 B
#define RSTAGE_B (ATILE_B + TILE_B)          // 10496 B
#define RGEMM_SMEM (3 * RSTAGE_B)            // 31488 B

__global__ void __launch_bounds__(256, 2) gemm_ref(
        const __half* __restrict__ AT,       // (B,D,S) fp16
        const __half* __restrict__ Bm,
        const float* __restrict__ bias,
        float* __restrict__ C, int N, int K)
{
    extern __shared__ char smem[];
    uint32_t sb = smem_u32(smem);

    int tid  = threadIdx.x;
    int lane = tid & 31;
    int warp = tid >> 5;
    int g = lane >> 2, t = lane & 3;
    int wm = (warp >> 2) * 64;
    int wn = (warp & 3) * 32;
    int m0 = blockIdx.x * 128, n0 = blockIdx.y * 128;
    int bz = m0 / S_;
    int sm0 = m0 & (S_ - 1);

    // trans-ldmatrix per-lane offset into A^T tile (bytes)
    uint32_t aoffT = (uint32_t)((((lane & 7) + ((lane >> 4) & 1) * 8) * ARSTR) + ((lane >> 3) & 1) * 16);
    // B ldmatrix per-lane offset (token-major tile, stride 48B)
    uint32_t boff = (uint32_t)((((lane & 7) + ((lane >> 4) & 1) * 8) * RSTR) + ((lane >> 3) & 1) * 16);

    // cp.async mappings
    int ar = tid >> 4, ac = tid & 15;        // A^T: 16 rows x 16 chunks
    int lr = tid >> 1;                       // B: 128 rows x 2 chunks
    uint32_t aso = (uint32_t)(ar * ARSTR + ac * 16);
    uint32_t bso = (uint32_t)(lr * RSTR + (tid & 1) * 16);
    int lc8 = (tid & 1) * 8;

    float acc[4][4][4];
#pragma unroll
    for (int mi = 0; mi < 4; mi++)
#pragma unroll
        for (int ni = 0; ni < 4; ni++)
#pragma unroll
            for (int r = 0; r < 4; r++) acc[mi][ni][r] = 0.f;

    auto load_stage = [&](int st, int kt) {
        int k0 = kt * 16;
        uint32_t base = sb + (uint32_t)st * RSTAGE_B;
        cp16s(base + aso, AT + (size_t)(bz * D_ + k0 + ar) * S_ + sm0 + ac * 8);
        cp16s(base + ATILE_B + bso, Bm + (size_t)(n0 + lr) * K + k0 + lc8);
    };

    int KT = K >> 4;
    load_stage(0, 0); cp_commit();
    load_stage(1, 1); cp_commit();

    for (int kt = 0; kt < KT; kt++) {
        if (kt == KT - 1) cp_wait<0>(); else cp_wait<1>();
        __syncthreads();
        if (kt + 2 < KT) { load_stage((kt + 2) % 3, kt + 2); cp_commit(); }

        uint32_t base = sb + (uint32_t)(kt % 3) * RSTAGE_B;
        uint32_t tA = base, tB = base + ATILE_B;

        uint32_t af[16], bf[8];
        LDSM4(bf[0], bf[1], bf[2], bf[3], tB + (uint32_t)(wn * RSTR) + boff);
        LDSM4(bf[4], bf[5], bf[6], bf[7], tB + (uint32_t)((wn + 16) * RSTR) + boff);
#pragma unroll
        for (int mi = 0; mi < 4; mi++)
            LDSM4T(af[mi*4], af[mi*4+1], af[mi*4+2], af[mi*4+3],
                   tA + aoffT + (uint32_t)((wm + mi * 16) * 2));
#pragma unroll
        for (int mi = 0; mi < 4; mi++)
#pragma unroll
            for (int ni = 0; ni < 4; ni++)
                mma_fp16(acc[mi][ni], &af[mi*4], &bf[ni*2]);
    }

#pragma unroll
    for (int mi = 0; mi < 4; mi++) {
        int r0 = m0 + wm + mi * 16 + g;
#pragma unroll
        for (int ni = 0; ni < 4; ni++) {
            int c0 = n0 + wn + ni * 8 + t * 2;
            float bv0 = bias[c0], bv1 = bias[c0 + 1];
            size_t o0 = (size_t)r0 * N + c0;
            size_t o1 = (size_t)(r0 + 8) * N + c0;
            float* a4 = acc[mi][ni];
            C[o0]     = a4[0] + bv0;
            C[o0 + 1] = a4[1] + bv1;
            C[o1]     = a4[2] + bv0;
            C[o1 + 1] = a4[3] + bv1;
        }
    }
}

// ---------------------------------------------------------------------------
// Single-product fp16 GEMM (gate + output projection), token-major A.
// EPI 0 (output): C = acc + bias (fp32)
// EPI 1 (gate)  : s=sigmoid(acc+bias); x' = s*refined+(1-s)*orig -> fp32+fp16
// ---------------------------------------------------------------------------
#define OSTAGE_B (2 * TILE_B)          // 12288 B
#define OGEMM_SMEM (3 * OSTAGE_B)      // 36864 B

template<int EPI>
__global__ void __launch_bounds__(256, 2) gemm_1p(
        const __half* __restrict__ A, const __half* __restrict__ Bm,
        const float* __restrict__ bias,
        const float* __restrict__ refined, const float* __restrict__ orig,
        float* __restrict__ C, __half* __restrict__ C16,
        int M, int N, int K)
{
    extern __shared__ char smem[];
    uint32_t sb = smem_u32(smem);

    int tid  = threadIdx.x;
    int lane = tid & 31;
    int warp = tid >> 5;
    int g = lane >> 2, t = lane & 3;
    int wm = (warp >> 2) * 64;
    int wn = (warp & 3) * 32;
    int m0 = blockIdx.x * 128, n0 = blockIdx.y * 128;

    uint32_t aoff = (uint32_t)((((lane & 7) + ((lane >> 3) & 1) * 8) * RSTR) + ((lane >> 4) & 1) * 16);
    uint32_t boff = (uint32_t)((((lane & 7) + ((lane >> 4) & 1) * 8) * RSTR) + ((lane >> 3) & 1) * 16);

    int lr = tid >> 1;
    int lc8 = (tid & 1) * 8;
    uint32_t so = (uint32_t)(lr * RSTR + (tid & 1) * 16);

    float acc[4][4][4];
#pragma unroll
    for (int mi = 0; mi < 4; mi++)
#pragma unroll
        for (int ni = 0; ni < 4; ni++)
#pragma unroll
            for (int r = 0; r < 4; r++) acc[mi][ni][r] = 0.f;

    auto load_stage = [&](int st, int kt) {
        int k0 = kt * 16;
        uint32_t base = sb + (uint32_t)st * OSTAGE_B;
        cp16s(base + so,          A  + (size_t)(m0 + lr) * K + k0 + lc8);
        cp16s(base + TILE_B + so, Bm + (size_t)(n0 + lr) * K + k0 + lc8);
    };

    int KT = K >> 4;
    load_stage(0, 0); cp_commit();
    load_stage(1, 1); cp_commit();

    for (int kt = 0; kt < KT; kt++) {
        if (kt == KT - 1) cp_wait<0>(); else cp_wait<1>();
        __syncthreads();
        if (kt + 2 < KT) { load_stage((kt + 2) % 3, kt + 2); cp_commit(); }

        uint32_t base = sb + (uint32_t)(kt % 3) * OSTAGE_B;
        uint32_t tA = base, tB = base + TILE_B;

        uint32_t af[16], bf[8];
        LDSM4(bf[0], bf[1], bf[2], bf[3], tB + (uint32_t)(wn * RSTR) + boff);
        LDSM4(bf[4], bf[5], bf[6], bf[7], tB + (uint32_t)((wn + 16) * RSTR) + boff);
#pragma unroll
        for (int mi = 0; mi < 4; mi++)
            LDSM4(af[mi*4], af[mi*4+1], af[mi*4+2], af[mi*4+3],
                  tA + (uint32_t)((wm + mi * 16) * RSTR) + aoff);
#pragma unroll
        for (int mi = 0; mi < 4; mi++)
#pragma unroll
            for (int ni = 0; ni < 4; ni++)
                mma_fp16(acc[mi][ni], &af[mi*4], &bf[ni*2]);
    }

#pragma unroll
    for (int mi = 0; mi < 4; mi++) {
        int r0 = m0 + wm + mi * 16 + g;
#pragma unroll
        for (int ni = 0; ni < 4; ni++) {
            int c0 = n0 + wn + ni * 8 + t * 2;
            float bv0 = bias[c0], bv1 = bias[c0 + 1];
            size_t o0 = (size_t)r0 * N + c0;
            size_t o1 = (size_t)(r0 + 8) * N + c0;
            float* a4 = acc[mi][ni];
            if (EPI == 0) {
                C[o0]     = a4[0] + bv0;
                C[o0 + 1] = a4[1] + bv1;
                C[o1]     = a4[2] + bv0;
                C[o1 + 1] = a4[3] + bv1;
            } else {
                float pre[4] = {a4[0] + bv0, a4[1] + bv1, a4[2] + bv0, a4[3] + bv1};
                size_t offs[4] = {o0, o0 + 1, o1, o1 + 1};
#pragma unroll
                for (int j = 0; j < 4; j++) {
                    float gt = 1.f / (1.f + expf(-pre[j]));
                    float res = gt * refined[offs[j]] + (1.f - gt) * orig[offs[j]];
                    C[offs[j]] = res;
                    C16[offs[j]] = __float2half(res);
                }
            }
        }
    }
}

// ---------------------------------------------------------------------------
// Embedding + sinusoidal PE (+ fp16 copy for layer-0 gate A)
// ---------------------------------------------------------------------------
__global__ void embed_kernel(const int* __restrict__ ids,
                             const float* __restrict__ emb,
                             float* __restrict__ x,
                             __half* __restrict__ x16) {
    int row = blockIdx.x;
    int s   = row & (S_ - 1);
    int tok = ids[row];
    int d0  = threadIdx.x * 4;
    float4 e = *(const float4*)(emb + (size_t)tok * D_ + d0);
    const float cln = -logf(10000.0f) / (float)D_;
    float pe[4];
#pragma unroll
    for (int j = 0; j < 4; j += 2) {
        float freq = expf(cln * (float)(d0 + j));
        float a = (float)s * freq;
        pe[j]   = sinf(a);
        pe[j+1] = cosf(a);
    }
    float o[4] = {e.x + pe[0], e.y + pe[1], e.z + pe[2], e.w + pe[3]};
    *(float4*)(x + (size_t)row * D_ + d0) = *(float4*)o;
    __half2 p0 = __floats2half2_rn(o[0], o[1]);
    __half2 p1 = __floats2half2_rn(o[2], o[3]);
    uint2 packed = {*(uint32_t*)&p0, *(uint32_t*)&p1};
    *(uint2*)(x16 + (size_t)row * D_ + d0) = packed;
}

// ---------------------------------------------------------------------------
// fp16 convert (layer weights, single level)
// ---------------------------------------------------------------------------
__global__ void conv16_kernel(const float* __restrict__ w,
                              __half* __restrict__ o, int n4) {
    int i = blockIdx.x * 256 + threadIdx.x;
    if (i >= n4) return;
    float4 v = ((const float4*)w)[i];
    __half2 p0 = __floats2half2_rn(v.x, v.y);
    __half2 p1 = __floats2half2_rn(v.z, v.w);
    uint2 packed = {*(uint32_t*)&p0, *(uint32_t*)&p1};
    ((uint2*)o)[i] = packed;
}

// ---------------------------------------------------------------------------
// outW (D,V) -> [V][D] fp16
// ---------------------------------------------------------------------------
__global__ void wout_t16_kernel(const float* __restrict__ w,
                                __half* __restrict__ o16) {
    __shared__ float tile[32][33];
    int v0 = blockIdx.x * 32, d0 = blockIdx.y * 32;
    int tx = threadIdx.x, ty = threadIdx.y;
#pragma unroll
    for (int i = 0; i < 4; i++)
        tile[ty + i * 8][tx] = w[(size_t)(d0 + ty + i * 8) * V_ + v0 + tx];
    __syncthreads();
#pragma unroll
    for (int i = 0; i < 4; i++) {
        size_t o = (size_t)(v0 + ty + i * 8) * D_ + d0 + tx;
        o16[o] = __float2half(tile[tx][ty + i * 8]);
    }
}

// ---------------------------------------------------------------------------
// LayerNorm statistics
// ---------------------------------------------------------------------------
__global__ void ln_stats_kernel(const float* __restrict__ x, float2* __restrict__ stats) {
    int row = blockIdx.x;
    float4 v = ((const float4*)(x + (size_t)row * D_))[threadIdx.x];
    float s = v.x + v.y + v.z + v.w;
    float q = v.x*v.x + v.y*v.y + v.z*v.z + v.w*v.w;
#pragma unroll
    for (int o = 16; o; o >>= 1) {
        s += __shfl_xor_sync(0xffffffffu, s, o);
        q += __shfl_xor_sync(0xffffffffu, q, o);
    }
    __shared__ float ss[8], sq[8];
    int w = threadIdx.x >> 5;
    if ((threadIdx.x & 31) == 0) { ss[w] = s; sq[w] = q; }
    __syncthreads();
    if (threadIdx.x == 0) {
        float S = 0.f, Q = 0.f;
#pragma unroll
        for (int i = 0; i < 8; i++) { S += ss[i]; Q += sq[i]; }
        float mu  = S / (float)D_;
        float var = Q / (float)D_ - mu * mu;
        stats[row] = make_float2(mu, rsqrtf(var + 1e-5f));
    }
}

// ---------------------------------------------------------------------------
// Apply LN while transposing (B,S,D)->(B,D,S)
// ---------------------------------------------------------------------------
__global__ void ln_transpose_kernel(const float* __restrict__ x,
                                    const float2* __restrict__ stats,
                                    const float* __restrict__ g,
                                    const float* __restrict__ bta,
                                    float* __restrict__ hT) {
    __shared__ float tile[32][33];
    int b  = blockIdx.z;
    int s0 = blockIdx.x * 32, d0 = blockIdx.y * 32;
    int tx = threadIdx.x, ty = threadIdx.y;
    float gg = g[d0 + tx], bb = bta[d0 + tx];
#pragma unroll
    for (int i = 0; i < 4; i++) {
        int s = s0 + ty + i * 8;
        float2 st = stats[b * S_ + s];
        float v = x[((size_t)(b * S_ + s)) * D_ + d0 + tx];
        tile[ty + i * 8][tx] = (v - st.x) * st.y * gg + bb;
    }
    __syncthreads();
#pragma unroll
    for (int i = 0; i < 4; i++) {
        int d = d0 + ty + i * 8;
        hT[((size_t)(b * D_ + d)) * S_ + s0 + tx] = tile[tx][ty + i * 8];
    }
}

// ---------------------------------------------------------------------------
// Final LN apply -> fp16
// ---------------------------------------------------------------------------
__global__ void apply_ln_kernel(const float* __restrict__ x,
                                const float2* __restrict__ stats,
                                const float* __restrict__ g,
                                const float* __restrict__ b,
                                __half* __restrict__ o16) {
    int row = blockIdx.x;
    int d0 = threadIdx.x * 4;
    float2 st = stats[row];
    float4 v  = *(const float4*)(x + (size_t)row * D_ + d0);
    float4 gg = *(const float4*)(g + d0);
    float4 bb = *(const float4*)(b + d0);
    __half2 p0 = __floats2half2_rn((v.x - st.x) * st.y * gg.x + bb.x,
                                   (v.y - st.x) * st.y * gg.y + bb.y);
    __half2 p1 = __floats2half2_rn((v.z - st.x) * st.y * gg.z + bb.z,
                                   (v.w - st.x) * st.y * gg.w + bb.w);
    uint2 packed = {*(uint32_t*)&p0, *(uint32_t*)&p1};
    *(uint2*)(o16 + (size_t)row * D_ + d0) = packed;
}

// ---------------------------------------------------------------------------
// Depthwise conv chain per (b,d) channel -> fp16 (B,D,S) output.
// ---------------------------------------------------------------------------
__global__ void __launch_bounds__(256) conv_kernel(const float* __restrict__ hT,
                                                   const float* __restrict__ lw,
                                                   const float* __restrict__ fw,
                                                   const float* __restrict__ mw,
                                                   __half* __restrict__ yT16) {
    int bd = blockIdx.x;
    int d  = bd & (D_ - 1);
    __shared__ float bufA[S_ + 64];
    __shared__ float bufB[S_ + 64];
    __shared__ float w3[3], wA[64], wB[64];
    int tid = threadIdx.x;
    if (tid < 64) {
        wA[tid] = fw[(size_t)d * 64 + tid];
        wB[tid] = fw[(size_t)(D_ + d) * 64 + tid];
    }
    if (tid < 3) w3[tid] = lw[d * 3 + tid];
    if (tid < 32) {
        bufA[tid] = 0.f; bufA[S_ + 32 + tid] = 0.f;
        bufB[tid] = 0.f; bufB[S_ + 32 + tid] = 0.f;
    }
    const float* cin = hT + (size_t)bd * S_;
    for (int i = tid; i < S_ / 4; i += 256)
        ((float4*)(bufA + 32))[i] = ((const float4*)cin)[i];
    __syncthreads();
    for (int s = tid; s < S_; s += 256)
        bufB[32 + s] = bufA[31 + s] * w3[0] + bufA[32 + s] * w3[1] + bufA[33 + s] * w3[2];
    __syncthreads();

    int s0 = tid * 8;
    float acc[8], win[8], nxt[8];

#pragma unroll
    for (int j = 0; j < 8; j++) { acc[j] = bufA[32 + s0 + j]; win[j] = bufB[s0 + j]; }
#pragma unroll
    for (int k0 = 0; k0 < 64; k0 += 8) {
#pragma unroll
        for (int j = 0; j < 8; j++) nxt[j] = bufB[s0 + 8 + k0 + j];
#pragma unroll
        for (int kk = 0; kk < 8; kk++) {
            float wk = wA[k0 + kk];
#pragma unroll
            for (int j = 0; j < 8; j++) {
                int ix = j + kk;
                acc[j] += (ix < 8 ? win[ix] : nxt[ix - 8]) * wk;
            }
        }
#pragma unroll
        for (int j = 0; j < 8; j++) win[j] = nxt[j];
    }
    __syncthreads();
#pragma unroll
    for (int j = 0; j < 8; j++) bufA[32 + s0 + j] = acc[j];
    __syncthreads();

    float mwd = mw[d];
#pragma unroll
    for (int j = 0; j < 8; j++) { acc[j] = 0.f; win[j] = bufA[s0 + j]; }
#pragma unroll
    for (int k0 = 0; k0 < 64; k0 += 8) {
#pragma unroll
        for (int j = 0; j < 8; j++) nxt[j] = bufA[s0 + 8 + k0 + j];
#pragma unroll
        for (int kk = 0; kk < 8; kk++) {
            float wk = wB[k0 + kk];
#pragma unroll
            for (int j = 0; j < 8; j++) {
                int ix = j + kk;
                acc[j] += (ix < 8 ? win[ix] : nxt[ix - 8]) * wk;
            }
        }
#pragma unroll
        for (int j = 0; j < 8; j++) win[j] = nxt[j];
    }
    __half hv[8];
#pragma unroll
    for (int j = 0; j < 8; j++) {
        float m = acc[j] * mwd;
        hv[j] = __float2half(m / (1.0f + expf(-m)));
    }
    *(uint4*)(yT16 + (size_t)bd * S_ + s0) = *(uint4*)hv;
}

// ---------------------------------------------------------------------------
// Host orchestration
// ---------------------------------------------------------------------------
static void* sym_addr(const void* sym) {
    void* p = nullptr;
    cudaGetSymbolAddress(&p, sym);
    return p;
}

extern "C" void kernel_launch(void* const* d_in, const int* in_sizes, int n_in,
                              void* d_out, int out_size) {
    (void)in_sizes; (void)n_in; (void)out_size;
    const int*   ids   = (const int*)d_in[0];
    const float* emb   = (const float*)d_in[1];
    const float* lw    = (const float*)d_in[2];
    const float* fw    = (const float*)d_in[3];
    const float* mw    = (const float*)d_in[4];
    const float* ln1g  = (const float*)d_in[5];
    const float* ln1b  = (const float*)d_in[6];
    const float* refW  = (const float*)d_in[7];
    const float* refb  = (const float*)d_in[8];
    const float* gateW = (const float*)d_in[9];
    const float* gateb = (const float*)d_in[10];
    const float* lnfg  = (const float*)d_in[11];
    const float* lnfb  = (const float*)d_in[12];
    const float* outW  = (const float*)d_in[13];
    const float* outb  = (const float*)d_in[14];
    float* out = (float*)d_out;

    float*  x0  = (float*)sym_addr(g_x0);
    float*  x1  = (float*)sym_addr(g_x1);
    float*  hT  = (float*)sym_addr(g_hT);
    float*  rf  = (float*)sym_addr(g_ref);
    float2* st  = (float2*)sym_addr(g_stats);
    __half* x016 = (__half*)sym_addr(g_x016);
    __half* x116 = (__half*)sym_addr(g_x116);
    __half* yT16 = (__half*)sym_addr(g_yT16);
    __half* wr16 = (__half*)sym_addr(g_wr16);
    __half* wg16 = (__half*)sym_addr(g_wg16);
    __half* xf16 = (__half*)sym_addr(g_xf16);
    __half* wo16 = (__half*)sym_addr(g_wo16);

    cudaFuncSetAttribute(gemm_ref,    cudaFuncAttributeMaxDynamicSharedMemorySize, RGEMM_SMEM);
    cudaFuncSetAttribute(gemm_1p<0>,  cudaFuncAttributeMaxDynamicSharedMemorySize, OGEMM_SMEM);
    cudaFuncSetAttribute(gemm_1p<1>,  cudaFuncAttributeMaxDynamicSharedMemorySize, OGEMM_SMEM);

    {
        int n4 = NL_ * D_ * D_ / 4;
        conv16_kernel<<<(n4 + 255) / 256, 256>>>(refW,  wr16, n4);
        conv16_kernel<<<(n4 + 255) / 256, 256>>>(gateW, wg16, n4);
        wout_t16_kernel<<<dim3(V_ / 32, D_ / 32), dim3(32, 8)>>>(outW, wo16);
    }

    embed_kernel<<<M_, 256>>>(ids, emb, x0, x016);

    float* cur = x0;        float* nxt = x1;
    __half *cur16 = x016, *nxt16 = x116;
    for (int l = 0; l < NL_; l++) {
        ln_stats_kernel<<<M_, 256>>>(cur, st);
        ln_transpose_kernel<<<dim3(S_/32, D_/32, B_), dim3(32, 8)>>>(
            cur, st, ln1g + (size_t)l * D_, ln1b + (size_t)l * D_, hT);
        conv_kernel<<<B_*D_, 256>>>(
            hT, lw + (size_t)l * D_ * 3, fw + (size_t)l * 2 * D_ * 64,
            mw + (size_t)l * D_, yT16);
        gemm_ref<<<dim3(M_/128, D_/128), 256, RGEMM_SMEM>>>(
            yT16, wr16 + (size_t)l * D_ * D_,
            refb + (size_t)l * D_, rf, D_, D_);
        gemm_1p<1><<<dim3(M_/128, D_/128), 256, OGEMM_SMEM>>>(
            cur16, wg16 + (size_t)l * D_ * D_,
            gateb + (size_t)l * D_, rf, cur, nxt, nxt16,
            M_, D_, D_);
        { float* tf = cur; cur = nxt; nxt = tf; }
        { __half* th = cur16; cur16 = nxt16; nxt16 = th; }
    }

    ln_stats_kernel<<<M_, 256>>>(cur, st);
    apply_ln_kernel<<<M_, 256>>>(cur, st, lnfg, lnfb, xf16);
    gemm_1p<0><<<dim3(M_/128, V_/128), 256, OGEMM_SMEM>>>(
        xf16, wo16, outb, nullptr, nullptr, out, nullptr, M_, V_, D_);
}